// round 4
// baseline (speedup 1.0000x reference)
#include <cuda_runtime.h>
#include <stdint.h>
#include <cstdint>
#include <math.h>

// ---------------------------------------------------------------------------
// Scratch (device globals -- allocation-free per harness rules)
// ---------------------------------------------------------------------------
__device__ float  g_col[44236800];   // im2col scratch (max: conv1 75*589824)
__device__ float  g_b1[18874368];    // conv1 out 32*768*768
__device__ float  g_b2[4718592];    // conv2 out 32*384*384
__device__ float  g_b3[9437184];    // conv3 out 64*384*384
__device__ float  g_b4[4718592];    // conv4 out 128*192*192
__device__ float  g_b5[4718592];    // conv5 out
__device__ float  g_b6[4718592];    // conv6 out (attention input)
__device__ float  g_fgp[10616832];  // 1152 x 9216   (K x M for S)
__device__ float  g_bgp[10616832];  // 1152 x 9216   (K x N for S; N x K for R)
__device__ float  g_S[84934656];    // 9216 x 9216 (S, then softmaxed A in-place)
__device__ float  g_Rt[10616832];   // 9216 x 1152 (R transposed: [p][c*9+k])
__device__ float  g_attn[4718592];  // attention out 128*192*192
__device__ float  g_b7[4718592];    // conv7 out
__device__ double g_sumsq;          // Frobenius norm accumulator

// ---------------------------------------------------------------------------
// Helpers
// ---------------------------------------------------------------------------
__device__ __forceinline__ int refl(int i, int n) {
    if (i < 0) i = -i;
    if (i >= n) i = 2 * n - 2 - i;
    return i;
}

__device__ __forceinline__ unsigned f2tf32(float x) {
    unsigned r;
    asm("cvt.rna.tf32.f32 %0, %1;" : "=r"(r) : "f"(x));
    return r;
}

__device__ __forceinline__ void mma_tf32(float* c, const unsigned* a, unsigned b0, unsigned b1) {
    asm volatile(
        "mma.sync.aligned.m16n8k8.row.col.f32.tf32.tf32.f32 "
        "{%0,%1,%2,%3},{%4,%5,%6,%7},{%8,%9},{%0,%1,%2,%3};\n"
        : "+f"(c[0]), "+f"(c[1]), "+f"(c[2]), "+f"(c[3])
        : "r"(a[0]), "r"(a[1]), "r"(a[2]), "r"(a[3]), "r"(b0), "r"(b1));
}

// Fragment-order word index within one 16k x 128m A tile.
// a0=(row g,col th) a1=(g+8,th) a2=(g,th+4) a3=(g+8,th+4); lane = g*4+th.
__device__ __forceinline__ int a_widx(int kk, int mm) {
    int ks = kk >> 3, k = kk & 7;
    int th = k & 3, rh = (k >> 2) & 1;
    int mb = mm >> 4, r = mm & 15, g = r & 7, mh = (r >> 3) & 1;
    return ((ks * 8 + mb) * 128) + (g * 4 + th) * 4 + rh * 2 + mh;
}
// b0=(k th, n g), b1=(k th+4, n g); lane = g*4+th.
__device__ __forceinline__ int b_widx(int kk, int nn) {
    int ks = kk >> 3, k = kk & 7;
    int th = k & 3, rh = (k >> 2) & 1;
    int nb = nn >> 3, g = nn & 7;
    return ((ks * 16 + nb) * 64) + (g * 4 + th) * 2 + rh;
}

// im2col with reflect padding (matches jnp.pad mode='reflect')
__global__ void im2col_kernel(const float* __restrict__ in, float* __restrict__ col,
                              int C, int H, int W, int KS, int pad, int stride,
                              int OH, int OW) {
    int total = C * KS * KS * OH * OW;
    int idx = blockIdx.x * blockDim.x + threadIdx.x;
    if (idx >= total) return;
    int hw  = OH * OW;
    int pix = idx % hw;
    int row = idx / hw;
    int kx = row % KS;
    int ky = (row / KS) % KS;
    int c  = row / (KS * KS);
    int oy = pix / OW, ox = pix % OW;
    int iy = refl(oy * stride + ky - pad, H);
    int ix = refl(ox * stride + kx - pad, W);
    col[idx] = in[(size_t)c * H * W + (size_t)iy * W + ix];
}

// ---------------------------------------------------------------------------
// FFMA conv GEMM: C[m,n] = act(sum_k A[m,k]*B[k,n] + bias[m])
// A: M x K weights, B: K x N im2col. Tile TM x TN, 256 threads, KT=8.
// ---------------------------------------------------------------------------
template <int ACT, int TM, int TN>
__global__ __launch_bounds__(256, 2) void conv_gemm_kernel(
    const float* __restrict__ A, const float* __restrict__ B,
    const float* __restrict__ bias, float* __restrict__ C,
    int M, int N, int K) {
    constexpr int TNTH = TN / 8;        // threads along n
    constexpr int TMTH = 256 / TNTH;    // threads along m
    constexpr int MR   = TM / TMTH;     // rows per thread (4 or 8)
    __shared__ __align__(16) float As[8][TM + 4];
    __shared__ __align__(16) float Bs[8][TN + 4];
    int t  = threadIdx.x;
    int tx = t % TNTH, ty = t / TNTH;
    int m0 = blockIdx.y * TM, n0 = blockIdx.x * TN;

    float acc[MR][8];
#pragma unroll
    for (int i = 0; i < MR; i++)
#pragma unroll
        for (int j = 0; j < 8; j++) acc[i][j] = 0.f;

    for (int k0 = 0; k0 < K; k0 += 8) {
#pragma unroll
        for (int i = 0; i < TM * 8 / 256; i++) {
            int id = t + i * 256;
            int kk = id & 7, mm = id >> 3;
            int gk = k0 + kk;
            As[kk][mm] = (gk < K && m0 + mm < M) ? A[(size_t)(m0 + mm) * K + gk] : 0.f;
        }
#pragma unroll
        for (int i = 0; i < TN * 8 / 256; i++) {
            int id = t + i * 256;
            int kk = id / TN, nn = id % TN;
            int gk = k0 + kk;
            Bs[kk][nn] = (gk < K && n0 + nn < N) ? B[(size_t)gk * N + n0 + nn] : 0.f;
        }
        __syncthreads();
#pragma unroll
        for (int kk = 0; kk < 8; kk++) {
            float a[MR], b[8];
#pragma unroll
            for (int h = 0; h < MR / 4; h++)
                *(float4*)&a[h * 4] = *(const float4*)&As[kk][ty * MR + h * 4];
            *(float4*)&b[0] = *(const float4*)&Bs[kk][tx * 8];
            *(float4*)&b[4] = *(const float4*)&Bs[kk][tx * 8 + 4];
#pragma unroll
            for (int i = 0; i < MR; i++)
#pragma unroll
                for (int j = 0; j < 8; j++) acc[i][j] += a[i] * b[j];
        }
        __syncthreads();
    }

#pragma unroll
    for (int i = 0; i < MR; i++) {
        int gm = m0 + ty * MR + i;
        if (gm >= M) continue;
        float bv = bias[gm];
#pragma unroll
        for (int j = 0; j < 8; j++) {
            int gn = n0 + tx * 8 + j;
            if (gn >= N) continue;
            float v = acc[i][j] + bv;
            if (ACT == 1) v = v > 0.f ? v : expm1f(v);
            else v = fmaxf(v, 0.f);
            C[(size_t)gm * N + gn] = v;
        }
    }
}

// ---------------------------------------------------------------------------
// TF32 tensor-core GEMM, fragment-order smem (LDS.128/LDS.64 fragment loads).
//   LAYOUT 0 (TN): A: K x M, B: K x N.  LAYOUT 1 (NT): A: M x K, B: N x K.
//   SPLIT: hi/lo tf32 decomposition (3 mma per product) for fp32-level accuracy.
//   SUMSQ: accumulate sum(C^2) into g_sumsq (block-reduced, 1 atomic/block).
// Requires M%128==0, N%128==0, K%16==0. Tile 128x128, KT=16, 8 warps.
// ---------------------------------------------------------------------------
template <int LAYOUT, int SPLIT, int SUMSQ>
__global__ __launch_bounds__(256) void mma_gemm_kernel(
    const float* __restrict__ A, const float* __restrict__ B, float* __restrict__ C,
    int M, int N, int K) {
    constexpr int AW = 2 * 8 * 128;   // 2048 words per (hi|lo) plane
    constexpr int BW = 2 * 16 * 64;   // 2048
    __shared__ __align__(16) unsigned AsmF[AW * (SPLIT ? 2 : 1)];
    __shared__ __align__(16) unsigned BsmF[BW * (SPLIT ? 2 : 1)];
    int t = threadIdx.x;
    int m0 = blockIdx.y * 128, n0 = blockIdx.x * 128;
    int lane = t & 31, warp = t >> 5;
    int wy = warp >> 1, wx = warp & 1;

    float acc[2][8][4];
#pragma unroll
    for (int mi = 0; mi < 2; mi++)
#pragma unroll
        for (int ni = 0; ni < 8; ni++)
#pragma unroll
            for (int r = 0; r < 4; r++) acc[mi][ni][r] = 0.f;

    float4 pa[2], pb[2];

    auto load_tile = [&](int k0) {
#pragma unroll
        for (int i = 0; i < 2; i++) {
            int id = t + i * 256;
            if (LAYOUT == 0) {  // 16 rows(k) x 128 cols
                int kk = id >> 5, cg = id & 31;
                pa[i] = *(const float4*)&A[(size_t)(k0 + kk) * M + m0 + cg * 4];
                pb[i] = *(const float4*)&B[(size_t)(k0 + kk) * N + n0 + cg * 4];
            } else {            // 128 rows x 16 cols(k)
                int mm = id >> 2, kg = id & 3;
                pa[i] = *(const float4*)&A[(size_t)(m0 + mm) * K + k0 + kg * 4];
                pb[i] = *(const float4*)&B[(size_t)(n0 + mm) * K + k0 + kg * 4];
            }
        }
    };

    auto store_frag = [&]() {
#pragma unroll
        for (int i = 0; i < 2; i++) {
            int id = t + i * 256;
            const float* va = (const float*)&pa[i];
            const float* vb = (const float*)&pb[i];
#pragma unroll
            for (int j = 0; j < 4; j++) {
                int kk, cc;
                if (LAYOUT == 0) { kk = id >> 5; cc = (id & 31) * 4 + j; }
                else             { kk = (id & 3) * 4 + j; cc = id >> 2; }
                int wa = a_widx(kk, cc);
                int wb = b_widx(kk, cc);
                unsigned ha = f2tf32(va[j]);
                unsigned hb = f2tf32(vb[j]);
                AsmF[wa] = ha;
                BsmF[wb] = hb;
                if (SPLIT) {
                    AsmF[AW + wa] = f2tf32(va[j] - __uint_as_float(ha));
                    BsmF[BW + wb] = f2tf32(vb[j] - __uint_as_float(hb));
                }
            }
        }
    };

    load_tile(0);
    int nk = K >> 4;
    for (int kt = 0; kt < nk; kt++) {
        __syncthreads();
        store_frag();
        __syncthreads();
        if (kt + 1 < nk) load_tile((kt + 1) << 4);

#pragma unroll
        for (int ks = 0; ks < 2; ks++) {
            unsigned ah[2][4], al[2][4];
#pragma unroll
            for (int mi = 0; mi < 2; mi++) {
                int off = (ks * 8 + wy * 2 + mi) * 128 + lane * 4;
                *(uint4*)ah[mi] = *(const uint4*)&AsmF[off];
                if (SPLIT) *(uint4*)al[mi] = *(const uint4*)&AsmF[AW + off];
            }
#pragma unroll
            for (int ni = 0; ni < 8; ni++) {
                int off = (ks * 16 + wx * 8 + ni) * 64 + lane * 2;
                unsigned bh[2];
                *(uint2*)bh = *(const uint2*)&BsmF[off];
#pragma unroll
                for (int mi = 0; mi < 2; mi++) mma_tf32(acc[mi][ni], ah[mi], bh[0], bh[1]);
                if (SPLIT) {
                    unsigned bl[2];
                    *(uint2*)bl = *(const uint2*)&BsmF[BW + off];
#pragma unroll
                    for (int mi = 0; mi < 2; mi++) {
                        mma_tf32(acc[mi][ni], al[mi], bh[0], bh[1]);
                        mma_tf32(acc[mi][ni], ah[mi], bl[0], bl[1]);
                    }
                }
            }
        }
    }

    // Epilogue: c0,c1 -> (row g, cols 2t,2t+1); c2,c3 -> (row g+8)
    int g = lane >> 2, th = lane & 3;
    int mbase = wy * 32, nbase = wx * 64;
    float ssq = 0.f;
#pragma unroll
    for (int mi = 0; mi < 2; mi++) {
        int gm0 = m0 + mbase + mi * 16 + g;
#pragma unroll
        for (int ni = 0; ni < 8; ni++) {
            int gn = n0 + nbase + ni * 8 + 2 * th;
            float2 v0 = {acc[mi][ni][0], acc[mi][ni][1]};
            float2 v1 = {acc[mi][ni][2], acc[mi][ni][3]};
            *(float2*)&C[(size_t)gm0 * N + gn] = v0;
            *(float2*)&C[(size_t)(gm0 + 8) * N + gn] = v1;
            if (SUMSQ)
                ssq += v0.x * v0.x + v0.y * v0.y + v1.x * v1.x + v1.y * v1.y;
        }
    }
    if (SUMSQ) {
#pragma unroll
        for (int o = 16; o; o >>= 1) ssq += __shfl_down_sync(0xffffffffu, ssq, o);
        __syncthreads();  // smem fragment reads all done; reuse as scratch
        float* red = (float*)AsmF;
        if (lane == 0) red[warp] = ssq;
        __syncthreads();
        if (t < 32) {
            float v = (t < 8) ? red[t] : 0.f;
#pragma unroll
            for (int o = 4; o; o >>= 1) v += __shfl_down_sync(0xffffffffu, v, o);
            if (t == 0) atomicAdd(&g_sumsq, (double)v);
        }
    }
}

// ---------------------------------------------------------------------------
// Attention: fused downsample(::2) + mask + zero-pad 3x3 patch extraction.
// fgp/bgp are (1152, 9216) = (C*9, 96*96), row = c*9 + dy*3 + dx.
// ---------------------------------------------------------------------------
__global__ void patches_kernel(const float* __restrict__ x6, const float* __restrict__ mask,
                               float* __restrict__ fgp, float* __restrict__ bgp) {
    int idx = blockIdx.x * blockDim.x + threadIdx.x;
    if (idx >= 1152 * 9216) return;
    int p   = idx % 9216;
    int row = idx / 9216;
    int k = row % 9, c = row / 9;
    int dy = k / 3, dx = k % 3;
    int py = p / 96, px = p % 96;
    int sy = py + dy - 1, sx = px + dx - 1;
    float v = 0.f, f = 0.f;
    if (sy >= 0 && sy < 96 && sx >= 0 && sx < 96) {
        v = x6[c * 36864 + (2 * sy) * 192 + 2 * sx];
        f = v * mask[(2 * sy) * 192 + 2 * sx];
    }
    bgp[idx] = v;
    fgp[idx] = f;
}

__global__ void zero_sum_kernel() {
    if (threadIdx.x == 0 && blockIdx.x == 0) g_sumsq = 0.0;
}

// One block per row p: A[p,:] = softmax(scale * S[p,:]), scale = 10/nrm. In-place.
__global__ void softmax_kernel(float* __restrict__ S) {
    extern __shared__ float row[];  // 9216 floats
    __shared__ float red[8];
    __shared__ float bval;
    int p = blockIdx.x;
    float* Sr = S + (size_t)p * 9216;
    float nrm = fmaxf(sqrtf((float)g_sumsq), 1e-12f);
    float scale = 10.f / nrm;
    int t = threadIdx.x;
    int lane = t & 31, w = t >> 5;

    float lm = -INFINITY;
    for (int i = t; i < 9216; i += 256) {
        float v = Sr[i] * scale;
        row[i] = v;
        lm = fmaxf(lm, v);
    }
    for (int o = 16; o; o >>= 1) lm = fmaxf(lm, __shfl_xor_sync(0xffffffffu, lm, o));
    if (lane == 0) red[w] = lm;
    __syncthreads();
    if (t < 32) {
        float v = (t < 8) ? red[t] : -INFINITY;
        for (int o = 4; o; o >>= 1) v = fmaxf(v, __shfl_xor_sync(0xffffffffu, v, o));
        if (t == 0) bval = v;
    }
    __syncthreads();
    float mx = bval;

    float ls = 0.f;
    for (int i = t; i < 9216; i += 256) {
        float e = __expf(row[i] - mx);
        row[i] = e;
        ls += e;
    }
    for (int o = 16; o; o >>= 1) ls += __shfl_xor_sync(0xffffffffu, ls, o);
    __syncthreads();
    if (lane == 0) red[w] = ls;
    __syncthreads();
    if (t < 32) {
        float v = (t < 8) ? red[t] : 0.f;
        for (int o = 4; o; o >>= 1) v += __shfl_xor_sync(0xffffffffu, v, o);
        if (t == 0) bval = v;
    }
    __syncthreads();
    float inv = 1.f / bval;
    for (int i = t; i < 9216; i += 256) Sr[i] = row[i] * inv;
}

// Overlap-add fold (crop [1:97]) + mask + 2x nearest upsample.
// Rt layout: [p][c*9 + dy*3 + dx], p = py*96+px.
__global__ void fold_kernel(const float* __restrict__ Rt, const float* __restrict__ mask,
                            float* __restrict__ attn) {
    int idx = blockIdx.x * blockDim.x + threadIdx.x;
    if (idx >= 128 * 9216) return;
    int c  = idx / 9216;
    int rem = idx % 9216;
    int yy = rem / 96, xx = rem % 96;
    float s = 0.f;
#pragma unroll
    for (int dy = 0; dy < 3; dy++) {
        int py = yy + 1 - dy;
        if (py < 0 || py >= 96) continue;
#pragma unroll
        for (int dx = 0; dx < 3; dx++) {
            int px = xx + 1 - dx;
            if (px < 0 || px >= 96) continue;
            s += Rt[(size_t)(py * 96 + px) * 1152 + c * 9 + dy * 3 + dx];
        }
    }
    s *= mask[(2 * yy) * 192 + 2 * xx];
    size_t base = (size_t)c * 36864 + (size_t)(2 * yy) * 192 + 2 * xx;
    attn[base]       = s;
    attn[base + 1]   = s;
    attn[base + 192] = s;
    attn[base + 193] = s;
}

// ---------------------------------------------------------------------------
// Host orchestration
// ---------------------------------------------------------------------------
template <int ACT, int TM, int TN>
static void run_conv(const float* in, float* out, const float* w, const float* bias,
                     float* col,
                     int C, int H, int W, int OC, int KS, int pad, int stride) {
    int OH = (H + 2 * pad - KS) / stride + 1;
    int OW = (W + 2 * pad - KS) / stride + 1;
    int K = C * KS * KS, N = OH * OW, M = OC;
    int total = K * N;
    im2col_kernel<<<(total + 255) / 256, 256>>>(in, col, C, H, W, KS, pad, stride, OH, OW);
    dim3 grid((N + TN - 1) / TN, (M + TM - 1) / TM);
    conv_gemm_kernel<ACT, TM, TN><<<grid, 256>>>(w, col, bias, out, M, N, K);
}

extern "C" void kernel_launch(void* const* d_in, const int* in_sizes, int n_in,
                              void* d_out, int out_size) {
    const float* x    = (const float*)d_in[0];
    const float* mask = (const float*)d_in[1];
    const float* w[8];
    const float* b[8];
    for (int i = 0; i < 8; i++) {
        w[i] = (const float*)d_in[2 + 2 * i];
        b[i] = (const float*)d_in[3 + 2 * i];
    }

    float *col, *b1, *b2, *b3, *b4, *b5, *b6, *fgp, *bgp, *S, *Rt, *attn, *b7;
    cudaGetSymbolAddress((void**)&col,  g_col);
    cudaGetSymbolAddress((void**)&b1,   g_b1);
    cudaGetSymbolAddress((void**)&b2,   g_b2);
    cudaGetSymbolAddress((void**)&b3,   g_b3);
    cudaGetSymbolAddress((void**)&b4,   g_b4);
    cudaGetSymbolAddress((void**)&b5,   g_b5);
    cudaGetSymbolAddress((void**)&b6,   g_b6);
    cudaGetSymbolAddress((void**)&fgp,  g_fgp);
    cudaGetSymbolAddress((void**)&bgp,  g_bgp);
    cudaGetSymbolAddress((void**)&S,    g_S);
    cudaGetSymbolAddress((void**)&Rt,   g_Rt);
    cudaGetSymbolAddress((void**)&attn, g_attn);
    cudaGetSymbolAddress((void**)&b7,   g_b7);

    // Encoder
    run_conv<1,  32, 256>(x,  b1, w[0], b[0], col,   3, 768, 768,  32, 5, 2, 1);
    run_conv<1,  32, 256>(b1, b2, w[1], b[1], col,  32, 768, 768,  32, 3, 1, 2);
    run_conv<1,  64, 128>(b2, b3, w[2], b[2], col,  32, 384, 384,  64, 3, 1, 1);
    run_conv<1, 128, 128>(b3, b4, w[3], b[3], col,  64, 384, 384, 128, 3, 1, 2);
    run_conv<1, 128, 128>(b4, b5, w[4], b[4], col, 128, 192, 192, 128, 3, 1, 1);
    run_conv<2, 128, 128>(b5, b6, w[5], b[5], col, 128, 192, 192, 128, 3, 1, 1);  // relu

    // Contextual attention
    patches_kernel<<<(1152 * 9216 + 255) / 256, 256>>>(b6, mask, fgp, bgp);
    zero_sum_kernel<<<1, 32>>>();
    {
        // S = fgp^T * bgp : M=N=9216, K=1152. TN layout, plain tf32, fused sumsq.
        dim3 g(72, 72);
        mma_gemm_kernel<0, 0, 1><<<g, 256>>>(fgp, bgp, S, 9216, 9216, 1152);
    }
    softmax_kernel<<<9216, 256, 9216 * sizeof(float)>>>(S);
    {
        // Rt[p,c] = sum_q A[p,q]*bgp[c,q] : M=9216, N=1152, K=9216. NT, split tf32.
        dim3 g(9, 72);
        mma_gemm_kernel<1, 1, 0><<<g, 256>>>(S, bgp, Rt, 9216, 1152, 9216);
    }
    fold_kernel<<<(128 * 9216 + 255) / 256, 256>>>(Rt, mask, attn);

    // Decoder head
    run_conv<1, 128, 128>(attn, b7,          w[6], b[6], col, 128, 192, 192, 128, 3, 1, 1);
    run_conv<1, 128, 128>(b7, (float*)d_out, w[7], b[7], col, 128, 192, 192, 128, 3, 1, 1);
}

// round 6
// speedup vs baseline: 1.5102x; 1.5102x over previous
#include <cuda_runtime.h>
#include <stdint.h>
#include <cstdint>
#include <math.h>

// ---------------------------------------------------------------------------
// Scratch (device globals -- allocation-free per harness rules)
// ---------------------------------------------------------------------------
__device__ float  g_col[44236800];   // im2col scratch (max: conv1 75*589824)
__device__ float  g_b1[18874368];    // conv1 out 32*768*768
__device__ float  g_b2[4718592];    // conv2 out 32*384*384
__device__ float  g_b3[9437184];    // conv3 out 64*384*384
__device__ float  g_b4[4718592];    // conv4 out 128*192*192
__device__ float  g_b5[4718592];    // conv5 out
__device__ float  g_b6[4718592];    // conv6 out (attention input)
__device__ float  g_fgp[10616832];  // 1152 x 9216   (K x M for S)
__device__ float  g_bgp[10616832];  // 1152 x 9216   (K x N for S; N x K for R)
__device__ float  g_S[84934656];    // 9216 x 9216 (S, then softmaxed A in-place)
__device__ float  g_Rt[10616832];   // 9216 x 1152 (R transposed: [p][c*9+k])
__device__ float  g_attn[4718592];  // attention out 128*192*192
__device__ float  g_b7[4718592];    // conv7 out
__device__ double g_sumsq;          // Frobenius norm accumulator

// ---------------------------------------------------------------------------
// Helpers
// ---------------------------------------------------------------------------
__device__ __forceinline__ int refl(int i, int n) {
    if (i < 0) i = -i;
    if (i >= n) i = 2 * n - 2 - i;
    return i;
}

__device__ __forceinline__ unsigned f2tf32(float x) {
    unsigned r;
    asm("cvt.rna.tf32.f32 %0, %1;" : "=r"(r) : "f"(x));
    return r;
}

__device__ __forceinline__ void mma_tf32(float* c, const unsigned* a, unsigned b0, unsigned b1) {
    asm volatile(
        "mma.sync.aligned.m16n8k8.row.col.f32.tf32.tf32.f32 "
        "{%0,%1,%2,%3},{%4,%5,%6,%7},{%8,%9},{%0,%1,%2,%3};\n"
        : "+f"(c[0]), "+f"(c[1]), "+f"(c[2]), "+f"(c[3])
        : "r"(a[0]), "r"(a[1]), "r"(a[2]), "r"(a[3]), "r"(b0), "r"(b1));
}

// Per-row group rotation to break store bank conflicts while keeping
// fragment loads (per-warp constant row) conflict-free permutations.
__device__ __forceinline__ int rot(int r) { return r + (r >> 3); }

// Fragment-order word index within one 16k x 128m A tile, swizzled.
// Row r = ks*8+mb holds 32 groups of 4 words (one LDS.128 per lane at load).
// a0=(row g,col th) a1=(g+8,th) a2=(g,th+4) a3=(g+8,th+4); lane = g*4+th.
__device__ __forceinline__ int a_widx(int kk, int mm) {
    int ks = kk >> 3, k = kk & 7;
    int th = k & 3, rh = (k >> 2) & 1;
    int mb = mm >> 4, rr = mm & 15, g = rr & 7, mh = (rr >> 3) & 1;
    int r = ks * 8 + mb;
    int grp = (g * 4 + th + rot(r)) & 31;
    return r * 128 + grp * 4 + rh * 2 + mh;
}
// B tile: row R = ks*16+nb holds 32 groups of 2 words (LDS.64 at load).
// b0=(k th, n g), b1=(k th+4, n g); lane = g*4+th.
__device__ __forceinline__ int b_widx(int kk, int nn) {
    int ks = kk >> 3, k = kk & 7;
    int th = k & 3, rh = (k >> 2) & 1;
    int nb = nn >> 3, g = nn & 7;
    int R = ks * 16 + nb;
    int grp = (g * 4 + th + rot(R)) & 31;
    return R * 64 + grp * 2 + rh;
}

// im2col with reflect padding (matches jnp.pad mode='reflect')
__global__ void im2col_kernel(const float* __restrict__ in, float* __restrict__ col,
                              int C, int H, int W, int KS, int pad, int stride,
                              int OH, int OW) {
    int total = C * KS * KS * OH * OW;
    int idx = blockIdx.x * blockDim.x + threadIdx.x;
    if (idx >= total) return;
    int hw  = OH * OW;
    int pix = idx % hw;
    int row = idx / hw;
    int kx = row % KS;
    int ky = (row / KS) % KS;
    int c  = row / (KS * KS);
    int oy = pix / OW, ox = pix % OW;
    int iy = refl(oy * stride + ky - pad, H);
    int ix = refl(ox * stride + kx - pad, W);
    col[idx] = in[(size_t)c * H * W + (size_t)iy * W + ix];
}

// ---------------------------------------------------------------------------
// FFMA conv GEMM: C[m,n] = act(sum_k A[m,k]*B[k,n] + bias[m])
// A: M x K weights, B: K x N im2col. Tile TM x TN, 256 threads, KT=8.
// ---------------------------------------------------------------------------
template <int ACT, int TM, int TN>
__global__ __launch_bounds__(256, 2) void conv_gemm_kernel(
    const float* __restrict__ A, const float* __restrict__ B,
    const float* __restrict__ bias, float* __restrict__ C,
    int M, int N, int K) {
    constexpr int TNTH = TN / 8;        // threads along n
    constexpr int TMTH = 256 / TNTH;    // threads along m
    constexpr int MR   = TM / TMTH;     // rows per thread (4 or 8)
    __shared__ __align__(16) float As[8][TM + 4];
    __shared__ __align__(16) float Bs[8][TN + 4];
    int t  = threadIdx.x;
    int tx = t % TNTH, ty = t / TNTH;
    int m0 = blockIdx.y * TM, n0 = blockIdx.x * TN;

    float acc[MR][8];
#pragma unroll
    for (int i = 0; i < MR; i++)
#pragma unroll
        for (int j = 0; j < 8; j++) acc[i][j] = 0.f;

    for (int k0 = 0; k0 < K; k0 += 8) {
#pragma unroll
        for (int i = 0; i < TM * 8 / 256; i++) {
            int id = t + i * 256;
            int kk = id & 7, mm = id >> 3;
            int gk = k0 + kk;
            As[kk][mm] = (gk < K && m0 + mm < M) ? A[(size_t)(m0 + mm) * K + gk] : 0.f;
        }
#pragma unroll
        for (int i = 0; i < TN * 8 / 256; i++) {
            int id = t + i * 256;
            int kk = id / TN, nn = id % TN;
            int gk = k0 + kk;
            Bs[kk][nn] = (gk < K && n0 + nn < N) ? B[(size_t)gk * N + n0 + nn] : 0.f;
        }
        __syncthreads();
#pragma unroll
        for (int kk = 0; kk < 8; kk++) {
            float a[MR], b[8];
#pragma unroll
            for (int h = 0; h < MR / 4; h++)
                *(float4*)&a[h * 4] = *(const float4*)&As[kk][ty * MR + h * 4];
            *(float4*)&b[0] = *(const float4*)&Bs[kk][tx * 8];
            *(float4*)&b[4] = *(const float4*)&Bs[kk][tx * 8 + 4];
#pragma unroll
            for (int i = 0; i < MR; i++)
#pragma unroll
                for (int j = 0; j < 8; j++) acc[i][j] += a[i] * b[j];
        }
        __syncthreads();
    }

#pragma unroll
    for (int i = 0; i < MR; i++) {
        int gm = m0 + ty * MR + i;
        if (gm >= M) continue;
        float bv = bias[gm];
#pragma unroll
        for (int j = 0; j < 8; j++) {
            int gn = n0 + tx * 8 + j;
            if (gn >= N) continue;
            float v = acc[i][j] + bv;
            if (ACT == 1) v = v > 0.f ? v : expm1f(v);
            else v = fmaxf(v, 0.f);
            C[(size_t)gm * N + gn] = v;
        }
    }
}

// ---------------------------------------------------------------------------
// TF32 tensor-core GEMM, swizzled fragment-order smem:
//   loads are LDS.128 (A) / LDS.64 (B), conflict-free;
//   stores are STS.32 with <=4-way conflicts (per-row group rotation).
//   LAYOUT 0 (TN): A: K x M, B: K x N.  LAYOUT 1 (NT): A: M x K, B: N x K.
//   SPLIT: hi/lo tf32 decomposition (3 mma per product) for fp32-level accuracy.
//   SUMSQ: accumulate sum(C^2) into g_sumsq (block-reduced, 1 atomic/block).
// Requires M%128==0, N%128==0, K%16==0. Tile 128x128, KT=16, 8 warps.
// ---------------------------------------------------------------------------
template <int LAYOUT, int SPLIT, int SUMSQ>
__global__ __launch_bounds__(256) void mma_gemm_kernel(
    const float* __restrict__ A, const float* __restrict__ B, float* __restrict__ C,
    int M, int N, int K) {
    constexpr int AW = 2 * 8 * 128;   // 2048 words per (hi|lo) plane
    constexpr int BW = 2 * 16 * 64;   // 2048
    __shared__ __align__(16) unsigned AsmF[AW * (SPLIT ? 2 : 1)];
    __shared__ __align__(16) unsigned BsmF[BW * (SPLIT ? 2 : 1)];
    int t = threadIdx.x;
    int m0 = blockIdx.y * 128, n0 = blockIdx.x * 128;
    int lane = t & 31, warp = t >> 5;
    int wy = warp >> 1, wx = warp & 1;

    float acc[2][8][4];
#pragma unroll
    for (int mi = 0; mi < 2; mi++)
#pragma unroll
        for (int ni = 0; ni < 8; ni++)
#pragma unroll
            for (int r = 0; r < 4; r++) acc[mi][ni][r] = 0.f;

    float4 pa[2], pb[2];

    auto load_tile = [&](int k0) {
#pragma unroll
        for (int i = 0; i < 2; i++) {
            int id = t + i * 256;
            if (LAYOUT == 0) {  // 16 rows(k) x 128 cols
                int kk = id >> 5, cg = id & 31;
                pa[i] = *(const float4*)&A[(size_t)(k0 + kk) * M + m0 + cg * 4];
                pb[i] = *(const float4*)&B[(size_t)(k0 + kk) * N + n0 + cg * 4];
            } else {            // 128 rows x 16 cols(k)
                int mm = id >> 2, kg = id & 3;
                pa[i] = *(const float4*)&A[(size_t)(m0 + mm) * K + k0 + kg * 4];
                pb[i] = *(const float4*)&B[(size_t)(n0 + mm) * K + k0 + kg * 4];
            }
        }
    };

    auto store_frag = [&]() {
#pragma unroll
        for (int i = 0; i < 2; i++) {
            int id = t + i * 256;
            const float* va = (const float*)&pa[i];
            const float* vb = (const float*)&pb[i];
#pragma unroll
            for (int j = 0; j < 4; j++) {
                int kk, cc;
                if (LAYOUT == 0) { kk = id >> 5; cc = (id & 31) * 4 + j; }
                else             { kk = (id & 3) * 4 + j; cc = id >> 2; }
                int wa = a_widx(kk, cc);
                int wb = b_widx(kk, cc);
                unsigned ha = f2tf32(va[j]);
                unsigned hb = f2tf32(vb[j]);
                AsmF[wa] = ha;
                BsmF[wb] = hb;
                if (SPLIT) {
                    AsmF[AW + wa] = f2tf32(va[j] - __uint_as_float(ha));
                    BsmF[BW + wb] = f2tf32(vb[j] - __uint_as_float(hb));
                }
            }
        }
    };

    load_tile(0);
    int nk = K >> 4;
    for (int kt = 0; kt < nk; kt++) {
        __syncthreads();
        store_frag();
        __syncthreads();
        if (kt + 1 < nk) load_tile((kt + 1) << 4);

#pragma unroll
        for (int ks = 0; ks < 2; ks++) {
            unsigned ah[2][4], al[2][4];
#pragma unroll
            for (int mi = 0; mi < 2; mi++) {
                int r = ks * 8 + wy * 2 + mi;
                int off = r * 128 + ((lane + rot(r)) & 31) * 4;
                *(uint4*)ah[mi] = *(const uint4*)&AsmF[off];
                if (SPLIT) *(uint4*)al[mi] = *(const uint4*)&AsmF[AW + off];
            }
#pragma unroll
            for (int ni = 0; ni < 8; ni++) {
                int R = ks * 16 + wx * 8 + ni;
                int off = R * 64 + ((lane + rot(R)) & 31) * 2;
                unsigned bh[2];
                *(uint2*)bh = *(const uint2*)&BsmF[off];
#pragma unroll
                for (int mi = 0; mi < 2; mi++) mma_tf32(acc[mi][ni], ah[mi], bh[0], bh[1]);
                if (SPLIT) {
                    unsigned bl[2];
                    *(uint2*)bl = *(const uint2*)&BsmF[BW + off];
#pragma unroll
                    for (int mi = 0; mi < 2; mi++) {
                        mma_tf32(acc[mi][ni], al[mi], bh[0], bh[1]);
                        mma_tf32(acc[mi][ni], ah[mi], bl[0], bl[1]);
                    }
                }
            }
        }
    }

    // Epilogue: c0,c1 -> (row g, cols 2t,2t+1); c2,c3 -> (row g+8)
    int g = lane >> 2, th = lane & 3;
    int mbase = wy * 32, nbase = wx * 64;
    float ssq = 0.f;
#pragma unroll
    for (int mi = 0; mi < 2; mi++) {
        int gm0 = m0 + mbase + mi * 16 + g;
#pragma unroll
        for (int ni = 0; ni < 8; ni++) {
            int gn = n0 + nbase + ni * 8 + 2 * th;
            float2 v0 = {acc[mi][ni][0], acc[mi][ni][1]};
            float2 v1 = {acc[mi][ni][2], acc[mi][ni][3]};
            *(float2*)&C[(size_t)gm0 * N + gn] = v0;
            *(float2*)&C[(size_t)(gm0 + 8) * N + gn] = v1;
            if (SUMSQ)
                ssq += v0.x * v0.x + v0.y * v0.y + v1.x * v1.x + v1.y * v1.y;
        }
    }
    if (SUMSQ) {
#pragma unroll
        for (int o = 16; o; o >>= 1) ssq += __shfl_down_sync(0xffffffffu, ssq, o);
        __syncthreads();  // smem fragment reads all done; reuse as scratch
        float* red = (float*)AsmF;
        if (lane == 0) red[warp] = ssq;
        __syncthreads();
        if (t < 32) {
            float v = (t < 8) ? red[t] : 0.f;
#pragma unroll
            for (int o = 4; o; o >>= 1) v += __shfl_down_sync(0xffffffffu, v, o);
            if (t == 0) atomicAdd(&g_sumsq, (double)v);
        }
    }
}

// ---------------------------------------------------------------------------
// Attention: fused downsample(::2) + mask + zero-pad 3x3 patch extraction.
// fgp/bgp are (1152, 9216) = (C*9, 96*96), row = c*9 + dy*3 + dx.
// ---------------------------------------------------------------------------
__global__ void patches_kernel(const float* __restrict__ x6, const float* __restrict__ mask,
                               float* __restrict__ fgp, float* __restrict__ bgp) {
    int idx = blockIdx.x * blockDim.x + threadIdx.x;
    if (idx >= 1152 * 9216) return;
    int p   = idx % 9216;
    int row = idx / 9216;
    int k = row % 9, c = row / 9;
    int dy = k / 3, dx = k % 3;
    int py = p / 96, px = p % 96;
    int sy = py + dy - 1, sx = px + dx - 1;
    float v = 0.f, f = 0.f;
    if (sy >= 0 && sy < 96 && sx >= 0 && sx < 96) {
        v = x6[c * 36864 + (2 * sy) * 192 + 2 * sx];
        f = v * mask[(2 * sy) * 192 + 2 * sx];
    }
    bgp[idx] = v;
    fgp[idx] = f;
}

__global__ void zero_sum_kernel() {
    if (threadIdx.x == 0 && blockIdx.x == 0) g_sumsq = 0.0;
}

// One block per row p: A[p,:] = softmax(scale * S[p,:]), scale = 10/nrm. In-place.
__global__ void softmax_kernel(float* __restrict__ S) {
    extern __shared__ float row[];  // 9216 floats
    __shared__ float red[8];
    __shared__ float bval;
    int p = blockIdx.x;
    float* Sr = S + (size_t)p * 9216;
    float nrm = fmaxf(sqrtf((float)g_sumsq), 1e-12f);
    float scale = 10.f / nrm;
    int t = threadIdx.x;
    int lane = t & 31, w = t >> 5;

    float lm = -INFINITY;
    for (int i = t; i < 9216; i += 256) {
        float v = Sr[i] * scale;
        row[i] = v;
        lm = fmaxf(lm, v);
    }
    for (int o = 16; o; o >>= 1) lm = fmaxf(lm, __shfl_xor_sync(0xffffffffu, lm, o));
    if (lane == 0) red[w] = lm;
    __syncthreads();
    if (t < 32) {
        float v = (t < 8) ? red[t] : -INFINITY;
        for (int o = 4; o; o >>= 1) v = fmaxf(v, __shfl_xor_sync(0xffffffffu, v, o));
        if (t == 0) bval = v;
    }
    __syncthreads();
    float mx = bval;

    float ls = 0.f;
    for (int i = t; i < 9216; i += 256) {
        float e = __expf(row[i] - mx);
        row[i] = e;
        ls += e;
    }
    for (int o = 16; o; o >>= 1) ls += __shfl_xor_sync(0xffffffffu, ls, o);
    __syncthreads();
    if (lane == 0) red[w] = ls;
    __syncthreads();
    if (t < 32) {
        float v = (t < 8) ? red[t] : 0.f;
        for (int o = 4; o; o >>= 1) v += __shfl_xor_sync(0xffffffffu, v, o);
        if (t == 0) bval = v;
    }
    __syncthreads();
    float inv = 1.f / bval;
    for (int i = t; i < 9216; i += 256) Sr[i] = row[i] * inv;
}

// Overlap-add fold (crop [1:97]) + mask + 2x nearest upsample.
// Rt layout: [p][c*9 + dy*3 + dx], p = py*96+px.
__global__ void fold_kernel(const float* __restrict__ Rt, const float* __restrict__ mask,
                            float* __restrict__ attn) {
    int idx = blockIdx.x * blockDim.x + threadIdx.x;
    if (idx >= 128 * 9216) return;
    int c  = idx / 9216;
    int rem = idx % 9216;
    int yy = rem / 96, xx = rem % 96;
    float s = 0.f;
#pragma unroll
    for (int dy = 0; dy < 3; dy++) {
        int py = yy + 1 - dy;
        if (py < 0 || py >= 96) continue;
#pragma unroll
        for (int dx = 0; dx < 3; dx++) {
            int px = xx + 1 - dx;
            if (px < 0 || px >= 96) continue;
            s += Rt[(size_t)(py * 96 + px) * 1152 + c * 9 + dy * 3 + dx];
        }
    }
    s *= mask[(2 * yy) * 192 + 2 * xx];
    size_t base = (size_t)c * 36864 + (size_t)(2 * yy) * 192 + 2 * xx;
    attn[base]       = s;
    attn[base + 1]   = s;
    attn[base + 192] = s;
    attn[base + 193] = s;
}

// ---------------------------------------------------------------------------
// Host orchestration
// ---------------------------------------------------------------------------
template <int ACT, int TM, int TN>
static void run_conv(const float* in, float* out, const float* w, const float* bias,
                     float* col,
                     int C, int H, int W, int OC, int KS, int pad, int stride) {
    int OH = (H + 2 * pad - KS) / stride + 1;
    int OW = (W + 2 * pad - KS) / stride + 1;
    int K = C * KS * KS, N = OH * OW, M = OC;
    int total = K * N;
    im2col_kernel<<<(total + 255) / 256, 256>>>(in, col, C, H, W, KS, pad, stride, OH, OW);
    dim3 grid((N + TN - 1) / TN, (M + TM - 1) / TM);
    conv_gemm_kernel<ACT, TM, TN><<<grid, 256>>>(w, col, bias, out, M, N, K);
}

extern "C" void kernel_launch(void* const* d_in, const int* in_sizes, int n_in,
                              void* d_out, int out_size) {
    const float* x    = (const float*)d_in[0];
    const float* mask = (const float*)d_in[1];
    const float* w[8];
    const float* b[8];
    for (int i = 0; i < 8; i++) {
        w[i] = (const float*)d_in[2 + 2 * i];
        b[i] = (const float*)d_in[3 + 2 * i];
    }

    float *col, *b1, *b2, *b3, *b4, *b5, *b6, *fgp, *bgp, *S, *Rt, *attn, *b7;
    cudaGetSymbolAddress((void**)&col,  g_col);
    cudaGetSymbolAddress((void**)&b1,   g_b1);
    cudaGetSymbolAddress((void**)&b2,   g_b2);
    cudaGetSymbolAddress((void**)&b3,   g_b3);
    cudaGetSymbolAddress((void**)&b4,   g_b4);
    cudaGetSymbolAddress((void**)&b5,   g_b5);
    cudaGetSymbolAddress((void**)&b6,   g_b6);
    cudaGetSymbolAddress((void**)&fgp,  g_fgp);
    cudaGetSymbolAddress((void**)&bgp,  g_bgp);
    cudaGetSymbolAddress((void**)&S,    g_S);
    cudaGetSymbolAddress((void**)&Rt,   g_Rt);
    cudaGetSymbolAddress((void**)&attn, g_attn);
    cudaGetSymbolAddress((void**)&b7,   g_b7);

    // Encoder
    run_conv<1,  32, 256>(x,  b1, w[0], b[0], col,   3, 768, 768,  32, 5, 2, 1);
    run_conv<1,  32, 256>(b1, b2, w[1], b[1], col,  32, 768, 768,  32, 3, 1, 2);
    run_conv<1,  64, 128>(b2, b3, w[2], b[2], col,  32, 384, 384,  64, 3, 1, 1);
    run_conv<1, 128, 128>(b3, b4, w[3], b[3], col,  64, 384, 384, 128, 3, 1, 2);
    run_conv<1, 128, 128>(b4, b5, w[4], b[4], col, 128, 192, 192, 128, 3, 1, 1);
    run_conv<2, 128, 128>(b5, b6, w[5], b[5], col, 128, 192, 192, 128, 3, 1, 1);  // relu

    // Contextual attention
    patches_kernel<<<(1152 * 9216 + 255) / 256, 256>>>(b6, mask, fgp, bgp);
    zero_sum_kernel<<<1, 32>>>();
    {
        // S = fgp^T * bgp : M=N=9216, K=1152. TN layout, plain tf32, fused sumsq.
        dim3 g(72, 72);
        mma_gemm_kernel<0, 0, 1><<<g, 256>>>(fgp, bgp, S, 9216, 9216, 1152);
    }
    softmax_kernel<<<9216, 256, 9216 * sizeof(float)>>>(S);
    {
        // Rt[p,c] = sum_q A[p,q]*bgp[c,q] : M=9216, N=1152, K=9216. NT, split tf32.
        dim3 g(9, 72);
        mma_gemm_kernel<1, 1, 0><<<g, 256>>>(S, bgp, Rt, 9216, 1152, 9216);
    }
    fold_kernel<<<(128 * 9216 + 255) / 256, 256>>>(Rt, mask, attn);

    // Decoder head
    run_conv<1, 128, 128>(attn, b7,          w[6], b[6], col, 128, 192, 192, 128, 3, 1, 1);
    run_conv<1, 128, 128>(b7, (float*)d_out, w[7], b[7], col, 128, 192, 192, 128, 3, 1, 1);
}

// round 7
// speedup vs baseline: 2.4911x; 1.6495x over previous
#include <cuda_runtime.h>
#include <stdint.h>
#include <cstdint>
#include <math.h>

// ---------------------------------------------------------------------------
// Scratch (device globals -- allocation-free per harness rules)
// ---------------------------------------------------------------------------
__device__ float  g_col[44236800];   // im2col scratch (max: conv1 75*589824)
__device__ float  g_b1[18874368];    // conv1 out 32*768*768
__device__ float  g_b2[4718592];    // conv2 out 32*384*384
__device__ float  g_b3[9437184];    // conv3 out 64*384*384
__device__ float  g_b4[4718592];    // conv4 out 128*192*192
__device__ float  g_b5[4718592];    // conv5 out
__device__ float  g_b6[4718592];    // conv6 out (attention input)
__device__ float  g_fg[1179648];    // fg = ds*mask, 128 x 9216 (K x M for C)
__device__ float  g_ds[1179648];    // ds downsampled bg, 128 x 9216
__device__ float  g_S[84934656];    // 9216 x 9216 (S, then softmaxed A in-place)
__device__ float  g_CM[84934656];   // C = fg^T ds, later M = diag9(A)
__device__ float  g_Rt[1179648];    // final gemm out: 9216 x 128 [x][c]
__device__ float  g_attn[4718592];  // attention out 128*192*192
__device__ float  g_b7[4718592];    // conv7 out
__device__ double g_sumsq;          // Frobenius norm accumulator

// ---------------------------------------------------------------------------
// Helpers
// ---------------------------------------------------------------------------
__device__ __forceinline__ int refl(int i, int n) {
    if (i < 0) i = -i;
    if (i >= n) i = 2 * n - 2 - i;
    return i;
}

__device__ __forceinline__ unsigned f2tf32(float x) {
    unsigned r;
    asm("cvt.rna.tf32.f32 %0, %1;" : "=r"(r) : "f"(x));
    return r;
}

__device__ __forceinline__ void mma_tf32(float* c, const unsigned* a, unsigned b0, unsigned b1) {
    asm volatile(
        "mma.sync.aligned.m16n8k8.row.col.f32.tf32.tf32.f32 "
        "{%0,%1,%2,%3},{%4,%5,%6,%7},{%8,%9},{%0,%1,%2,%3};\n"
        : "+f"(c[0]), "+f"(c[1]), "+f"(c[2]), "+f"(c[3])
        : "r"(a[0]), "r"(a[1]), "r"(a[2]), "r"(a[3]), "r"(b0), "r"(b1));
}

// Per-row group rotation to break store bank conflicts while keeping
// fragment loads (per-warp constant row) conflict-free permutations.
__device__ __forceinline__ int rot(int r) { return r + (r >> 3); }

// Fragment-order word index within one 16k x 128m A tile, swizzled.
__device__ __forceinline__ int a_widx(int kk, int mm) {
    int ks = kk >> 3, k = kk & 7;
    int th = k & 3, rh = (k >> 2) & 1;
    int mb = mm >> 4, rr = mm & 15, g = rr & 7, mh = (rr >> 3) & 1;
    int r = ks * 8 + mb;
    int grp = (g * 4 + th + rot(r)) & 31;
    return r * 128 + grp * 4 + rh * 2 + mh;
}
__device__ __forceinline__ int b_widx(int kk, int nn) {
    int ks = kk >> 3, k = kk & 7;
    int th = k & 3, rh = (k >> 2) & 1;
    int nb = nn >> 3, g = nn & 7;
    int R = ks * 16 + nb;
    int grp = (g * 4 + th + rot(R)) & 31;
    return R * 64 + grp * 2 + rh;
}

// im2col with reflect padding (matches jnp.pad mode='reflect')
__global__ void im2col_kernel(const float* __restrict__ in, float* __restrict__ col,
                              int C, int H, int W, int KS, int pad, int stride,
                              int OH, int OW) {
    int total = C * KS * KS * OH * OW;
    int idx = blockIdx.x * blockDim.x + threadIdx.x;
    if (idx >= total) return;
    int hw  = OH * OW;
    int pix = idx % hw;
    int row = idx / hw;
    int kx = row % KS;
    int ky = (row / KS) % KS;
    int c  = row / (KS * KS);
    int oy = pix / OW, ox = pix % OW;
    int iy = refl(oy * stride + ky - pad, H);
    int ix = refl(ox * stride + kx - pad, W);
    col[idx] = in[(size_t)c * H * W + (size_t)iy * W + ix];
}

// ---------------------------------------------------------------------------
// FFMA conv GEMM: C[m,n] = act(sum_k A[m,k]*B[k,n] + bias[m])
// ---------------------------------------------------------------------------
template <int ACT, int TM, int TN>
__global__ __launch_bounds__(256, 2) void conv_gemm_kernel(
    const float* __restrict__ A, const float* __restrict__ B,
    const float* __restrict__ bias, float* __restrict__ C,
    int M, int N, int K) {
    constexpr int TNTH = TN / 8;
    constexpr int TMTH = 256 / TNTH;
    constexpr int MR   = TM / TMTH;
    __shared__ __align__(16) float As[8][TM + 4];
    __shared__ __align__(16) float Bs[8][TN + 4];
    int t  = threadIdx.x;
    int tx = t % TNTH, ty = t / TNTH;
    int m0 = blockIdx.y * TM, n0 = blockIdx.x * TN;

    float acc[MR][8];
#pragma unroll
    for (int i = 0; i < MR; i++)
#pragma unroll
        for (int j = 0; j < 8; j++) acc[i][j] = 0.f;

    for (int k0 = 0; k0 < K; k0 += 8) {
#pragma unroll
        for (int i = 0; i < TM * 8 / 256; i++) {
            int id = t + i * 256;
            int kk = id & 7, mm = id >> 3;
            int gk = k0 + kk;
            As[kk][mm] = (gk < K && m0 + mm < M) ? A[(size_t)(m0 + mm) * K + gk] : 0.f;
        }
#pragma unroll
        for (int i = 0; i < TN * 8 / 256; i++) {
            int id = t + i * 256;
            int kk = id / TN, nn = id % TN;
            int gk = k0 + kk;
            Bs[kk][nn] = (gk < K && n0 + nn < N) ? B[(size_t)gk * N + n0 + nn] : 0.f;
        }
        __syncthreads();
#pragma unroll
        for (int kk = 0; kk < 8; kk++) {
            float a[MR], b[8];
#pragma unroll
            for (int h = 0; h < MR / 4; h++)
                *(float4*)&a[h * 4] = *(const float4*)&As[kk][ty * MR + h * 4];
            *(float4*)&b[0] = *(const float4*)&Bs[kk][tx * 8];
            *(float4*)&b[4] = *(const float4*)&Bs[kk][tx * 8 + 4];
#pragma unroll
            for (int i = 0; i < MR; i++)
#pragma unroll
                for (int j = 0; j < 8; j++) acc[i][j] += a[i] * b[j];
        }
        __syncthreads();
    }

#pragma unroll
    for (int i = 0; i < MR; i++) {
        int gm = m0 + ty * MR + i;
        if (gm >= M) continue;
        float bv = bias[gm];
#pragma unroll
        for (int j = 0; j < 8; j++) {
            int gn = n0 + tx * 8 + j;
            if (gn >= N) continue;
            float v = acc[i][j] + bv;
            if (ACT == 1) v = v > 0.f ? v : expm1f(v);
            else v = fmaxf(v, 0.f);
            C[(size_t)gm * N + gn] = v;
        }
    }
}

// ---------------------------------------------------------------------------
// TF32 tensor-core GEMM, swizzled fragment-order smem.
//   LAYOUT 0 (TN): A: K x M, B: K x N.  LAYOUT 1 (NT): A: M x K, B: N x K.
//   SPLIT: hi/lo tf32 decomposition for fp32-level accuracy.
// Requires M%128==0, N%128==0, K%16==0. Tile 128x128, KT=16, 8 warps.
// ---------------------------------------------------------------------------
template <int LAYOUT, int SPLIT>
__global__ __launch_bounds__(256) void mma_gemm_kernel(
    const float* __restrict__ A, const float* __restrict__ B, float* __restrict__ C,
    int M, int N, int K) {
    constexpr int AW = 2 * 8 * 128;
    constexpr int BW = 2 * 16 * 64;
    __shared__ __align__(16) unsigned AsmF[AW * (SPLIT ? 2 : 1)];
    __shared__ __align__(16) unsigned BsmF[BW * (SPLIT ? 2 : 1)];
    int t = threadIdx.x;
    int m0 = blockIdx.y * 128, n0 = blockIdx.x * 128;
    int lane = t & 31, warp = t >> 5;
    int wy = warp >> 1, wx = warp & 1;

    float acc[2][8][4];
#pragma unroll
    for (int mi = 0; mi < 2; mi++)
#pragma unroll
        for (int ni = 0; ni < 8; ni++)
#pragma unroll
            for (int r = 0; r < 4; r++) acc[mi][ni][r] = 0.f;

    float4 pa[2], pb[2];

    auto load_tile = [&](int k0) {
#pragma unroll
        for (int i = 0; i < 2; i++) {
            int id = t + i * 256;
            if (LAYOUT == 0) {
                int kk = id >> 5, cg = id & 31;
                pa[i] = *(const float4*)&A[(size_t)(k0 + kk) * M + m0 + cg * 4];
                pb[i] = *(const float4*)&B[(size_t)(k0 + kk) * N + n0 + cg * 4];
            } else {
                int mm = id >> 2, kg = id & 3;
                pa[i] = *(const float4*)&A[(size_t)(m0 + mm) * K + k0 + kg * 4];
                pb[i] = *(const float4*)&B[(size_t)(n0 + mm) * K + k0 + kg * 4];
            }
        }
    };

    auto store_frag = [&]() {
#pragma unroll
        for (int i = 0; i < 2; i++) {
            int id = t + i * 256;
            const float* va = (const float*)&pa[i];
            const float* vb = (const float*)&pb[i];
#pragma unroll
            for (int j = 0; j < 4; j++) {
                int kk, cc;
                if (LAYOUT == 0) { kk = id >> 5; cc = (id & 31) * 4 + j; }
                else             { kk = (id & 3) * 4 + j; cc = id >> 2; }
                int wa = a_widx(kk, cc);
                int wb = b_widx(kk, cc);
                unsigned ha = f2tf32(va[j]);
                unsigned hb = f2tf32(vb[j]);
                AsmF[wa] = ha;
                BsmF[wb] = hb;
                if (SPLIT) {
                    AsmF[AW + wa] = f2tf32(va[j] - __uint_as_float(ha));
                    BsmF[BW + wb] = f2tf32(vb[j] - __uint_as_float(hb));
                }
            }
        }
    };

    load_tile(0);
    int nk = K >> 4;
    for (int kt = 0; kt < nk; kt++) {
        __syncthreads();
        store_frag();
        __syncthreads();
        if (kt + 1 < nk) load_tile((kt + 1) << 4);

#pragma unroll
        for (int ks = 0; ks < 2; ks++) {
            unsigned ah[2][4], al[2][4];
#pragma unroll
            for (int mi = 0; mi < 2; mi++) {
                int r = ks * 8 + wy * 2 + mi;
                int off = r * 128 + ((lane + rot(r)) & 31) * 4;
                *(uint4*)ah[mi] = *(const uint4*)&AsmF[off];
                if (SPLIT) *(uint4*)al[mi] = *(const uint4*)&AsmF[AW + off];
            }
#pragma unroll
            for (int ni = 0; ni < 8; ni++) {
                int R = ks * 16 + wx * 8 + ni;
                int off = R * 64 + ((lane + rot(R)) & 31) * 2;
                unsigned bh[2];
                *(uint2*)bh = *(const uint2*)&BsmF[off];
#pragma unroll
                for (int mi = 0; mi < 2; mi++) mma_tf32(acc[mi][ni], ah[mi], bh[0], bh[1]);
                if (SPLIT) {
                    unsigned bl[2];
                    *(uint2*)bl = *(const uint2*)&BsmF[BW + off];
#pragma unroll
                    for (int mi = 0; mi < 2; mi++) {
                        mma_tf32(acc[mi][ni], al[mi], bh[0], bh[1]);
                        mma_tf32(acc[mi][ni], ah[mi], bl[0], bl[1]);
                    }
                }
            }
        }
    }

    int g = lane >> 2, th = lane & 3;
    int mbase = wy * 32, nbase = wx * 64;
#pragma unroll
    for (int mi = 0; mi < 2; mi++) {
        int gm0 = m0 + mbase + mi * 16 + g;
#pragma unroll
        for (int ni = 0; ni < 8; ni++) {
            int gn = n0 + nbase + ni * 8 + 2 * th;
            float2 v0 = {acc[mi][ni][0], acc[mi][ni][1]};
            float2 v1 = {acc[mi][ni][2], acc[mi][ni][3]};
            *(float2*)&C[(size_t)gm0 * N + gn] = v0;
            *(float2*)&C[(size_t)(gm0 + 8) * N + gn] = v1;
        }
    }
}

// ---------------------------------------------------------------------------
// Attention (restructured):
//   ds[c,u]  = x6[c, ::2, ::2]          (bg image, 128 x 9216)
//   fg[c,u]  = ds[c,u] * m[u]
//   C = fg^T ds  (9216x9216, K=128 tf32 GEMM)
//   S[a,b] = sum_{d in {-1,0,1}^2} [a+d in grid][b+d in grid] C[a+d, b+d]
//   A = softmax(10*S/||S||_F)  rowwise
//   M[a,b] = sum_d [a+d][b+d] A[a+d, b+d]   (same diag9 form)
//   out[x,c] = sum_u M[x,u] ds[c,u]  (9216x128, split tf32 GEMM)
//   attn = upsample2x(out * m)
// ---------------------------------------------------------------------------
__global__ void ds_kernel(const float* __restrict__ x6, const float* __restrict__ mask,
                          float* __restrict__ fg, float* __restrict__ ds) {
    int idx = blockIdx.x * blockDim.x + threadIdx.x;
    if (idx >= 128 * 9216) return;
    int c = idx / 9216, u = idx % 9216;
    int uy = u / 96, ux = u % 96;
    float v = x6[c * 36864 + (2 * uy) * 192 + 2 * ux];
    ds[idx] = v;
    fg[idx] = v * mask[(2 * uy) * 192 + 2 * ux];
}

// Out[a,b] = sum over 9 diagonal shifts of In with per-coordinate validity.
__global__ void diag9_kernel(const float* __restrict__ In, float* __restrict__ Out) {
    int idx = blockIdx.x * blockDim.x + threadIdx.x;
    if (idx >= 84934656) return;
    int a = idx / 9216, b = idx % 9216;
    int ay = a / 96, ax = a % 96;
    int by = b / 96, bx = b % 96;
    float s = 0.f;
#pragma unroll
    for (int dy = -1; dy <= 1; dy++) {
        if ((unsigned)(ay + dy) >= 96u || (unsigned)(by + dy) >= 96u) continue;
#pragma unroll
        for (int dx = -1; dx <= 1; dx++) {
            if ((unsigned)(ax + dx) >= 96u || (unsigned)(bx + dx) >= 96u) continue;
            s += In[idx + (dy * 96 + dx) * 9217];
        }
    }
    Out[idx] = s;
}

__global__ void zero_sum_kernel() {
    if (threadIdx.x == 0 && blockIdx.x == 0) g_sumsq = 0.0;
}

__global__ void sumsq_kernel(const float* __restrict__ S, int n) {
    float s = 0.f;
    for (int i = blockIdx.x * blockDim.x + threadIdx.x; i < n; i += gridDim.x * blockDim.x) {
        float v = S[i];
        s += v * v;
    }
    for (int o = 16; o; o >>= 1) s += __shfl_down_sync(0xffffffffu, s, o);
    __shared__ float red[32];
    int lane = threadIdx.x & 31, w = threadIdx.x >> 5;
    if (lane == 0) red[w] = s;
    __syncthreads();
    if (w == 0) {
        s = (lane < (int)(blockDim.x >> 5)) ? red[lane] : 0.f;
        for (int o = 16; o; o >>= 1) s += __shfl_down_sync(0xffffffffu, s, o);
        if (lane == 0) atomicAdd(&g_sumsq, (double)s);
    }
}

// One block per row p: A[p,:] = softmax(scale * S[p,:]), scale = 10/nrm. In-place.
__global__ void softmax_kernel(float* __restrict__ S) {
    extern __shared__ float row[];
    __shared__ float red[8];
    __shared__ float bval;
    int p = blockIdx.x;
    float* Sr = S + (size_t)p * 9216;
    float nrm = fmaxf(sqrtf((float)g_sumsq), 1e-12f);
    float scale = 10.f / nrm;
    int t = threadIdx.x;
    int lane = t & 31, w = t >> 5;

    float lm = -INFINITY;
    for (int i = t; i < 9216; i += 256) {
        float v = Sr[i] * scale;
        row[i] = v;
        lm = fmaxf(lm, v);
    }
    for (int o = 16; o; o >>= 1) lm = fmaxf(lm, __shfl_xor_sync(0xffffffffu, lm, o));
    if (lane == 0) red[w] = lm;
    __syncthreads();
    if (t < 32) {
        float v = (t < 8) ? red[t] : -INFINITY;
        for (int o = 4; o; o >>= 1) v = fmaxf(v, __shfl_xor_sync(0xffffffffu, v, o));
        if (t == 0) bval = v;
    }
    __syncthreads();
    float mx = bval;

    float ls = 0.f;
    for (int i = t; i < 9216; i += 256) {
        float e = __expf(row[i] - mx);
        row[i] = e;
        ls += e;
    }
    for (int o = 16; o; o >>= 1) ls += __shfl_xor_sync(0xffffffffu, ls, o);
    __syncthreads();
    if (lane == 0) red[w] = ls;
    __syncthreads();
    if (t < 32) {
        float v = (t < 8) ? red[t] : 0.f;
        for (int o = 4; o; o >>= 1) v += __shfl_xor_sync(0xffffffffu, v, o);
        if (t == 0) bval = v;
    }
    __syncthreads();
    float inv = 1.f / bval;
    for (int i = t; i < 9216; i += 256) Sr[i] = row[i] * inv;
}

// attn[c, 2x] = Rt2[x, c] * m[x], 2x nearest upsample.
__global__ void maskup_kernel(const float* __restrict__ Rt2, const float* __restrict__ mask,
                              float* __restrict__ attn) {
    int idx = blockIdx.x * blockDim.x + threadIdx.x;
    if (idx >= 128 * 9216) return;
    int c = idx / 9216, x = idx % 9216;
    int yy = x / 96, xx = x % 96;
    float s = Rt2[(size_t)x * 128 + c] * mask[(2 * yy) * 192 + 2 * xx];
    size_t base = (size_t)c * 36864 + (size_t)(2 * yy) * 192 + 2 * xx;
    attn[base]       = s;
    attn[base + 1]   = s;
    attn[base + 192] = s;
    attn[base + 193] = s;
}

// ---------------------------------------------------------------------------
// Host orchestration
// ---------------------------------------------------------------------------
template <int ACT, int TM, int TN>
static void run_conv(const float* in, float* out, const float* w, const float* bias,
                     float* col,
                     int C, int H, int W, int OC, int KS, int pad, int stride) {
    int OH = (H + 2 * pad - KS) / stride + 1;
    int OW = (W + 2 * pad - KS) / stride + 1;
    int K = C * KS * KS, N = OH * OW, M = OC;
    int total = K * N;
    im2col_kernel<<<(total + 255) / 256, 256>>>(in, col, C, H, W, KS, pad, stride, OH, OW);
    dim3 grid((N + TN - 1) / TN, (M + TM - 1) / TM);
    conv_gemm_kernel<ACT, TM, TN><<<grid, 256>>>(w, col, bias, out, M, N, K);
}

extern "C" void kernel_launch(void* const* d_in, const int* in_sizes, int n_in,
                              void* d_out, int out_size) {
    const float* x    = (const float*)d_in[0];
    const float* mask = (const float*)d_in[1];
    const float* w[8];
    const float* b[8];
    for (int i = 0; i < 8; i++) {
        w[i] = (const float*)d_in[2 + 2 * i];
        b[i] = (const float*)d_in[3 + 2 * i];
    }

    float *col, *b1, *b2, *b3, *b4, *b5, *b6, *fg, *ds, *S, *CM, *Rt, *attn, *b7;
    cudaGetSymbolAddress((void**)&col,  g_col);
    cudaGetSymbolAddress((void**)&b1,   g_b1);
    cudaGetSymbolAddress((void**)&b2,   g_b2);
    cudaGetSymbolAddress((void**)&b3,   g_b3);
    cudaGetSymbolAddress((void**)&b4,   g_b4);
    cudaGetSymbolAddress((void**)&b5,   g_b5);
    cudaGetSymbolAddress((void**)&b6,   g_b6);
    cudaGetSymbolAddress((void**)&fg,   g_fg);
    cudaGetSymbolAddress((void**)&ds,   g_ds);
    cudaGetSymbolAddress((void**)&S,    g_S);
    cudaGetSymbolAddress((void**)&CM,   g_CM);
    cudaGetSymbolAddress((void**)&Rt,   g_Rt);
    cudaGetSymbolAddress((void**)&attn, g_attn);
    cudaGetSymbolAddress((void**)&b7,   g_b7);

    // Encoder
    run_conv<1,  32, 256>(x,  b1, w[0], b[0], col,   3, 768, 768,  32, 5, 2, 1);
    run_conv<1,  32, 256>(b1, b2, w[1], b[1], col,  32, 768, 768,  32, 3, 1, 2);
    run_conv<1,  64, 128>(b2, b3, w[2], b[2], col,  32, 384, 384,  64, 3, 1, 1);
    run_conv<1, 128, 128>(b3, b4, w[3], b[3], col,  64, 384, 384, 128, 3, 1, 2);
    run_conv<1, 128, 128>(b4, b5, w[4], b[4], col, 128, 192, 192, 128, 3, 1, 1);
    run_conv<2, 128, 128>(b5, b6, w[5], b[5], col, 128, 192, 192, 128, 3, 1, 1);  // relu

    // Contextual attention (restructured via shift algebra)
    ds_kernel<<<(128 * 9216 + 255) / 256, 256>>>(b6, mask, fg, ds);
    {
        // C = fg^T * ds : M=N=9216, K=128, TN layout, plain tf32.
        dim3 g(72, 72);
        mma_gemm_kernel<0, 0><<<g, 256>>>(fg, ds, CM, 9216, 9216, 128);
    }
    diag9_kernel<<<(84934656 + 255) / 256, 256>>>(CM, S);  // S from C
    zero_sum_kernel<<<1, 32>>>();
    sumsq_kernel<<<2048, 256>>>(S, 84934656);
    softmax_kernel<<<9216, 256, 9216 * sizeof(float)>>>(S);  // S -> A in place
    diag9_kernel<<<(84934656 + 255) / 256, 256>>>(S, CM);  // M from A (overwrites C)
    {
        // out[x,c] = sum_u M[x,u] * ds[c,u] : M=9216, N=128, K=9216, NT, split tf32.
        dim3 g(1, 72);
        mma_gemm_kernel<1, 1><<<g, 256>>>(CM, ds, Rt, 9216, 128, 9216);
    }
    maskup_kernel<<<(128 * 9216 + 255) / 256, 256>>>(Rt, mask, attn);

    // Decoder head
    run_conv<1, 128, 128>(attn, b7,          w[6], b[6], col, 128, 192, 192, 128, 3, 1, 1);
    run_conv<1, 128, 128>(b7, (float*)d_out, w[7], b[7], col, 128, 192, 192, 128, 3, 1, 1);
}

// round 8
// speedup vs baseline: 2.6413x; 1.0603x over previous
#include <cuda_runtime.h>
#include <stdint.h>
#include <cstdint>
#include <math.h>

// ---------------------------------------------------------------------------
// Scratch (device globals -- allocation-free per harness rules)
// ---------------------------------------------------------------------------
__device__ float  g_col[44236800];   // im2col scratch (max: conv1 75*589824)
__device__ float  g_b1[18874368];    // conv1 out 32*768*768
__device__ float  g_b2[4718592];    // conv2 out 32*384*384
__device__ float  g_b3[9437184];    // conv3 out 64*384*384
__device__ float  g_b4[4718592];    // conv4 out 128*192*192
__device__ float  g_b5[4718592];    // conv5 out
__device__ float  g_b6[4718592];    // conv6 out (attention input)
__device__ float  g_fg[1179648];    // fg = ds*mask, 128 x 9216 (K x M for C)
__device__ float  g_ds[1179648];    // ds downsampled bg, 128 x 9216
__device__ float  g_S[84934656];    // 9216 x 9216 (S, then softmaxed A in-place)
__device__ float  g_CM[84934656];   // C = fg^T ds, later M = diag9(A)
__device__ float  g_Rt[1179648];    // final gemm out: 9216 x 128 [x][c]
__device__ float  g_attn[4718592];  // attention out 128*192*192
__device__ float  g_b7[4718592];    // conv7 out
__device__ float  g_wt[147456];     // transposed padded weights K x 128
__device__ double g_sumsq;          // Frobenius norm accumulator

// ---------------------------------------------------------------------------
// Helpers
// ---------------------------------------------------------------------------
__device__ __forceinline__ int refl(int i, int n) {
    if (i < 0) i = -i;
    if (i >= n) i = 2 * n - 2 - i;
    return i;
}

__device__ __forceinline__ unsigned f2tf32(float x) {
    unsigned r;
    asm("cvt.rna.tf32.f32 %0, %1;" : "=r"(r) : "f"(x));
    return r;
}

__device__ __forceinline__ void mma_tf32(float* c, const unsigned* a, unsigned b0, unsigned b1) {
    asm volatile(
        "mma.sync.aligned.m16n8k8.row.col.f32.tf32.tf32.f32 "
        "{%0,%1,%2,%3},{%4,%5,%6,%7},{%8,%9},{%0,%1,%2,%3};\n"
        : "+f"(c[0]), "+f"(c[1]), "+f"(c[2]), "+f"(c[3])
        : "r"(a[0]), "r"(a[1]), "r"(a[2]), "r"(a[3]), "r"(b0), "r"(b1));
}

// Per-row group rotation to break store bank conflicts while keeping
// fragment loads (per-warp constant row) conflict-free permutations.
__device__ __forceinline__ int rot(int r) { return r + (r >> 3); }

// Fragment-order word index within one 16k x 128m A tile, swizzled.
__device__ __forceinline__ int a_widx(int kk, int mm) {
    int ks = kk >> 3, k = kk & 7;
    int th = k & 3, rh = (k >> 2) & 1;
    int mb = mm >> 4, rr = mm & 15, g = rr & 7, mh = (rr >> 3) & 1;
    int r = ks * 8 + mb;
    int grp = (g * 4 + th + rot(r)) & 31;
    return r * 128 + grp * 4 + rh * 2 + mh;
}
__device__ __forceinline__ int b_widx(int kk, int nn) {
    int ks = kk >> 3, k = kk & 7;
    int th = k & 3, rh = (k >> 2) & 1;
    int nb = nn >> 3, g = nn & 7;
    int R = ks * 16 + nb;
    int grp = (g * 4 + th + rot(R)) & 31;
    return R * 64 + grp * 2 + rh;
}

// im2col with reflect padding (matches jnp.pad mode='reflect')
__global__ void im2col_kernel(const float* __restrict__ in, float* __restrict__ col,
                              int C, int H, int W, int KS, int pad, int stride,
                              int OH, int OW) {
    int total = C * KS * KS * OH * OW;
    int idx = blockIdx.x * blockDim.x + threadIdx.x;
    if (idx >= total) return;
    int hw  = OH * OW;
    int pix = idx % hw;
    int row = idx / hw;
    int kx = row % KS;
    int ky = (row / KS) % KS;
    int c  = row / (KS * KS);
    int oy = pix / OW, ox = pix % OW;
    int iy = refl(oy * stride + ky - pad, H);
    int ix = refl(ox * stride + kx - pad, W);
    col[idx] = in[(size_t)c * H * W + (size_t)iy * W + ix];
}

// wt[k*128 + m] = w[m*K + k] for m < M, else 0.
__global__ void transpose_w_kernel(const float* __restrict__ w, float* __restrict__ wt,
                                   int M, int K) {
    int idx = blockIdx.x * blockDim.x + threadIdx.x;
    if (idx >= K * 128) return;
    int k = idx >> 7, m = idx & 127;
    wt[idx] = (m < M) ? w[m * K + k] : 0.f;
}

// ---------------------------------------------------------------------------
// FFMA conv GEMM (conv1 only: K=75 not a multiple of 16)
// ---------------------------------------------------------------------------
template <int ACT, int TM, int TN>
__global__ __launch_bounds__(256, 2) void conv_gemm_kernel(
    const float* __restrict__ A, const float* __restrict__ B,
    const float* __restrict__ bias, float* __restrict__ C,
    int M, int N, int K) {
    constexpr int TNTH = TN / 8;
    constexpr int TMTH = 256 / TNTH;
    constexpr int MR   = TM / TMTH;
    __shared__ __align__(16) float As[8][TM + 4];
    __shared__ __align__(16) float Bs[8][TN + 4];
    int t  = threadIdx.x;
    int tx = t % TNTH, ty = t / TNTH;
    int m0 = blockIdx.y * TM, n0 = blockIdx.x * TN;

    float acc[MR][8];
#pragma unroll
    for (int i = 0; i < MR; i++)
#pragma unroll
        for (int j = 0; j < 8; j++) acc[i][j] = 0.f;

    for (int k0 = 0; k0 < K; k0 += 8) {
#pragma unroll
        for (int i = 0; i < TM * 8 / 256; i++) {
            int id = t + i * 256;
            int kk = id & 7, mm = id >> 3;
            int gk = k0 + kk;
            As[kk][mm] = (gk < K && m0 + mm < M) ? A[(size_t)(m0 + mm) * K + gk] : 0.f;
        }
#pragma unroll
        for (int i = 0; i < TN * 8 / 256; i++) {
            int id = t + i * 256;
            int kk = id / TN, nn = id % TN;
            int gk = k0 + kk;
            Bs[kk][nn] = (gk < K && n0 + nn < N) ? B[(size_t)gk * N + n0 + nn] : 0.f;
        }
        __syncthreads();
#pragma unroll
        for (int kk = 0; kk < 8; kk++) {
            float a[MR], b[8];
#pragma unroll
            for (int h = 0; h < MR / 4; h++)
                *(float4*)&a[h * 4] = *(const float4*)&As[kk][ty * MR + h * 4];
            *(float4*)&b[0] = *(const float4*)&Bs[kk][tx * 8];
            *(float4*)&b[4] = *(const float4*)&Bs[kk][tx * 8 + 4];
#pragma unroll
            for (int i = 0; i < MR; i++)
#pragma unroll
                for (int j = 0; j < 8; j++) acc[i][j] += a[i] * b[j];
        }
        __syncthreads();
    }

#pragma unroll
    for (int i = 0; i < MR; i++) {
        int gm = m0 + ty * MR + i;
        if (gm >= M) continue;
        float bv = bias[gm];
#pragma unroll
        for (int j = 0; j < 8; j++) {
            int gn = n0 + tx * 8 + j;
            if (gn >= N) continue;
            float v = acc[i][j] + bv;
            if (ACT == 1) v = v > 0.f ? v : expm1f(v);
            else v = fmaxf(v, 0.f);
            C[(size_t)gm * N + gn] = v;
        }
    }
}

// ---------------------------------------------------------------------------
// TF32 tensor-core GEMM, swizzled fragment-order smem.
//   LAYOUT 0 (TN): A: K x M, B: K x N.  LAYOUT 1 (NT): A: M x K, B: N x K.
//   SPLIT: hi/lo tf32 decomposition for fp32-level accuracy.
//   ACT: 0 none, 1 elu(+bias), 2 relu(+bias). Mreal guards padded M rows.
// Requires M%128==0, N%128==0, K%16==0. Tile 128x128, KT=16, 8 warps.
// ---------------------------------------------------------------------------
template <int LAYOUT, int SPLIT, int ACT>
__global__ __launch_bounds__(256) void mma_gemm_kernel(
    const float* __restrict__ A, const float* __restrict__ B,
    const float* __restrict__ bias, float* __restrict__ C,
    int M, int N, int K, int Mreal) {
    constexpr int AW = 2 * 8 * 128;
    constexpr int BW = 2 * 16 * 64;
    __shared__ __align__(16) unsigned AsmF[AW * (SPLIT ? 2 : 1)];
    __shared__ __align__(16) unsigned BsmF[BW * (SPLIT ? 2 : 1)];
    int t = threadIdx.x;
    int m0 = blockIdx.y * 128, n0 = blockIdx.x * 128;
    int lane = t & 31, warp = t >> 5;
    int wy = warp >> 1, wx = warp & 1;

    float acc[2][8][4];
#pragma unroll
    for (int mi = 0; mi < 2; mi++)
#pragma unroll
        for (int ni = 0; ni < 8; ni++)
#pragma unroll
            for (int r = 0; r < 4; r++) acc[mi][ni][r] = 0.f;

    float4 pa[2], pb[2];

    auto load_tile = [&](int k0) {
#pragma unroll
        for (int i = 0; i < 2; i++) {
            int id = t + i * 256;
            if (LAYOUT == 0) {
                int kk = id >> 5, cg = id & 31;
                pa[i] = *(const float4*)&A[(size_t)(k0 + kk) * M + m0 + cg * 4];
                pb[i] = *(const float4*)&B[(size_t)(k0 + kk) * N + n0 + cg * 4];
            } else {
                int mm = id >> 2, kg = id & 3;
                pa[i] = *(const float4*)&A[(size_t)(m0 + mm) * K + k0 + kg * 4];
                pb[i] = *(const float4*)&B[(size_t)(n0 + mm) * K + k0 + kg * 4];
            }
        }
    };

    auto store_frag = [&]() {
#pragma unroll
        for (int i = 0; i < 2; i++) {
            int id = t + i * 256;
            const float* va = (const float*)&pa[i];
            const float* vb = (const float*)&pb[i];
#pragma unroll
            for (int j = 0; j < 4; j++) {
                int kk, cc;
                if (LAYOUT == 0) { kk = id >> 5; cc = (id & 31) * 4 + j; }
                else             { kk = (id & 3) * 4 + j; cc = id >> 2; }
                int wa = a_widx(kk, cc);
                int wb = b_widx(kk, cc);
                unsigned ha = f2tf32(va[j]);
                unsigned hb = f2tf32(vb[j]);
                AsmF[wa] = ha;
                BsmF[wb] = hb;
                if (SPLIT) {
                    AsmF[AW + wa] = f2tf32(va[j] - __uint_as_float(ha));
                    BsmF[BW + wb] = f2tf32(vb[j] - __uint_as_float(hb));
                }
            }
        }
    };

    load_tile(0);
    int nk = K >> 4;
    for (int kt = 0; kt < nk; kt++) {
        __syncthreads();
        store_frag();
        __syncthreads();
        if (kt + 1 < nk) load_tile((kt + 1) << 4);

#pragma unroll
        for (int ks = 0; ks < 2; ks++) {
            unsigned ah[2][4], al[2][4];
#pragma unroll
            for (int mi = 0; mi < 2; mi++) {
                int r = ks * 8 + wy * 2 + mi;
                int off = r * 128 + ((lane + rot(r)) & 31) * 4;
                *(uint4*)ah[mi] = *(const uint4*)&AsmF[off];
                if (SPLIT) *(uint4*)al[mi] = *(const uint4*)&AsmF[AW + off];
            }
#pragma unroll
            for (int ni = 0; ni < 8; ni++) {
                int R = ks * 16 + wx * 8 + ni;
                int off = R * 64 + ((lane + rot(R)) & 31) * 2;
                unsigned bh[2];
                *(uint2*)bh = *(const uint2*)&BsmF[off];
#pragma unroll
                for (int mi = 0; mi < 2; mi++) mma_tf32(acc[mi][ni], ah[mi], bh[0], bh[1]);
                if (SPLIT) {
                    unsigned bl[2];
                    *(uint2*)bl = *(const uint2*)&BsmF[BW + off];
#pragma unroll
                    for (int mi = 0; mi < 2; mi++) {
                        mma_tf32(acc[mi][ni], al[mi], bh[0], bh[1]);
                        mma_tf32(acc[mi][ni], ah[mi], bl[0], bl[1]);
                    }
                }
            }
        }
    }

    int g = lane >> 2, th = lane & 3;
    int mbase = wy * 32, nbase = wx * 64;
#pragma unroll
    for (int mi = 0; mi < 2; mi++) {
        int gm0 = m0 + mbase + mi * 16 + g;
        float bv0 = 0.f, bv1 = 0.f;
        if (ACT) {
            if (gm0 < Mreal)     bv0 = bias[gm0];
            if (gm0 + 8 < Mreal) bv1 = bias[gm0 + 8];
        }
#pragma unroll
        for (int ni = 0; ni < 8; ni++) {
            int gn = n0 + nbase + ni * 8 + 2 * th;
            float2 v0 = {acc[mi][ni][0], acc[mi][ni][1]};
            float2 v1 = {acc[mi][ni][2], acc[mi][ni][3]};
            if (ACT) {
                v0.x += bv0; v0.y += bv0;
                v1.x += bv1; v1.y += bv1;
                if (ACT == 1) {
                    v0.x = v0.x > 0.f ? v0.x : expm1f(v0.x);
                    v0.y = v0.y > 0.f ? v0.y : expm1f(v0.y);
                    v1.x = v1.x > 0.f ? v1.x : expm1f(v1.x);
                    v1.y = v1.y > 0.f ? v1.y : expm1f(v1.y);
                } else {
                    v0.x = fmaxf(v0.x, 0.f); v0.y = fmaxf(v0.y, 0.f);
                    v1.x = fmaxf(v1.x, 0.f); v1.y = fmaxf(v1.y, 0.f);
                }
                if (gm0 < Mreal)     *(float2*)&C[(size_t)gm0 * N + gn] = v0;
                if (gm0 + 8 < Mreal) *(float2*)&C[(size_t)(gm0 + 8) * N + gn] = v1;
            } else {
                *(float2*)&C[(size_t)gm0 * N + gn] = v0;
                *(float2*)&C[(size_t)(gm0 + 8) * N + gn] = v1;
            }
        }
    }
}

// ---------------------------------------------------------------------------
// Attention helpers (shift-algebra form)
// ---------------------------------------------------------------------------
__global__ void ds_kernel(const float* __restrict__ x6, const float* __restrict__ mask,
                          float* __restrict__ fg, float* __restrict__ ds) {
    int idx = blockIdx.x * blockDim.x + threadIdx.x;
    if (idx >= 128 * 9216) return;
    int c = idx / 9216, u = idx % 9216;
    int uy = u / 96, ux = u % 96;
    float v = x6[c * 36864 + (2 * uy) * 192 + 2 * ux];
    ds[idx] = v;
    fg[idx] = v * mask[(2 * uy) * 192 + 2 * ux];
}

// Out[a,b] = sum over 9 diagonal shifts of In with per-coordinate validity.
__global__ void diag9_kernel(const float* __restrict__ In, float* __restrict__ Out) {
    int idx = blockIdx.x * blockDim.x + threadIdx.x;
    if (idx >= 84934656) return;
    int a = idx / 9216, b = idx % 9216;
    int ay = a / 96, ax = a % 96;
    int by = b / 96, bx = b % 96;
    float s = 0.f;
#pragma unroll
    for (int dy = -1; dy <= 1; dy++) {
        if ((unsigned)(ay + dy) >= 96u || (unsigned)(by + dy) >= 96u) continue;
#pragma unroll
        for (int dx = -1; dx <= 1; dx++) {
            if ((unsigned)(ax + dx) >= 96u || (unsigned)(bx + dx) >= 96u) continue;
            s += In[idx + (dy * 96 + dx) * 9217];
        }
    }
    Out[idx] = s;
}

__global__ void zero_sum_kernel() {
    if (threadIdx.x == 0 && blockIdx.x == 0) g_sumsq = 0.0;
}

__global__ void sumsq_kernel(const float* __restrict__ S, int n) {
    float s = 0.f;
    for (int i = blockIdx.x * blockDim.x + threadIdx.x; i < n; i += gridDim.x * blockDim.x) {
        float v = S[i];
        s += v * v;
    }
    for (int o = 16; o; o >>= 1) s += __shfl_down_sync(0xffffffffu, s, o);
    __shared__ float red[32];
    int lane = threadIdx.x & 31, w = threadIdx.x >> 5;
    if (lane == 0) red[w] = s;
    __syncthreads();
    if (w == 0) {
        s = (lane < (int)(blockDim.x >> 5)) ? red[lane] : 0.f;
        for (int o = 16; o; o >>= 1) s += __shfl_down_sync(0xffffffffu, s, o);
        if (lane == 0) atomicAdd(&g_sumsq, (double)s);
    }
}

// One block per row p: A[p,:] = softmax(scale * S[p,:]), scale = 10/nrm. In-place.
__global__ void softmax_kernel(float* __restrict__ S) {
    extern __shared__ float row[];
    __shared__ float red[8];
    __shared__ float bval;
    int p = blockIdx.x;
    float* Sr = S + (size_t)p * 9216;
    float nrm = fmaxf(sqrtf((float)g_sumsq), 1e-12f);
    float scale = 10.f / nrm;
    int t = threadIdx.x;
    int lane = t & 31, w = t >> 5;

    float lm = -INFINITY;
    for (int i = t; i < 9216; i += 256) {
        float v = Sr[i] * scale;
        row[i] = v;
        lm = fmaxf(lm, v);
    }
    for (int o = 16; o; o >>= 1) lm = fmaxf(lm, __shfl_xor_sync(0xffffffffu, lm, o));
    if (lane == 0) red[w] = lm;
    __syncthreads();
    if (t < 32) {
        float v = (t < 8) ? red[t] : -INFINITY;
        for (int o = 4; o; o >>= 1) v = fmaxf(v, __shfl_xor_sync(0xffffffffu, v, o));
        if (t == 0) bval = v;
    }
    __syncthreads();
    float mx = bval;

    float ls = 0.f;
    for (int i = t; i < 9216; i += 256) {
        float e = __expf(row[i] - mx);
        row[i] = e;
        ls += e;
    }
    for (int o = 16; o; o >>= 1) ls += __shfl_xor_sync(0xffffffffu, ls, o);
    __syncthreads();
    if (lane == 0) red[w] = ls;
    __syncthreads();
    if (t < 32) {
        float v = (t < 8) ? red[t] : 0.f;
        for (int o = 4; o; o >>= 1) v += __shfl_xor_sync(0xffffffffu, v, o);
        if (t == 0) bval = v;
    }
    __syncthreads();
    float inv = 1.f / bval;
    for (int i = t; i < 9216; i += 256) Sr[i] = row[i] * inv;
}

// attn[c, 2x] = Rt2[x, c] * m[x], 2x nearest upsample.
__global__ void maskup_kernel(const float* __restrict__ Rt2, const float* __restrict__ mask,
                              float* __restrict__ attn) {
    int idx = blockIdx.x * blockDim.x + threadIdx.x;
    if (idx >= 128 * 9216) return;
    int c = idx / 9216, x = idx % 9216;
    int yy = x / 96, xx = x % 96;
    float s = Rt2[(size_t)x * 128 + c] * mask[(2 * yy) * 192 + 2 * xx];
    size_t base = (size_t)c * 36864 + (size_t)(2 * yy) * 192 + 2 * xx;
    attn[base]       = s;
    attn[base + 1]   = s;
    attn[base + 192] = s;
    attn[base + 193] = s;
}

// ---------------------------------------------------------------------------
// Host orchestration
// ---------------------------------------------------------------------------
// MMA conv path: K must be a multiple of 16, N a multiple of 128.
template <int ACT>
static void run_conv_mma(const float* in, float* out, const float* w, const float* bias,
                         float* col, float* wt,
                         int C, int H, int W, int OC, int KS, int pad, int stride) {
    int OH = (H + 2 * pad - KS) / stride + 1;
    int OW = (W + 2 * pad - KS) / stride + 1;
    int K = C * KS * KS, N = OH * OW;
    im2col_kernel<<<(K * N + 255) / 256, 256>>>(in, col, C, H, W, KS, pad, stride, OH, OW);
    transpose_w_kernel<<<(K * 128 + 255) / 256, 256>>>(w, wt, OC, K);
    dim3 grid(N / 128, 1);
    mma_gemm_kernel<0, 1, ACT><<<grid, 256>>>(wt, col, bias, out, 128, N, K, OC);
}

extern "C" void kernel_launch(void* const* d_in, const int* in_sizes, int n_in,
                              void* d_out, int out_size) {
    const float* x    = (const float*)d_in[0];
    const float* mask = (const float*)d_in[1];
    const float* w[8];
    const float* b[8];
    for (int i = 0; i < 8; i++) {
        w[i] = (const float*)d_in[2 + 2 * i];
        b[i] = (const float*)d_in[3 + 2 * i];
    }

    float *col, *b1, *b2, *b3, *b4, *b5, *b6, *fg, *ds, *S, *CM, *Rt, *attn, *b7, *wt;
    cudaGetSymbolAddress((void**)&col,  g_col);
    cudaGetSymbolAddress((void**)&b1,   g_b1);
    cudaGetSymbolAddress((void**)&b2,   g_b2);
    cudaGetSymbolAddress((void**)&b3,   g_b3);
    cudaGetSymbolAddress((void**)&b4,   g_b4);
    cudaGetSymbolAddress((void**)&b5,   g_b5);
    cudaGetSymbolAddress((void**)&b6,   g_b6);
    cudaGetSymbolAddress((void**)&fg,   g_fg);
    cudaGetSymbolAddress((void**)&ds,   g_ds);
    cudaGetSymbolAddress((void**)&S,    g_S);
    cudaGetSymbolAddress((void**)&CM,   g_CM);
    cudaGetSymbolAddress((void**)&Rt,   g_Rt);
    cudaGetSymbolAddress((void**)&attn, g_attn);
    cudaGetSymbolAddress((void**)&b7,   g_b7);
    cudaGetSymbolAddress((void**)&wt,   g_wt);

    // Encoder. conv1 (K=75) stays FFMA; the rest use split-tf32 tensor cores.
    {
        int K = 75, N = 589824;
        im2col_kernel<<<(K * N + 255) / 256, 256>>>(x, col, 3, 768, 768, 5, 2, 1, 768, 768);
        dim3 grid((N + 255) / 256, 1);
        conv_gemm_kernel<1, 32, 256><<<grid, 256>>>(w[0], col, b[0], b1, 32, N, K);
    }
    run_conv_mma<1>(b1, b2, w[1], b[1], col, wt,  32, 768, 768,  32, 3, 1, 2);
    run_conv_mma<1>(b2, b3, w[2], b[2], col, wt,  32, 384, 384,  64, 3, 1, 1);
    run_conv_mma<1>(b3, b4, w[3], b[3], col, wt,  64, 384, 384, 128, 3, 1, 2);
    run_conv_mma<1>(b4, b5, w[4], b[4], col, wt, 128, 192, 192, 128, 3, 1, 1);
    run_conv_mma<2>(b5, b6, w[5], b[5], col, wt, 128, 192, 192, 128, 3, 1, 1);  // relu

    // Contextual attention (shift algebra)
    ds_kernel<<<(128 * 9216 + 255) / 256, 256>>>(b6, mask, fg, ds);
    {
        // C = fg^T * ds : M=N=9216, K=128, TN layout, plain tf32.
        dim3 g(72, 72);
        mma_gemm_kernel<0, 0, 0><<<g, 256>>>(fg, ds, nullptr, CM, 9216, 9216, 128, 9216);
    }
    diag9_kernel<<<(84934656 + 255) / 256, 256>>>(CM, S);
    zero_sum_kernel<<<1, 32>>>();
    sumsq_kernel<<<2048, 256>>>(S, 84934656);
    softmax_kernel<<<9216, 256, 9216 * sizeof(float)>>>(S);
    diag9_kernel<<<(84934656 + 255) / 256, 256>>>(S, CM);
    {
        // out[x,c] = sum_u M[x,u] * ds[c,u] : M=9216, N=128, K=9216, NT, split tf32.
        dim3 g(1, 72);
        mma_gemm_kernel<1, 1, 0><<<g, 256>>>(CM, ds, nullptr, Rt, 9216, 128, 9216, 9216);
    }
    maskup_kernel<<<(128 * 9216 + 255) / 256, 256>>>(Rt, mask, attn);

    // Decoder head
    run_conv_mma<1>(attn, b7,          w[6], b[6], col, wt, 128, 192, 192, 128, 3, 1, 1);
    run_conv_mma<1>(b7, (float*)d_out, w[7], b[7], col, wt, 128, 192, 192, 128, 3, 1, 1);
}

// round 10
// speedup vs baseline: 4.3188x; 1.6351x over previous
#include <cuda_runtime.h>
#include <stdint.h>
#include <cstdint>
#include <math.h>

// ---------------------------------------------------------------------------
// Scratch (device globals -- allocation-free per harness rules)
// ---------------------------------------------------------------------------
__device__ float  g_b1[18874368];   // conv1 out 32*768*768
__device__ float  g_b2[4718592];    // conv2 out 32*384*384
__device__ float  g_b3[9437184];    // conv3 out 64*384*384
__device__ float  g_b4[4718592];    // conv4 out 128*192*192
__device__ float  g_b5[4718592];    // conv5 out
__device__ float  g_fg[1179648];    // fg = ds*mask, 128 x 9216
__device__ float  g_ds[1179648];    // ds downsampled bg, 128 x 9216
__device__ float  g_S[84934656];    // 9216 x 9216 (S, then softmaxed A in-place)
__device__ float  g_CM[84934656];   // C = fg^T ds, later M = diag9(A)
__device__ float  g_Rt[4718592];    // 4 split-K partials of 9216 x 128
__device__ float  g_attn[4718592];  // attention out 128*192*192
__device__ float  g_b7[4718592];    // conv7 out
__device__ float  g_wt[147456];     // transposed padded weights K x 128
__device__ double g_sumsq;          // Frobenius norm accumulator

// ---------------------------------------------------------------------------
// Helpers
// ---------------------------------------------------------------------------
__device__ __forceinline__ int refl(int i, int n) {
    if (i < 0) i = -i;
    if (i >= n) i = 2 * n - 2 - i;
    return i;
}

__device__ __forceinline__ unsigned f2tf32(float x) {
    unsigned r;
    asm("cvt.rna.tf32.f32 %0, %1;" : "=r"(r) : "f"(x));
    return r;
}

__device__ __forceinline__ void mma_tf32(float* c, const unsigned* a, unsigned b0, unsigned b1) {
    asm volatile(
        "mma.sync.aligned.m16n8k8.row.col.f32.tf32.tf32.f32 "
        "{%0,%1,%2,%3},{%4,%5,%6,%7},{%8,%9},{%0,%1,%2,%3};\n"
        : "+f"(c[0]), "+f"(c[1]), "+f"(c[2]), "+f"(c[3])
        : "r"(a[0]), "r"(a[1]), "r"(a[2]), "r"(a[3]), "r"(b0), "r"(b1));
}

__device__ __forceinline__ int rot(int r) { return r + (r >> 3); }

__device__ __forceinline__ int a_widx(int kk, int mm) {
    int ks = kk >> 3, k = kk & 7;
    int th = k & 3, rh = (k >> 2) & 1;
    int mb = mm >> 4, rr = mm & 15, g = rr & 7, mh = (rr >> 3) & 1;
    int r = ks * 8 + mb;
    int grp = (g * 4 + th + rot(r)) & 31;
    return r * 128 + grp * 4 + rh * 2 + mh;
}
__device__ __forceinline__ int b_widx(int kk, int nn) {
    int ks = kk >> 3, k = kk & 7;
    int th = k & 3, rh = (k >> 2) & 1;
    int nb = nn >> 3, g = nn & 7;
    int R = ks * 16 + nb;
    int grp = (g * 4 + th + rot(R)) & 31;
    return R * 64 + grp * 2 + rh;
}

// wt[k*128 + m] = w[m*K + k] for m < M, else 0.
__global__ void transpose_w_kernel(const float* __restrict__ w, float* __restrict__ wt,
                                   int M, int K) {
    int idx = blockIdx.x * blockDim.x + threadIdx.x;
    if (idx >= K * 128) return;
    int k = idx >> 7, m = idx & 127;
    wt[idx] = (m < M) ? w[m * K + k] : 0.f;
}

// ---------------------------------------------------------------------------
// FFMA conv GEMM with implicit (fused) im2col gather. Used for conv1 (K=75).
// A: M x K weights; input image In[CC][HH][WW] gathered with reflect pad.
// ---------------------------------------------------------------------------
template <int ACT, int TM, int TN, int CC, int HH, int WW, int KS, int PAD, int STR>
__global__ __launch_bounds__(256, 2) void conv_ffma_kernel(
    const float* __restrict__ A, const float* __restrict__ In,
    const float* __restrict__ bias, float* __restrict__ C,
    int M, int N, int K) {
    constexpr int OW = (WW + 2 * PAD - KS) / STR + 1;
    constexpr int KSQ = KS * KS;
    constexpr int TNTH = TN / 8;
    constexpr int TMTH = 256 / TNTH;
    constexpr int MR   = TM / TMTH;
    __shared__ __align__(16) float As[8][TM + 4];
    __shared__ __align__(16) float Bs[8][TN + 4];
    __shared__ int s_off[TN][KSQ];
    int t  = threadIdx.x;
    int tx = t % TNTH, ty = t / TNTH;
    int m0 = blockIdx.y * TM, n0 = blockIdx.x * TN;

    if (t < TN) {
        int n = n0 + t;
        int oy = n / OW;
        int ox = n - oy * OW;
        int iy[KS], ix[KS];
#pragma unroll
        for (int q = 0; q < KS; q++) {
            iy[q] = refl(oy * STR + q - PAD, HH) * WW;
            ix[q] = refl(ox * STR + q - PAD, WW);
        }
#pragma unroll
        for (int ky = 0; ky < KS; ky++)
#pragma unroll
            for (int kx = 0; kx < KS; kx++)
                s_off[t][ky * KS + kx] = iy[ky] + ix[kx];
    }
    __syncthreads();

    float acc[MR][8];
#pragma unroll
    for (int i = 0; i < MR; i++)
#pragma unroll
        for (int j = 0; j < 8; j++) acc[i][j] = 0.f;

    for (int k0 = 0; k0 < K; k0 += 8) {
#pragma unroll
        for (int i = 0; i < TM * 8 / 256; i++) {
            int id = t + i * 256;
            int kk = id & 7, mm = id >> 3;
            int gk = k0 + kk;
            As[kk][mm] = (gk < K && m0 + mm < M) ? A[(size_t)(m0 + mm) * K + gk] : 0.f;
        }
#pragma unroll
        for (int i = 0; i < TN * 8 / 256; i++) {
            int id = t + i * 256;
            int kk = id / TN, nn = id % TN;
            int gk = k0 + kk;
            float v = 0.f;
            if (gk < K) {
                int c = gk / KSQ;
                int r = gk - c * KSQ;
                v = In[c * (HH * WW) + s_off[nn][r]];
            }
            Bs[kk][nn] = v;
        }
        __syncthreads();
#pragma unroll
        for (int kk = 0; kk < 8; kk++) {
            float a[MR], b[8];
#pragma unroll
            for (int h = 0; h < MR / 4; h++)
                *(float4*)&a[h * 4] = *(const float4*)&As[kk][ty * MR + h * 4];
            *(float4*)&b[0] = *(const float4*)&Bs[kk][tx * 8];
            *(float4*)&b[4] = *(const float4*)&Bs[kk][tx * 8 + 4];
#pragma unroll
            for (int i = 0; i < MR; i++)
#pragma unroll
                for (int j = 0; j < 8; j++) acc[i][j] += a[i] * b[j];
        }
        __syncthreads();
    }

#pragma unroll
    for (int i = 0; i < MR; i++) {
        int gm = m0 + ty * MR + i;
        if (gm >= M) continue;
        float bv = bias[gm];
#pragma unroll
        for (int j = 0; j < 8; j++) {
            int gn = n0 + tx * 8 + j;
            if (gn >= N) continue;
            float v = acc[i][j] + bv;
            if (ACT == 1) v = v > 0.f ? v : expm1f(v);
            else v = fmaxf(v, 0.f);
            C[(size_t)gm * N + gn] = v;
        }
    }
}

// ---------------------------------------------------------------------------
// TF32 tensor-core GEMM, swizzled fragment-order smem.
//   LAYOUT 0 (TN): A: K x M, B: K x N.  LAYOUT 1 (NT): A: M x K, B: N x K.
//   SPLIT: hi/lo tf32 decomposition for fp32-level accuracy.
//   ACT: 0 none, 1 elu(+bias), 2 relu(+bias). Mreal guards padded M rows.
//   MODE: 0 plain B; 1 implicit 3x3 reflect-pad conv gather (B = input image);
//         2 like 1 but strided-downsample conv with dual ds/fg epilogue.
//   Split-K via gridDim.z (partials at C + z*M*N). Tile 128x128, KT=16.
// ---------------------------------------------------------------------------
template <int LAYOUT, int SPLIT, int ACT, int MODE, int CC, int HH, int WW, int STR>
__global__ __launch_bounds__(256) void mma_gemm_kernel(
    const float* __restrict__ A, const float* __restrict__ B,
    const float* __restrict__ bias, float* __restrict__ C,
    int M, int N, int K, int Mreal,
    const float* __restrict__ mask, float* __restrict__ out2) {
    constexpr int OWc = MODE ? ((WW - 1) / STR + 1) : 1;
    constexpr int AW = 2 * 8 * 128;
    constexpr int BW = 2 * 16 * 64;
    __shared__ __align__(16) unsigned AsmF[AW * (SPLIT ? 2 : 1)];
    __shared__ __align__(16) unsigned BsmF[BW * (SPLIT ? 2 : 1)];
    __shared__ int s_off[MODE ? 128 : 1][MODE ? 9 : 1];
    __shared__ int s_m[MODE == 2 ? 128 : 1];
    int t = threadIdx.x;
    int m0 = blockIdx.y * 128, n0 = blockIdx.x * 128;
    int lane = t & 31, warp = t >> 5;
    int wy = warp >> 1, wx = warp & 1;

    int kchunk = K / (int)gridDim.z;
    int kbeg = (int)blockIdx.z * kchunk;
    float* Cz = C + (size_t)blockIdx.z * ((size_t)M * N);

    if (MODE) {
        if (t < 128) {
            int n = n0 + t;
            int oy = n / OWc;
            int ox = n - oy * OWc;
            int by = oy * STR, bx = ox * STR;
            int iy[3], ix[3];
#pragma unroll
            for (int q = 0; q < 3; q++) {
                iy[q] = refl(by + q - 1, HH) * WW;
                ix[q] = refl(bx + q - 1, WW);
            }
#pragma unroll
            for (int ky = 0; ky < 3; ky++)
#pragma unroll
                for (int kx = 0; kx < 3; kx++)
                    s_off[t][ky * 3 + kx] = iy[ky] + ix[kx];
            if (MODE == 2) s_m[t] = by * WW + bx;
        }
        __syncthreads();
    }

    float acc[2][8][4];
#pragma unroll
    for (int mi = 0; mi < 2; mi++)
#pragma unroll
        for (int ni = 0; ni < 8; ni++)
#pragma unroll
            for (int r = 0; r < 4; r++) acc[mi][ni][r] = 0.f;

    float4 pa[2], pb[2];

    auto load_tile = [&](int k0) {
#pragma unroll
        for (int i = 0; i < 2; i++) {
            int id = t + i * 256;
            if (LAYOUT == 0) {
                int kk = id >> 5, cg = id & 31;
                pa[i] = *(const float4*)&A[(size_t)(k0 + kk) * M + m0 + cg * 4];
                if (MODE) {
                    int k = k0 + kk;
                    int c = k / 9;
                    int r9 = k - c * 9;
                    const float* Bp = B + (size_t)c * (HH * WW);
                    float v[4];
#pragma unroll
                    for (int j = 0; j < 4; j++) {
                        int nn = cg + 32 * j;  // lane-coalesced gather mapping
                        v[j] = Bp[s_off[nn][r9]];
                    }
                    pb[i] = {v[0], v[1], v[2], v[3]};
                } else {
                    pb[i] = *(const float4*)&B[(size_t)(k0 + kk) * N + n0 + cg * 4];
                }
            } else {
                int mm = id >> 2, kg = id & 3;
                pa[i] = *(const float4*)&A[(size_t)(m0 + mm) * K + k0 + kg * 4];
                pb[i] = *(const float4*)&B[(size_t)(n0 + mm) * K + k0 + kg * 4];
            }
        }
    };

    auto store_frag = [&]() {
#pragma unroll
        for (int i = 0; i < 2; i++) {
            int id = t + i * 256;
            const float* va = (const float*)&pa[i];
            const float* vb = (const float*)&pb[i];
#pragma unroll
            for (int j = 0; j < 4; j++) {
                int kk, cca, ccb;
                if (LAYOUT == 0) {
                    kk = id >> 5;
                    cca = (id & 31) * 4 + j;
                    ccb = MODE ? ((id & 31) + 32 * j) : cca;
                } else {
                    kk = (id & 3) * 4 + j;
                    cca = id >> 2;
                    ccb = cca;
                }
                int wa = a_widx(kk, cca);
                int wb = b_widx(kk, ccb);
                unsigned ha = f2tf32(va[j]);
                unsigned hb = f2tf32(vb[j]);
                AsmF[wa] = ha;
                BsmF[wb] = hb;
                if (SPLIT) {
                    AsmF[AW + wa] = f2tf32(va[j] - __uint_as_float(ha));
                    BsmF[BW + wb] = f2tf32(vb[j] - __uint_as_float(hb));
                }
            }
        }
    };

    load_tile(kbeg);
    int nk = kchunk >> 4;
    for (int kt = 0; kt < nk; kt++) {
        __syncthreads();
        store_frag();
        __syncthreads();
        if (kt + 1 < nk) load_tile(kbeg + ((kt + 1) << 4));

#pragma unroll
        for (int ks = 0; ks < 2; ks++) {
            unsigned ah[2][4], al[2][4];
#pragma unroll
            for (int mi = 0; mi < 2; mi++) {
                int r = ks * 8 + wy * 2 + mi;
                int off = r * 128 + ((lane + rot(r)) & 31) * 4;
                *(uint4*)ah[mi] = *(const uint4*)&AsmF[off];
                if (SPLIT) *(uint4*)al[mi] = *(const uint4*)&AsmF[AW + off];
            }
#pragma unroll
            for (int ni = 0; ni < 8; ni++) {
                int R = ks * 16 + wx * 8 + ni;
                int off = R * 64 + ((lane + rot(R)) & 31) * 2;
                unsigned bh[2];
                *(uint2*)bh = *(const uint2*)&BsmF[off];
#pragma unroll
                for (int mi = 0; mi < 2; mi++) mma_tf32(acc[mi][ni], ah[mi], bh[0], bh[1]);
                if (SPLIT) {
                    unsigned bl[2];
                    *(uint2*)bl = *(const uint2*)&BsmF[BW + off];
#pragma unroll
                    for (int mi = 0; mi < 2; mi++) {
                        mma_tf32(acc[mi][ni], al[mi], bh[0], bh[1]);
                        mma_tf32(acc[mi][ni], ah[mi], bl[0], bl[1]);
                    }
                }
            }
        }
    }

    int g = lane >> 2, th = lane & 3;
    int mbase = wy * 32, nbase = wx * 64;
#pragma unroll
    for (int mi = 0; mi < 2; mi++) {
        int gm0 = m0 + mbase + mi * 16 + g;
        float bv0 = 0.f, bv1 = 0.f;
        if (ACT) {
            if (gm0 < Mreal)     bv0 = bias[gm0];
            if (gm0 + 8 < Mreal) bv1 = bias[gm0 + 8];
        }
#pragma unroll
        for (int ni = 0; ni < 8; ni++) {
            int gn = n0 + nbase + ni * 8 + 2 * th;
            float2 v0 = {acc[mi][ni][0], acc[mi][ni][1]};
            float2 v1 = {acc[mi][ni][2], acc[mi][ni][3]};
            if (MODE == 2) {
                v0.x = fmaxf(v0.x + bv0, 0.f); v0.y = fmaxf(v0.y + bv0, 0.f);
                v1.x = fmaxf(v1.x + bv1, 0.f); v1.y = fmaxf(v1.y + bv1, 0.f);
                int l = gn - n0;
                float ma = mask[s_m[l]], mb = mask[s_m[l + 1]];
                *(float2*)&Cz[(size_t)gm0 * N + gn] = v0;
                *(float2*)&Cz[(size_t)(gm0 + 8) * N + gn] = v1;
                float2 f0 = {v0.x * ma, v0.y * mb};
                float2 f1 = {v1.x * ma, v1.y * mb};
                *(float2*)&out2[(size_t)gm0 * N + gn] = f0;
                *(float2*)&out2[(size_t)(gm0 + 8) * N + gn] = f1;
            } else if (ACT) {
                v0.x += bv0; v0.y += bv0;
                v1.x += bv1; v1.y += bv1;
                if (ACT == 1) {
                    v0.x = v0.x > 0.f ? v0.x : expm1f(v0.x);
                    v0.y = v0.y > 0.f ? v0.y : expm1f(v0.y);
                    v1.x = v1.x > 0.f ? v1.x : expm1f(v1.x);
                    v1.y = v1.y > 0.f ? v1.y : expm1f(v1.y);
                } else {
                    v0.x = fmaxf(v0.x, 0.f); v0.y = fmaxf(v0.y, 0.f);
                    v1.x = fmaxf(v1.x, 0.f); v1.y = fmaxf(v1.y, 0.f);
                }
                if (gm0 < Mreal)     *(float2*)&Cz[(size_t)gm0 * N + gn] = v0;
                if (gm0 + 8 < Mreal) *(float2*)&Cz[(size_t)(gm0 + 8) * N + gn] = v1;
            } else {
                *(float2*)&Cz[(size_t)gm0 * N + gn] = v0;
                *(float2*)&Cz[(size_t)(gm0 + 8) * N + gn] = v1;
            }
        }
    }
}

// ---------------------------------------------------------------------------
// Attention helpers (shift-algebra form)
// ---------------------------------------------------------------------------
// Out[a,b] = sum over 9 diagonal shifts of In with per-coordinate validity.
__global__ void diag9_kernel(const float* __restrict__ In, float* __restrict__ Out) {
    int idx = blockIdx.x * blockDim.x + threadIdx.x;
    if (idx >= 84934656) return;
    int a = idx / 9216, b = idx % 9216;
    int ay = a / 96, ax = a % 96;
    int by = b / 96, bx = b % 96;
    float s = 0.f;
#pragma unroll
    for (int dy = -1; dy <= 1; dy++) {
        if ((unsigned)(ay + dy) >= 96u || (unsigned)(by + dy) >= 96u) continue;
#pragma unroll
        for (int dx = -1; dx <= 1; dx++) {
            if ((unsigned)(ax + dx) >= 96u || (unsigned)(bx + dx) >= 96u) continue;
            s += In[idx + (dy * 96 + dx) * 9217];
        }
    }
    Out[idx] = s;
}

__global__ void zero_sum_kernel() {
    if (threadIdx.x == 0 && blockIdx.x == 0) g_sumsq = 0.0;
}

__global__ void sumsq_kernel(const float* __restrict__ S, int n) {
    float s = 0.f;
    for (int i = blockIdx.x * blockDim.x + threadIdx.x; i < n; i += gridDim.x * blockDim.x) {
        float v = S[i];
        s += v * v;
    }
    for (int o = 16; o; o >>= 1) s += __shfl_down_sync(0xffffffffu, s, o);
    __shared__ float red[32];
    int lane = threadIdx.x & 31, w = threadIdx.x >> 5;
    if (lane == 0) red[w] = s;
    __syncthreads();
    if (w == 0) {
        s = (lane < (int)(blockDim.x >> 5)) ? red[lane] : 0.f;
        for (int o = 16; o; o >>= 1) s += __shfl_down_sync(0xffffffffu, s, o);
        if (lane == 0) atomicAdd(&g_sumsq, (double)s);
    }
}

// One block per row p: A[p,:] = softmax(scale * S[p,:]), scale = 10/nrm. In-place.
__global__ void softmax_kernel(float* __restrict__ S) {
    extern __shared__ float row[];
    __shared__ float red[8];
    __shared__ float bval;
    int p = blockIdx.x;
    float* Sr = S + (size_t)p * 9216;
    float nrm = fmaxf(sqrtf((float)g_sumsq), 1e-12f);
    float scale = 10.f / nrm;
    int t = threadIdx.x;
    int lane = t & 31, w = t >> 5;

    float lm = -INFINITY;
    for (int i = t; i < 9216; i += 256) {
        float v = Sr[i] * scale;
        row[i] = v;
        lm = fmaxf(lm, v);
    }
    for (int o = 16; o; o >>= 1) lm = fmaxf(lm, __shfl_xor_sync(0xffffffffu, lm, o));
    if (lane == 0) red[w] = lm;
    __syncthreads();
    if (t < 32) {
        float v = (t < 8) ? red[t] : -INFINITY;
        for (int o = 4; o; o >>= 1) v = fmaxf(v, __shfl_xor_sync(0xffffffffu, v, o));
        if (t == 0) bval = v;
    }
    __syncthreads();
    float mx = bval;

    float ls = 0.f;
    for (int i = t; i < 9216; i += 256) {
        float e = __expf(row[i] - mx);
        row[i] = e;
        ls += e;
    }
    for (int o = 16; o; o >>= 1) ls += __shfl_xor_sync(0xffffffffu, ls, o);
    __syncthreads();
    if (lane == 0) red[w] = ls;
    __syncthreads();
    if (t < 32) {
        float v = (t < 8) ? red[t] : 0.f;
        for (int o = 4; o; o >>= 1) v += __shfl_xor_sync(0xffffffffu, v, o);
        if (t == 0) bval = v;
    }
    __syncthreads();
    float inv = 1.f / bval;
    for (int i = t; i < 9216; i += 256) Sr[i] = row[i] * inv;
}

// attn[c, 2x] = (sum of 4 split-K partials of Rt)[x, c] * m[x], 2x upsample.
__global__ void maskup_kernel(const float* __restrict__ Rt, const float* __restrict__ mask,
                              float* __restrict__ attn) {
    int idx = blockIdx.x * blockDim.x + threadIdx.x;
    if (idx >= 128 * 9216) return;
    int c = idx / 9216, x = idx % 9216;
    int yy = x / 96, xx = x % 96;
    float s = 0.f;
#pragma unroll
    for (int p = 0; p < 4; p++)
        s += Rt[(size_t)p * 1179648 + (size_t)x * 128 + c];
    s *= mask[(2 * yy) * 192 + 2 * xx];
    size_t base = (size_t)c * 36864 + (size_t)(2 * yy) * 192 + 2 * xx;
    attn[base]       = s;
    attn[base + 1]   = s;
    attn[base + 192] = s;
    attn[base + 193] = s;
}

// ---------------------------------------------------------------------------
// Host orchestration
// ---------------------------------------------------------------------------
extern "C" void kernel_launch(void* const* d_in, const int* in_sizes, int n_in,
                              void* d_out, int out_size) {
    const float* x    = (const float*)d_in[0];
    const float* mask = (const float*)d_in[1];
    const float* w[8];
    const float* b[8];
    for (int i = 0; i < 8; i++) {
        w[i] = (const float*)d_in[2 + 2 * i];
        b[i] = (const float*)d_in[3 + 2 * i];
    }

    float *b1, *b2, *b3, *b4, *b5, *fg, *ds, *S, *CM, *Rt, *attn, *b7, *wt;
    cudaGetSymbolAddress((void**)&b1,   g_b1);
    cudaGetSymbolAddress((void**)&b2,   g_b2);
    cudaGetSymbolAddress((void**)&b3,   g_b3);
    cudaGetSymbolAddress((void**)&b4,   g_b4);
    cudaGetSymbolAddress((void**)&b5,   g_b5);
    cudaGetSymbolAddress((void**)&fg,   g_fg);
    cudaGetSymbolAddress((void**)&ds,   g_ds);
    cudaGetSymbolAddress((void**)&S,    g_S);
    cudaGetSymbolAddress((void**)&CM,   g_CM);
    cudaGetSymbolAddress((void**)&Rt,   g_Rt);
    cudaGetSymbolAddress((void**)&attn, g_attn);
    cudaGetSymbolAddress((void**)&b7,   g_b7);
    cudaGetSymbolAddress((void**)&wt,   g_wt);

    // conv1: K=75, FFMA with implicit gather (C=3,768x768, 5x5, pad2, str1)
    conv_ffma_kernel<1, 32, 256, 3, 768, 768, 5, 2, 1>
        <<<dim3(589824 / 256, 1), 256>>>(w[0], x, b[0], b1, 32, 589824, 75);

    // conv2: C=32, 768x768, str2 -> 384x384, K=288, OC=32
    transpose_w_kernel<<<(288 * 128 + 255) / 256, 256>>>(w[1], wt, 32, 288);
    mma_gemm_kernel<0, 1, 1, 1, 32, 768, 768, 2><<<dim3(1152, 1, 1), 256>>>(
        wt, b1, b[1], b2, 128, 147456, 288, 32, nullptr, nullptr);

    // conv3: C=32, 384x384, str1, K=288, OC=64
    transpose_w_kernel<<<(288 * 128 + 255) / 256, 256>>>(w[2], wt, 64, 288);
    mma_gemm_kernel<0, 1, 1, 1, 32, 384, 384, 1><<<dim3(1152, 1, 1), 256>>>(
        wt, b2, b[2], b3, 128, 147456, 288, 64, nullptr, nullptr);

    // conv4: C=64, 384x384, str2 -> 192x192, K=576, OC=128
    transpose_w_kernel<<<(576 * 128 + 255) / 256, 256>>>(w[3], wt, 128, 576);
    mma_gemm_kernel<0, 1, 1, 1, 64, 384, 384, 2><<<dim3(288, 1, 1), 256>>>(
        wt, b3, b[3], b4, 128, 36864, 576, 128, nullptr, nullptr);

    // conv5: C=128, 192x192, str1, K=1152
    transpose_w_kernel<<<(1152 * 128 + 255) / 256, 256>>>(w[4], wt, 128, 1152);
    mma_gemm_kernel<0, 1, 1, 1, 128, 192, 192, 1><<<dim3(288, 1, 1), 256>>>(
        wt, b4, b[4], b5, 128, 36864, 1152, 128, nullptr, nullptr);

    // conv6: only downsampled pixels needed -> strided conv (192x192, str2 -> 96x96),
    // relu epilogue writes ds and fg = ds*mask directly. N=9216.
    transpose_w_kernel<<<(1152 * 128 + 255) / 256, 256>>>(w[5], wt, 128, 1152);
    mma_gemm_kernel<0, 1, 2, 2, 128, 192, 192, 2><<<dim3(72, 1, 1), 256>>>(
        wt, b5, b[5], ds, 128, 9216, 1152, 128, mask, fg);

    // Contextual attention (shift algebra)
    {
        // C = fg^T * ds : M=N=9216, K=128, TN layout, plain tf32.
        mma_gemm_kernel<0, 0, 0, 0, 1, 1, 1, 1><<<dim3(72, 72, 1), 256>>>(
            fg, ds, nullptr, CM, 9216, 9216, 128, 9216, nullptr, nullptr);
    }
    diag9_kernel<<<(84934656 + 255) / 256, 256>>>(CM, S);
    zero_sum_kernel<<<1, 32>>>();
    sumsq_kernel<<<2048, 256>>>(S, 84934656);
    softmax_kernel<<<9216, 256, 9216 * sizeof(float)>>>(S);
    diag9_kernel<<<(84934656 + 255) / 256, 256>>>(S, CM);
    {
        // out[x,c] = sum_u M[x,u] * ds[c,u] : M=9216, N=128, K=9216, NT,
        // split tf32, split-K x4 into partials (summed in maskup).
        mma_gemm_kernel<1, 1, 0, 0, 1, 1, 1, 1><<<dim3(1, 72, 4), 256>>>(
            CM, ds, nullptr, Rt, 9216, 128, 9216, 9216, nullptr, nullptr);
    }
    maskup_kernel<<<(128 * 9216 + 255) / 256, 256>>>(Rt, mask, attn);

    // conv7: C=128, 192x192, str1, K=1152
    transpose_w_kernel<<<(1152 * 128 + 255) / 256, 256>>>(w[6], wt, 128, 1152);
    mma_gemm_kernel<0, 1, 1, 1, 128, 192, 192, 1><<<dim3(288, 1, 1), 256>>>(
        wt, attn, b[6], b7, 128, 36864, 1152, 128, nullptr, nullptr);

    // conv8
    transpose_w_kernel<<<(1152 * 128 + 255) / 256, 256>>>(w[7], wt, 128, 1152);
    mma_gemm_kernel<0, 1, 1, 1, 128, 192, 192, 1><<<dim3(288, 1, 1), 256>>>(
        wt, b7, b[7], (float*)d_out, 128, 36864, 1152, 128, nullptr, nullptr);
}

// round 11
// speedup vs baseline: 4.4289x; 1.0255x over previous
#include <cuda_runtime.h>
#include <stdint.h>
#include <cstdint>
#include <math.h>

// ---------------------------------------------------------------------------
// Scratch (device globals -- allocation-free per harness rules)
// ---------------------------------------------------------------------------
__device__ float  g_b1[18874368];   // conv1 out 32*768*768
__device__ float  g_b2[4718592];    // conv2 out 32*384*384
__device__ float  g_b3[9437184];    // conv3 out 64*384*384
__device__ float  g_b4[4718592];    // conv4 out 128*192*192
__device__ float  g_b5[4718592];    // conv5 out
__device__ float  g_fg[1179648];    // fg = ds*mask, 128 x 9216
__device__ float  g_ds[1179648];    // ds downsampled bg, 128 x 9216
__device__ float  g_S[84934656];    // 9216 x 9216 (S, then softmaxed A in-place)
__device__ float  g_CM[84934656];   // C = fg^T ds, later M = diag9(A)
__device__ float  g_Rt[4718592];    // 4 split-K partials of 9216 x 128
__device__ float  g_attn[4718592];  // attention out 128*192*192
__device__ float  g_b7[4718592];    // conv7 out
__device__ float  g_wt[737280];     // all transposed padded weights (segmented)
__device__ double g_sumsq;          // Frobenius norm accumulator

// ---------------------------------------------------------------------------
// Helpers
// ---------------------------------------------------------------------------
__device__ __forceinline__ int refl(int i, int n) {
    if (i < 0) i = -i;
    if (i >= n) i = 2 * n - 2 - i;
    return i;
}

__device__ __forceinline__ unsigned f2tf32(float x) {
    unsigned r;
    asm("cvt.rna.tf32.f32 %0, %1;" : "=r"(r) : "f"(x));
    return r;
}

__device__ __forceinline__ void mma_tf32(float* c, const unsigned* a, unsigned b0, unsigned b1) {
    asm volatile(
        "mma.sync.aligned.m16n8k8.row.col.f32.tf32.tf32.f32 "
        "{%0,%1,%2,%3},{%4,%5,%6,%7},{%8,%9},{%0,%1,%2,%3};\n"
        : "+f"(c[0]), "+f"(c[1]), "+f"(c[2]), "+f"(c[3])
        : "r"(a[0]), "r"(a[1]), "r"(a[2]), "r"(a[3]), "r"(b0), "r"(b1));
}

__device__ __forceinline__ int rot(int r) { return r + (r >> 3); }

__device__ __forceinline__ int a_widx(int kk, int mm) {
    int ks = kk >> 3, k = kk & 7;
    int th = k & 3, rh = (k >> 2) & 1;
    int mb = mm >> 4, rr = mm & 15, g = rr & 7, mh = (rr >> 3) & 1;
    int r = ks * 8 + mb;
    int grp = (g * 4 + th + rot(r)) & 31;
    return r * 128 + grp * 4 + rh * 2 + mh;
}
__device__ __forceinline__ int b_widx(int kk, int nn) {
    int ks = kk >> 3, k = kk & 7;
    int th = k & 3, rh = (k >> 2) & 1;
    int nb = nn >> 3, g = nn & 7;
    int R = ks * 16 + nb;
    int grp = (g * 4 + th + rot(R)) & 31;
    return R * 64 + grp * 2 + rh;
}

// One launch: transpose+pad all 7 conv weights into segmented g_wt (K x 128).
__global__ void transpose_all_kernel(
    const float* __restrict__ w2, const float* __restrict__ w3,
    const float* __restrict__ w4, const float* __restrict__ w5,
    const float* __restrict__ w6, const float* __restrict__ w7,
    const float* __restrict__ w8, float* __restrict__ wt) {
    int idx = blockIdx.x * blockDim.x + threadIdx.x;
    if (idx >= 737280) return;
    const float* w; int K, M, off;
    if (idx < 36864)       { w = w2; K = 288;  M = 32;  off = 0; }
    else if (idx < 73728)  { w = w3; K = 288;  M = 64;  off = 36864; }
    else if (idx < 147456) { w = w4; K = 576;  M = 128; off = 73728; }
    else if (idx < 294912) { w = w5; K = 1152; M = 128; off = 147456; }
    else if (idx < 442368) { w = w6; K = 1152; M = 128; off = 294912; }
    else if (idx < 589824) { w = w7; K = 1152; M = 128; off = 442368; }
    else                   { w = w8; K = 1152; M = 128; off = 589824; }
    int l = idx - off;
    int k = l >> 7, m = l & 127;
    wt[idx] = (m < M) ? w[m * K + k] : 0.f;
}

// ---------------------------------------------------------------------------
// FFMA conv GEMM with implicit im2col gather (conv1: K=75 not %16)
// ---------------------------------------------------------------------------
template <int ACT, int TM, int TN, int CC, int HH, int WW, int KS, int PAD, int STR>
__global__ __launch_bounds__(256, 2) void conv_ffma_kernel(
    const float* __restrict__ A, const float* __restrict__ In,
    const float* __restrict__ bias, float* __restrict__ C,
    int M, int N, int K) {
    constexpr int OW = (WW + 2 * PAD - KS) / STR + 1;
    constexpr int KSQ = KS * KS;
    constexpr int TNTH = TN / 8;
    constexpr int TMTH = 256 / TNTH;
    constexpr int MR   = TM / TMTH;
    __shared__ __align__(16) float As[8][TM + 4];
    __shared__ __align__(16) float Bs[8][TN + 4];
    __shared__ int s_off[TN][KSQ];
    int t  = threadIdx.x;
    int tx = t % TNTH, ty = t / TNTH;
    int m0 = blockIdx.y * TM, n0 = blockIdx.x * TN;

    if (t < TN) {
        int n = n0 + t;
        int oy = n / OW;
        int ox = n - oy * OW;
        int iy[KS], ix[KS];
#pragma unroll
        for (int q = 0; q < KS; q++) {
            iy[q] = refl(oy * STR + q - PAD, HH) * WW;
            ix[q] = refl(ox * STR + q - PAD, WW);
        }
#pragma unroll
        for (int ky = 0; ky < KS; ky++)
#pragma unroll
            for (int kx = 0; kx < KS; kx++)
                s_off[t][ky * KS + kx] = iy[ky] + ix[kx];
    }
    __syncthreads();

    float acc[MR][8];
#pragma unroll
    for (int i = 0; i < MR; i++)
#pragma unroll
        for (int j = 0; j < 8; j++) acc[i][j] = 0.f;

    for (int k0 = 0; k0 < K; k0 += 8) {
#pragma unroll
        for (int i = 0; i < TM * 8 / 256; i++) {
            int id = t + i * 256;
            int kk = id & 7, mm = id >> 3;
            int gk = k0 + kk;
            As[kk][mm] = (gk < K && m0 + mm < M) ? A[(size_t)(m0 + mm) * K + gk] : 0.f;
        }
#pragma unroll
        for (int i = 0; i < TN * 8 / 256; i++) {
            int id = t + i * 256;
            int kk = id / TN, nn = id % TN;
            int gk = k0 + kk;
            float v = 0.f;
            if (gk < K) {
                int c = gk / KSQ;
                int r = gk - c * KSQ;
                v = In[c * (HH * WW) + s_off[nn][r]];
            }
            Bs[kk][nn] = v;
        }
        __syncthreads();
#pragma unroll
        for (int kk = 0; kk < 8; kk++) {
            float a[MR], b[8];
#pragma unroll
            for (int h = 0; h < MR / 4; h++)
                *(float4*)&a[h * 4] = *(const float4*)&As[kk][ty * MR + h * 4];
            *(float4*)&b[0] = *(const float4*)&Bs[kk][tx * 8];
            *(float4*)&b[4] = *(const float4*)&Bs[kk][tx * 8 + 4];
#pragma unroll
            for (int i = 0; i < MR; i++)
#pragma unroll
                for (int j = 0; j < 8; j++) acc[i][j] += a[i] * b[j];
        }
        __syncthreads();
    }

#pragma unroll
    for (int i = 0; i < MR; i++) {
        int gm = m0 + ty * MR + i;
        if (gm >= M) continue;
        float bv = bias[gm];
#pragma unroll
        for (int j = 0; j < 8; j++) {
            int gn = n0 + tx * 8 + j;
            if (gn >= N) continue;
            float v = acc[i][j] + bv;
            if (ACT == 1) v = v > 0.f ? v : expm1f(v);
            else v = fmaxf(v, 0.f);
            C[(size_t)gm * N + gn] = v;
        }
    }
}

// ---------------------------------------------------------------------------
// TF32 tensor-core GEMM, swizzled fragment-order smem, DOUBLE-BUFFERED.
//   LAYOUT 0 (TN): A: K x M, B: K x N.  LAYOUT 1 (NT): A: M x K, B: N x K.
//   SPLIT: hi/lo tf32 decomposition for fp32-level accuracy.
//   ACT: 0 none, 1 elu(+bias), 2 relu(+bias). Mreal guards padded M rows.
//   MODE: 0 plain B; 1 implicit 3x3 reflect-pad conv gather;
//         2 strided-downsample conv with dual ds/fg epilogue.
//   Split-K via gridDim.z (partials at C + z*M*N). Tile 128x128, KT=16.
// Dynamic smem: 2 stages x (A + B), (SPLIT?64:32) KB.
// ---------------------------------------------------------------------------
template <int LAYOUT, int SPLIT, int ACT, int MODE, int CC, int HH, int WW, int STR>
__global__ __launch_bounds__(256) void mma_gemm_kernel(
    const float* __restrict__ A, const float* __restrict__ B,
    const float* __restrict__ bias, float* __restrict__ C,
    int M, int N, int K, int Mreal,
    const float* __restrict__ mask, float* __restrict__ out2) {
    constexpr int OWc = MODE ? ((WW - 1) / STR + 1) : 1;
    constexpr int AW = 2 * 8 * 128;   // 2048 words per plane
    constexpr int BW = 2 * 16 * 64;   // 2048
    constexpr int PL = SPLIT ? 2 : 1;
    constexpr int ASTG = AW * PL;
    constexpr int BSTG = BW * PL;
    extern __shared__ unsigned dyns[];
    unsigned* Abuf = dyns;             // 2 stages of ASTG
    unsigned* Bbuf = dyns + 2 * ASTG;  // 2 stages of BSTG
    __shared__ int s_off[MODE ? 128 : 1][MODE ? 9 : 1];
    __shared__ int s_m[MODE == 2 ? 128 : 1];
    int t = threadIdx.x;
    int m0 = blockIdx.y * 128, n0 = blockIdx.x * 128;
    int lane = t & 31, warp = t >> 5;
    int wy = warp >> 1, wx = warp & 1;

    int kchunk = K / (int)gridDim.z;
    int kbeg = (int)blockIdx.z * kchunk;
    float* Cz = C + (size_t)blockIdx.z * ((size_t)M * N);

    if (MODE) {
        if (t < 128) {
            int n = n0 + t;
            int oy = n / OWc;
            int ox = n - oy * OWc;
            int by = oy * STR, bx = ox * STR;
            int iy[3], ix[3];
#pragma unroll
            for (int q = 0; q < 3; q++) {
                iy[q] = refl(by + q - 1, HH) * WW;
                ix[q] = refl(bx + q - 1, WW);
            }
#pragma unroll
            for (int ky = 0; ky < 3; ky++)
#pragma unroll
                for (int kx = 0; kx < 3; kx++)
                    s_off[t][ky * 3 + kx] = iy[ky] + ix[kx];
            if (MODE == 2) s_m[t] = by * WW + bx;
        }
        __syncthreads();
    }

    float acc[2][8][4];
#pragma unroll
    for (int mi = 0; mi < 2; mi++)
#pragma unroll
        for (int ni = 0; ni < 8; ni++)
#pragma unroll
            for (int r = 0; r < 4; r++) acc[mi][ni][r] = 0.f;

    float4 pa[2], pb[2];

    auto load_tile = [&](int k0) {
#pragma unroll
        for (int i = 0; i < 2; i++) {
            int id = t + i * 256;
            if (LAYOUT == 0) {
                int kk = id >> 5, cg = id & 31;
                pa[i] = *(const float4*)&A[(size_t)(k0 + kk) * M + m0 + cg * 4];
                if (MODE) {
                    int k = k0 + kk;
                    int c = k / 9;
                    int r9 = k - c * 9;
                    const float* Bp = B + (size_t)c * (HH * WW);
                    float v[4];
#pragma unroll
                    for (int j = 0; j < 4; j++) {
                        int nn = cg + 32 * j;  // lane-coalesced gather mapping
                        v[j] = Bp[s_off[nn][r9]];
                    }
                    pb[i] = {v[0], v[1], v[2], v[3]};
                } else {
                    pb[i] = *(const float4*)&B[(size_t)(k0 + kk) * N + n0 + cg * 4];
                }
            } else {
                int mm = id >> 2, kg = id & 3;
                pa[i] = *(const float4*)&A[(size_t)(m0 + mm) * K + k0 + kg * 4];
                pb[i] = *(const float4*)&B[(size_t)(n0 + mm) * K + k0 + kg * 4];
            }
        }
    };

    auto store_frag = [&](int stg) {
        unsigned* As = Abuf + stg * ASTG;
        unsigned* Bs = Bbuf + stg * BSTG;
#pragma unroll
        for (int i = 0; i < 2; i++) {
            int id = t + i * 256;
            const float* va = (const float*)&pa[i];
            const float* vb = (const float*)&pb[i];
#pragma unroll
            for (int j = 0; j < 4; j++) {
                int kk, cca, ccb;
                if (LAYOUT == 0) {
                    kk = id >> 5;
                    cca = (id & 31) * 4 + j;
                    ccb = MODE ? ((id & 31) + 32 * j) : cca;
                } else {
                    kk = (id & 3) * 4 + j;
                    cca = id >> 2;
                    ccb = cca;
                }
                int wa = a_widx(kk, cca);
                int wb = b_widx(kk, ccb);
                unsigned ha = f2tf32(va[j]);
                unsigned hb = f2tf32(vb[j]);
                As[wa] = ha;
                Bs[wb] = hb;
                if (SPLIT) {
                    As[AW + wa] = f2tf32(va[j] - __uint_as_float(ha));
                    Bs[BW + wb] = f2tf32(vb[j] - __uint_as_float(hb));
                }
            }
        }
    };

    auto do_mma = [&](int stg) {
        const unsigned* As = Abuf + stg * ASTG;
        const unsigned* Bs = Bbuf + stg * BSTG;
#pragma unroll
        for (int ks = 0; ks < 2; ks++) {
            unsigned ah[2][4], al[2][4];
#pragma unroll
            for (int mi = 0; mi < 2; mi++) {
                int r = ks * 8 + wy * 2 + mi;
                int off = r * 128 + ((lane + rot(r)) & 31) * 4;
                *(uint4*)ah[mi] = *(const uint4*)&As[off];
                if (SPLIT) *(uint4*)al[mi] = *(const uint4*)&As[AW + off];
            }
#pragma unroll
            for (int ni = 0; ni < 8; ni++) {
                int R = ks * 16 + wx * 8 + ni;
                int off = R * 64 + ((lane + rot(R)) & 31) * 2;
                unsigned bh[2];
                *(uint2*)bh = *(const uint2*)&Bs[off];
#pragma unroll
                for (int mi = 0; mi < 2; mi++) mma_tf32(acc[mi][ni], ah[mi], bh[0], bh[1]);
                if (SPLIT) {
                    unsigned bl[2];
                    *(uint2*)bl = *(const uint2*)&Bs[BW + off];
#pragma unroll
                    for (int mi = 0; mi < 2; mi++) {
                        mma_tf32(acc[mi][ni], al[mi], bh[0], bh[1]);
                        mma_tf32(acc[mi][ni], ah[mi], bl[0], bl[1]);
                    }
                }
            }
        }
    };

    // Pipelined mainloop: one sync per K-tile; global load issued 2 tiles ahead.
    int nk = kchunk >> 4;
    load_tile(kbeg);
    store_frag(0);
    __syncthreads();
    if (nk > 1) load_tile(kbeg + 16);
    for (int kt = 0; kt < nk; kt++) {
        do_mma(kt & 1);
        if (kt + 1 < nk) {
            store_frag((kt + 1) & 1);
            if (kt + 2 < nk) load_tile(kbeg + ((kt + 2) << 4));
            __syncthreads();
        }
    }

    int g = lane >> 2, th = lane & 3;
    int mbase = wy * 32, nbase = wx * 64;
#pragma unroll
    for (int mi = 0; mi < 2; mi++) {
        int gm0 = m0 + mbase + mi * 16 + g;
        float bv0 = 0.f, bv1 = 0.f;
        if (ACT) {
            if (gm0 < Mreal)     bv0 = bias[gm0];
            if (gm0 + 8 < Mreal) bv1 = bias[gm0 + 8];
        }
#pragma unroll
        for (int ni = 0; ni < 8; ni++) {
            int gn = n0 + nbase + ni * 8 + 2 * th;
            float2 v0 = {acc[mi][ni][0], acc[mi][ni][1]};
            float2 v1 = {acc[mi][ni][2], acc[mi][ni][3]};
            if (MODE == 2) {
                v0.x = fmaxf(v0.x + bv0, 0.f); v0.y = fmaxf(v0.y + bv0, 0.f);
                v1.x = fmaxf(v1.x + bv1, 0.f); v1.y = fmaxf(v1.y + bv1, 0.f);
                int l = gn - n0;
                float ma = mask[s_m[l]], mb = mask[s_m[l + 1]];
                *(float2*)&Cz[(size_t)gm0 * N + gn] = v0;
                *(float2*)&Cz[(size_t)(gm0 + 8) * N + gn] = v1;
                float2 f0 = {v0.x * ma, v0.y * mb};
                float2 f1 = {v1.x * ma, v1.y * mb};
                *(float2*)&out2[(size_t)gm0 * N + gn] = f0;
                *(float2*)&out2[(size_t)(gm0 + 8) * N + gn] = f1;
            } else if (ACT) {
                v0.x += bv0; v0.y += bv0;
                v1.x += bv1; v1.y += bv1;
                if (ACT == 1) {
                    v0.x = v0.x > 0.f ? v0.x : expm1f(v0.x);
                    v0.y = v0.y > 0.f ? v0.y : expm1f(v0.y);
                    v1.x = v1.x > 0.f ? v1.x : expm1f(v1.x);
                    v1.y = v1.y > 0.f ? v1.y : expm1f(v1.y);
                } else {
                    v0.x = fmaxf(v0.x, 0.f); v0.y = fmaxf(v0.y, 0.f);
                    v1.x = fmaxf(v1.x, 0.f); v1.y = fmaxf(v1.y, 0.f);
                }
                if (gm0 < Mreal)     *(float2*)&Cz[(size_t)gm0 * N + gn] = v0;
                if (gm0 + 8 < Mreal) *(float2*)&Cz[(size_t)(gm0 + 8) * N + gn] = v1;
            } else {
                *(float2*)&Cz[(size_t)gm0 * N + gn] = v0;
                *(float2*)&Cz[(size_t)(gm0 + 8) * N + gn] = v1;
            }
        }
    }
}

// ---------------------------------------------------------------------------
// Attention helpers (shift-algebra form)
// ---------------------------------------------------------------------------
// Out[a,b] = sum over 9 diagonal shifts of In with per-coordinate validity.
// Grid-stride; SUMSQ=1 also accumulates sum(Out^2) into g_sumsq.
template <int SUMSQ>
__global__ void diag9_kernel(const float* __restrict__ In, float* __restrict__ Out) {
    unsigned stride = gridDim.x * blockDim.x;
    float ssq = 0.f;
    for (unsigned ii = blockIdx.x * blockDim.x + threadIdx.x; ii < 84934656u; ii += stride) {
        unsigned a = ii / 9216u, b = ii - a * 9216u;
        int ay = a / 96, ax = (int)a - ay * 96;
        int by = b / 96, bx = (int)b - by * 96;
        float s = 0.f;
#pragma unroll
        for (int dy = -1; dy <= 1; dy++) {
            if ((unsigned)(ay + dy) >= 96u || (unsigned)(by + dy) >= 96u) continue;
#pragma unroll
            for (int dx = -1; dx <= 1; dx++) {
                if ((unsigned)(ax + dx) >= 96u || (unsigned)(bx + dx) >= 96u) continue;
                s += In[(int)ii + (dy * 96 + dx) * 9217];
            }
        }
        Out[ii] = s;
        if (SUMSQ) ssq += s * s;
    }
    if (SUMSQ) {
        for (int o = 16; o; o >>= 1) ssq += __shfl_down_sync(0xffffffffu, ssq, o);
        __shared__ float red[8];
        int lane = threadIdx.x & 31, w = threadIdx.x >> 5;
        if (lane == 0) red[w] = ssq;
        __syncthreads();
        if (threadIdx.x < 32) {
            float v = (threadIdx.x < 8) ? red[threadIdx.x] : 0.f;
            for (int o = 4; o; o >>= 1) v += __shfl_down_sync(0xffffffffu, v, o);
            if (threadIdx.x == 0) atomicAdd(&g_sumsq, (double)v);
        }
    }
}

__global__ void zero_sum_kernel() {
    if (threadIdx.x == 0 && blockIdx.x == 0) g_sumsq = 0.0;
}

// One block per row p: A[p,:] = softmax(scale * S[p,:]), scale = 10/nrm. In-place.
__global__ void softmax_kernel(float* __restrict__ S) {
    extern __shared__ float row[];
    __shared__ float red[8];
    __shared__ float bval;
    int p = blockIdx.x;
    float* Sr = S + (size_t)p * 9216;
    float nrm = fmaxf(sqrtf((float)g_sumsq), 1e-12f);
    float scale = 10.f / nrm;
    int t = threadIdx.x;
    int lane = t & 31, w = t >> 5;

    float lm = -INFINITY;
    for (int i = t; i < 9216; i += 256) {
        float v = Sr[i] * scale;
        row[i] = v;
        lm = fmaxf(lm, v);
    }
    for (int o = 16; o; o >>= 1) lm = fmaxf(lm, __shfl_xor_sync(0xffffffffu, lm, o));
    if (lane == 0) red[w] = lm;
    __syncthreads();
    if (t < 32) {
        float v = (t < 8) ? red[t] : -INFINITY;
        for (int o = 4; o; o >>= 1) v = fmaxf(v, __shfl_xor_sync(0xffffffffu, v, o));
        if (t == 0) bval = v;
    }
    __syncthreads();
    float mx = bval;

    float ls = 0.f;
    for (int i = t; i < 9216; i += 256) {
        float e = __expf(row[i] - mx);
        row[i] = e;
        ls += e;
    }
    for (int o = 16; o; o >>= 1) ls += __shfl_xor_sync(0xffffffffu, ls, o);
    __syncthreads();
    if (lane == 0) red[w] = ls;
    __syncthreads();
    if (t < 32) {
        float v = (t < 8) ? red[t] : 0.f;
        for (int o = 4; o; o >>= 1) v += __shfl_xor_sync(0xffffffffu, v, o);
        if (t == 0) bval = v;
    }
    __syncthreads();
    float inv = 1.f / bval;
    for (int i = t; i < 9216; i += 256) Sr[i] = row[i] * inv;
}

// attn[c, 2x] = (sum of 4 split-K partials of Rt)[x, c] * m[x], 2x upsample.
__global__ void maskup_kernel(const float* __restrict__ Rt, const float* __restrict__ mask,
                              float* __restrict__ attn) {
    int idx = blockIdx.x * blockDim.x + threadIdx.x;
    if (idx >= 128 * 9216) return;
    int c = idx / 9216, x = idx % 9216;
    int yy = x / 96, xx = x % 96;
    float s = 0.f;
#pragma unroll
    for (int p = 0; p < 4; p++)
        s += Rt[(size_t)p * 1179648 + (size_t)x * 128 + c];
    s *= mask[(2 * yy) * 192 + 2 * xx];
    size_t base = (size_t)c * 36864 + (size_t)(2 * yy) * 192 + 2 * xx;
    attn[base]       = s;
    attn[base + 1]   = s;
    attn[base + 192] = s;
    attn[base + 193] = s;
}

// ---------------------------------------------------------------------------
// Host orchestration
// ---------------------------------------------------------------------------
#define SMEM_SPLIT 65536
#define SMEM_PLAIN 32768

extern "C" void kernel_launch(void* const* d_in, const int* in_sizes, int n_in,
                              void* d_out, int out_size) {
    const float* x    = (const float*)d_in[0];
    const float* mask = (const float*)d_in[1];
    const float* w[8];
    const float* b[8];
    for (int i = 0; i < 8; i++) {
        w[i] = (const float*)d_in[2 + 2 * i];
        b[i] = (const float*)d_in[3 + 2 * i];
    }

    float *b1, *b2, *b3, *b4, *b5, *fg, *ds, *S, *CM, *Rt, *attn, *b7, *wt;
    cudaGetSymbolAddress((void**)&b1,   g_b1);
    cudaGetSymbolAddress((void**)&b2,   g_b2);
    cudaGetSymbolAddress((void**)&b3,   g_b3);
    cudaGetSymbolAddress((void**)&b4,   g_b4);
    cudaGetSymbolAddress((void**)&b5,   g_b5);
    cudaGetSymbolAddress((void**)&fg,   g_fg);
    cudaGetSymbolAddress((void**)&ds,   g_ds);
    cudaGetSymbolAddress((void**)&S,    g_S);
    cudaGetSymbolAddress((void**)&CM,   g_CM);
    cudaGetSymbolAddress((void**)&Rt,   g_Rt);
    cudaGetSymbolAddress((void**)&attn, g_attn);
    cudaGetSymbolAddress((void**)&b7,   g_b7);
    cudaGetSymbolAddress((void**)&wt,   g_wt);

    // Opt into >48KB dynamic smem for the split-tf32 instantiations.
    cudaFuncSetAttribute(mma_gemm_kernel<0, 1, 1, 1, 32, 768, 768, 2>,
                         cudaFuncAttributeMaxDynamicSharedMemorySize, SMEM_SPLIT);
    cudaFuncSetAttribute(mma_gemm_kernel<0, 1, 1, 1, 32, 384, 384, 1>,
                         cudaFuncAttributeMaxDynamicSharedMemorySize, SMEM_SPLIT);
    cudaFuncSetAttribute(mma_gemm_kernel<0, 1, 1, 1, 64, 384, 384, 2>,
                         cudaFuncAttributeMaxDynamicSharedMemorySize, SMEM_SPLIT);
    cudaFuncSetAttribute(mma_gemm_kernel<0, 1, 1, 1, 128, 192, 192, 1>,
                         cudaFuncAttributeMaxDynamicSharedMemorySize, SMEM_SPLIT);
    cudaFuncSetAttribute(mma_gemm_kernel<0, 1, 2, 2, 128, 192, 192, 2>,
                         cudaFuncAttributeMaxDynamicSharedMemorySize, SMEM_SPLIT);
    cudaFuncSetAttribute(mma_gemm_kernel<1, 1, 0, 0, 1, 1, 1, 1>,
                         cudaFuncAttributeMaxDynamicSharedMemorySize, SMEM_SPLIT);

    // conv1: K=75, FFMA with implicit gather (C=3, 768x768, 5x5, pad2, str1)
    conv_ffma_kernel<1, 32, 256, 3, 768, 768, 5, 2, 1>
        <<<dim3(589824 / 256, 1), 256>>>(w[0], x, b[0], b1, 32, 589824, 75);

    // All weight transposes in one launch.
    transpose_all_kernel<<<(737280 + 255) / 256, 256>>>(
        w[1], w[2], w[3], w[4], w[5], w[6], w[7], wt);

    // conv2: C=32, 768x768, str2 -> 384x384, K=288, OC=32
    mma_gemm_kernel<0, 1, 1, 1, 32, 768, 768, 2><<<dim3(1152, 1, 1), 256, SMEM_SPLIT>>>(
        wt + 0, b1, b[1], b2, 128, 147456, 288, 32, nullptr, nullptr);

    // conv3: C=32, 384x384, str1, K=288, OC=64
    mma_gemm_kernel<0, 1, 1, 1, 32, 384, 384, 1><<<dim3(1152, 1, 1), 256, SMEM_SPLIT>>>(
        wt + 36864, b2, b[2], b3, 128, 147456, 288, 64, nullptr, nullptr);

    // conv4: C=64, 384x384, str2 -> 192x192, K=576, OC=128
    mma_gemm_kernel<0, 1, 1, 1, 64, 384, 384, 2><<<dim3(288, 1, 1), 256, SMEM_SPLIT>>>(
        wt + 73728, b3, b[3], b4, 128, 36864, 576, 128, nullptr, nullptr);

    // conv5: C=128, 192x192, str1, K=1152
    mma_gemm_kernel<0, 1, 1, 1, 128, 192, 192, 1><<<dim3(288, 1, 1), 256, SMEM_SPLIT>>>(
        wt + 147456, b4, b[4], b5, 128, 36864, 1152, 128, nullptr, nullptr);

    // conv6: strided conv (192x192, str2 -> 96x96), relu epilogue -> ds, fg.
    mma_gemm_kernel<0, 1, 2, 2, 128, 192, 192, 2><<<dim3(72, 1, 1), 256, SMEM_SPLIT>>>(
        wt + 294912, b5, b[5], ds, 128, 9216, 1152, 128, mask, fg);

    // Contextual attention (shift algebra)
    // C = fg^T * ds : M=N=9216, K=128, TN layout, plain tf32.
    mma_gemm_kernel<0, 0, 0, 0, 1, 1, 1, 1><<<dim3(72, 72, 1), 256, SMEM_PLAIN>>>(
        fg, ds, nullptr, CM, 9216, 9216, 128, 9216, nullptr, nullptr);
    zero_sum_kernel<<<1, 32>>>();
    diag9_kernel<1><<<2048, 256>>>(CM, S);   // S = diag9(C), fused ||S||^2
    softmax_kernel<<<9216, 256, 9216 * sizeof(float)>>>(S);
    diag9_kernel<0><<<2048, 256>>>(S, CM);   // M = diag9(A)
    // out[x,c] = sum_u M[x,u] * ds[c,u] : NT, split tf32, split-K x4.
    mma_gemm_kernel<1, 1, 0, 0, 1, 1, 1, 1><<<dim3(1, 72, 4), 256, SMEM_SPLIT>>>(
        CM, ds, nullptr, Rt, 9216, 128, 9216, 9216, nullptr, nullptr);
    maskup_kernel<<<(128 * 9216 + 255) / 256, 256>>>(Rt, mask, attn);

    // conv7: C=128, 192x192, str1, K=1152
    mma_gemm_kernel<0, 1, 1, 1, 128, 192, 192, 1><<<dim3(288, 1, 1), 256, SMEM_SPLIT>>>(
        wt + 442368, attn, b[6], b7, 128, 36864, 1152, 128, nullptr, nullptr);

    // conv8
    mma_gemm_kernel<0, 1, 1, 1, 128, 192, 192, 1><<<dim3(288, 1, 1), 256, SMEM_SPLIT>>>(
        wt + 589824, b7, b[7], (float*)d_out, 128, 36864, 1152, 128, nullptr, nullptr);
}

// round 12
// speedup vs baseline: 4.8615x; 1.0977x over previous
#include <cuda_runtime.h>
#include <stdint.h>
#include <cstdint>
#include <math.h>

// ---------------------------------------------------------------------------
// Scratch (device globals -- allocation-free per harness rules)
// ---------------------------------------------------------------------------
__device__ float  g_b1[18874368];   // conv1 out 32*768*768
__device__ float  g_b2[4718592];    // conv2 out 32*384*384
__device__ float  g_b3[9437184];    // conv3 out 64*384*384
__device__ float  g_b4[4718592];    // conv4 out 128*192*192
__device__ float  g_b5[4718592];    // conv5 out
__device__ float  g_fg[1179648];    // fg = ds*mask, 128 x 9216
__device__ float  g_ds[1179648];    // ds downsampled bg, 128 x 9216
__device__ float  g_S[84934656];    // 9216 x 9216 (S, then softmaxed A in-place)
__device__ float  g_CM[84934656];   // C = fg^T ds, later M = diag9(A)
__device__ float  g_Rt[4718592];    // 4 split-K partials of 9216 x 128
__device__ float  g_attn[4718592];  // attention out 128*192*192
__device__ float  g_b7[4718592];    // conv7 out
__device__ float  g_wt[737280];     // transposed padded weights (segmented, K x MT)
__device__ double g_sumsq;          // Frobenius norm accumulator

// ---------------------------------------------------------------------------
// Helpers
// ---------------------------------------------------------------------------
__device__ __forceinline__ int refl(int i, int n) {
    if (i < 0) i = -i;
    if (i >= n) i = 2 * n - 2 - i;
    return i;
}

__device__ __forceinline__ unsigned f2tf32(float x) {
    unsigned r;
    asm("cvt.rna.tf32.f32 %0, %1;" : "=r"(r) : "f"(x));
    return r;
}

__device__ __forceinline__ void mma_tf32(float* c, const unsigned* a, unsigned b0, unsigned b1) {
    asm volatile(
        "mma.sync.aligned.m16n8k8.row.col.f32.tf32.tf32.f32 "
        "{%0,%1,%2,%3},{%4,%5,%6,%7},{%8,%9},{%0,%1,%2,%3};\n"
        : "+f"(c[0]), "+f"(c[1]), "+f"(c[2]), "+f"(c[3])
        : "r"(a[0]), "r"(a[1]), "r"(a[2]), "r"(a[3]), "r"(b0), "r"(b1));
}

__device__ __forceinline__ int rot(int r) { return r + (r >> 3); }

// A fragment-order index within a 16k x MT tile (AROWS = MT/16 rows per ks).
template <int AROWS>
__device__ __forceinline__ int a_widx(int kk, int mm) {
    int ks = kk >> 3, k = kk & 7;
    int th = k & 3, rh = (k >> 2) & 1;
    int mb = mm >> 4, rr = mm & 15, g = rr & 7, mh = (rr >> 3) & 1;
    int r = ks * AROWS + mb;
    int grp = (g * 4 + th + rot(r)) & 31;
    return r * 128 + grp * 4 + rh * 2 + mh;
}
__device__ __forceinline__ int b_widx(int kk, int nn) {
    int ks = kk >> 3, k = kk & 7;
    int th = k & 3, rh = (k >> 2) & 1;
    int nb = nn >> 3, g = nn & 7;
    int R = ks * 16 + nb;
    int grp = (g * 4 + th + rot(R)) & 31;
    return R * 64 + grp * 2 + rh;
}

// One launch: transpose+pad all 7 conv weights into segmented g_wt (K x MT).
__global__ void transpose_all_kernel(
    const float* __restrict__ w2, const float* __restrict__ w3,
    const float* __restrict__ w4, const float* __restrict__ w5,
    const float* __restrict__ w6, const float* __restrict__ w7,
    const float* __restrict__ w8, float* __restrict__ wt) {
    int idx = blockIdx.x * blockDim.x + threadIdx.x;
    if (idx >= 691200) return;
    const float* w; int K, M, MT, off;
    if (idx < 9216)        { w = w2; K = 288;  M = 32;  MT = 32;  off = 0; }
    else if (idx < 27648)  { w = w3; K = 288;  M = 64;  MT = 64;  off = 9216; }
    else if (idx < 101376) { w = w4; K = 576;  M = 128; MT = 128; off = 27648; }
    else if (idx < 248832) { w = w5; K = 1152; M = 128; MT = 128; off = 101376; }
    else if (idx < 396288) { w = w6; K = 1152; M = 128; MT = 128; off = 248832; }
    else if (idx < 543744) { w = w7; K = 1152; M = 128; MT = 128; off = 396288; }
    else                   { w = w8; K = 1152; M = 128; MT = 128; off = 543744; }
    int l = idx - off;
    int k = l / MT, m = l - k * MT;
    wt[idx] = (m < M) ? w[m * K + k] : 0.f;
}

// ---------------------------------------------------------------------------
// FFMA conv GEMM with implicit im2col gather (conv1: K=75 not %16)
// ---------------------------------------------------------------------------
template <int ACT, int TM, int TN, int CC, int HH, int WW, int KS, int PAD, int STR>
__global__ __launch_bounds__(256, 2) void conv_ffma_kernel(
    const float* __restrict__ A, const float* __restrict__ In,
    const float* __restrict__ bias, float* __restrict__ C,
    int M, int N, int K) {
    constexpr int OW = (WW + 2 * PAD - KS) / STR + 1;
    constexpr int KSQ = KS * KS;
    constexpr int TNTH = TN / 8;
    constexpr int TMTH = 256 / TNTH;
    constexpr int MR   = TM / TMTH;
    __shared__ __align__(16) float As[8][TM + 4];
    __shared__ __align__(16) float Bs[8][TN + 4];
    __shared__ int s_off[TN][KSQ];
    int t  = threadIdx.x;
    int tx = t % TNTH, ty = t / TNTH;
    int m0 = blockIdx.y * TM, n0 = blockIdx.x * TN;

    if (t < TN) {
        int n = n0 + t;
        int oy = n / OW;
        int ox = n - oy * OW;
        int iy[KS], ix[KS];
#pragma unroll
        for (int q = 0; q < KS; q++) {
            iy[q] = refl(oy * STR + q - PAD, HH) * WW;
            ix[q] = refl(ox * STR + q - PAD, WW);
        }
#pragma unroll
        for (int ky = 0; ky < KS; ky++)
#pragma unroll
            for (int kx = 0; kx < KS; kx++)
                s_off[t][ky * KS + kx] = iy[ky] + ix[kx];
    }
    __syncthreads();

    float acc[MR][8];
#pragma unroll
    for (int i = 0; i < MR; i++)
#pragma unroll
        for (int j = 0; j < 8; j++) acc[i][j] = 0.f;

    for (int k0 = 0; k0 < K; k0 += 8) {
#pragma unroll
        for (int i = 0; i < TM * 8 / 256; i++) {
            int id = t + i * 256;
            int kk = id & 7, mm = id >> 3;
            int gk = k0 + kk;
            As[kk][mm] = (gk < K && m0 + mm < M) ? A[(size_t)(m0 + mm) * K + gk] : 0.f;
        }
#pragma unroll
        for (int i = 0; i < TN * 8 / 256; i++) {
            int id = t + i * 256;
            int kk = id / TN, nn = id % TN;
            int gk = k0 + kk;
            float v = 0.f;
            if (gk < K) {
                int c = gk / KSQ;
                int r = gk - c * KSQ;
                v = In[c * (HH * WW) + s_off[nn][r]];
            }
            Bs[kk][nn] = v;
        }
        __syncthreads();
#pragma unroll
        for (int kk = 0; kk < 8; kk++) {
            float a[MR], b[8];
#pragma unroll
            for (int h = 0; h < MR / 4; h++)
                *(float4*)&a[h * 4] = *(const float4*)&As[kk][ty * MR + h * 4];
            *(float4*)&b[0] = *(const float4*)&Bs[kk][tx * 8];
            *(float4*)&b[4] = *(const float4*)&Bs[kk][tx * 8 + 4];
#pragma unroll
            for (int i = 0; i < MR; i++)
#pragma unroll
                for (int j = 0; j < 8; j++) acc[i][j] += a[i] * b[j];
        }
        __syncthreads();
    }

#pragma unroll
    for (int i = 0; i < MR; i++) {
        int gm = m0 + ty * MR + i;
        if (gm >= M) continue;
        float bv = bias[gm];
#pragma unroll
        for (int j = 0; j < 8; j++) {
            int gn = n0 + tx * 8 + j;
            if (gn >= N) continue;
            float v = acc[i][j] + bv;
            if (ACT == 1) v = v > 0.f ? v : expm1f(v);
            else v = fmaxf(v, 0.f);
            C[(size_t)gm * N + gn] = v;
        }
    }
}

// ---------------------------------------------------------------------------
// TF32 tensor-core GEMM, swizzled fragment-order smem, double-buffered.
//   MT: M tile (32/64/128) -- matches OC so no padded-M flops.
//   LAYOUT 0 (TN): A: K x MT, B: K x N.  LAYOUT 1 (NT, MT=128): A: M x K, B: N x K.
//   SPLIT: hi/lo tf32 decomposition. ACT: 0 none, 1 elu, 2 relu (+bias).
//   MODE: 0 plain B; 1 implicit 3x3 reflect-pad conv gather; 2 strided conv
//         with dual ds/fg epilogue. Split-K via gridDim.z.
// ---------------------------------------------------------------------------
template <int MT, int LAYOUT, int SPLIT, int ACT, int MODE, int CC, int HH, int WW, int STR>
__global__ __launch_bounds__(256) void mma_gemm_kernel(
    const float* __restrict__ A, const float* __restrict__ B,
    const float* __restrict__ bias, float* __restrict__ C,
    int M, int N, int K, int Mreal,
    const float* __restrict__ mask, float* __restrict__ out2) {
    constexpr int OWc = MODE ? ((WW - 1) / STR + 1) : 1;
    constexpr int AROWS = MT / 16;           // A frag rows per ks
    constexpr int AW = 2 * AROWS * 128;      // words per plane
    constexpr int BW = 2 * 16 * 64;
    constexpr int PL = SPLIT ? 2 : 1;
    constexpr int ASTG = AW * PL;
    constexpr int BSTG = BW * PL;
    constexpr int NW_Y = MT / 32;            // warps along m
    constexpr int NW_X = 8 / NW_Y;           // warps along n
    constexpr int NFRAG = 16 / NW_X;         // 8-wide n frags per warp
    constexpr int AF4 = 4 * MT;              // float4 loads for A tile
    extern __shared__ unsigned dyns[];
    unsigned* Abuf = dyns;
    unsigned* Bbuf = dyns + 2 * ASTG;
    __shared__ int s_off[MODE ? 128 : 1][MODE ? 9 : 1];
    __shared__ int s_m[MODE == 2 ? 128 : 1];
    int t = threadIdx.x;
    int m0 = blockIdx.y * MT, n0 = blockIdx.x * 128;
    int lane = t & 31, warp = t >> 5;
    int wy = warp / NW_X, wx = warp % NW_X;

    int kchunk = K / (int)gridDim.z;
    int kbeg = (int)blockIdx.z * kchunk;
    float* Cz = C + (size_t)blockIdx.z * ((size_t)M * N);

    if (MODE) {
        if (t < 128) {
            int n = n0 + t;
            int oy = n / OWc;
            int ox = n - oy * OWc;
            int by = oy * STR, bx = ox * STR;
            int iy[3], ix[3];
#pragma unroll
            for (int q = 0; q < 3; q++) {
                iy[q] = refl(by + q - 1, HH) * WW;
                ix[q] = refl(bx + q - 1, WW);
            }
#pragma unroll
            for (int ky = 0; ky < 3; ky++)
#pragma unroll
                for (int kx = 0; kx < 3; kx++)
                    s_off[t][ky * 3 + kx] = iy[ky] + ix[kx];
            if (MODE == 2) s_m[t] = by * WW + bx;
        }
        __syncthreads();
    }

    float acc[2][NFRAG][4];
#pragma unroll
    for (int mi = 0; mi < 2; mi++)
#pragma unroll
        for (int ni = 0; ni < NFRAG; ni++)
#pragma unroll
            for (int r = 0; r < 4; r++) acc[mi][ni][r] = 0.f;

    float4 pa[2], pb[2];

    auto load_tile = [&](int k0) {
#pragma unroll
        for (int i = 0; i < 2; i++) {
            int id = t + i * 256;
            if (LAYOUT == 0) {
                if (id < AF4) {
                    int kk = id / (MT / 4), cg = id % (MT / 4);
                    pa[i] = *(const float4*)&A[(size_t)(k0 + kk) * M + m0 + cg * 4];
                }
                int kk = id >> 5, cg = id & 31;
                if (MODE) {
                    int k = k0 + kk;
                    int c = k / 9;
                    int r9 = k - c * 9;
                    const float* Bp = B + (size_t)c * (HH * WW);
                    float v[4];
#pragma unroll
                    for (int j = 0; j < 4; j++) {
                        int nn = cg + 32 * j;  // lane-coalesced gather mapping
                        v[j] = Bp[s_off[nn][r9]];
                    }
                    pb[i] = {v[0], v[1], v[2], v[3]};
                } else {
                    pb[i] = *(const float4*)&B[(size_t)(k0 + kk) * N + n0 + cg * 4];
                }
            } else {
                int mm = id >> 2, kg = id & 3;
                pa[i] = *(const float4*)&A[(size_t)(m0 + mm) * K + k0 + kg * 4];
                pb[i] = *(const float4*)&B[(size_t)(n0 + mm) * K + k0 + kg * 4];
            }
        }
    };

    auto store_frag = [&](int stg) {
        unsigned* As = Abuf + stg * ASTG;
        unsigned* Bs = Bbuf + stg * BSTG;
#pragma unroll
        for (int i = 0; i < 2; i++) {
            int id = t + i * 256;
            const float* va = (const float*)&pa[i];
            const float* vb = (const float*)&pb[i];
            // A side
            if (LAYOUT == 1 || id < AF4) {
#pragma unroll
                for (int j = 0; j < 4; j++) {
                    int kk, cca;
                    if (LAYOUT == 0) { kk = id / (MT / 4); cca = (id % (MT / 4)) * 4 + j; }
                    else             { kk = (id & 3) * 4 + j; cca = id >> 2; }
                    int wa = a_widx<AROWS>(kk, cca);
                    unsigned ha = f2tf32(va[j]);
                    As[wa] = ha;
                    if (SPLIT) As[AW + wa] = f2tf32(va[j] - __uint_as_float(ha));
                }
            }
            // B side
#pragma unroll
            for (int j = 0; j < 4; j++) {
                int kk, ccb;
                if (LAYOUT == 0) {
                    kk = id >> 5;
                    ccb = MODE ? ((id & 31) + 32 * j) : ((id & 31) * 4 + j);
                } else {
                    kk = (id & 3) * 4 + j;
                    ccb = id >> 2;
                }
                int wb = b_widx(kk, ccb);
                unsigned hb = f2tf32(vb[j]);
                Bs[wb] = hb;
                if (SPLIT) Bs[BW + wb] = f2tf32(vb[j] - __uint_as_float(hb));
            }
        }
    };

    auto do_mma = [&](int stg) {
        const unsigned* As = Abuf + stg * ASTG;
        const unsigned* Bs = Bbuf + stg * BSTG;
#pragma unroll
        for (int ks = 0; ks < 2; ks++) {
            unsigned ah[2][4], al[2][4];
#pragma unroll
            for (int mi = 0; mi < 2; mi++) {
                int r = ks * AROWS + wy * 2 + mi;
                int off = r * 128 + ((lane + rot(r)) & 31) * 4;
                *(uint4*)ah[mi] = *(const uint4*)&As[off];
                if (SPLIT) *(uint4*)al[mi] = *(const uint4*)&As[AW + off];
            }
#pragma unroll
            for (int ni = 0; ni < NFRAG; ni++) {
                int R = ks * 16 + wx * NFRAG + ni;
                int off = R * 64 + ((lane + rot(R)) & 31) * 2;
                unsigned bh[2];
                *(uint2*)bh = *(const uint2*)&Bs[off];
#pragma unroll
                for (int mi = 0; mi < 2; mi++) mma_tf32(acc[mi][ni], ah[mi], bh[0], bh[1]);
                if (SPLIT) {
                    unsigned bl[2];
                    *(uint2*)bl = *(const uint2*)&Bs[BW + off];
#pragma unroll
                    for (int mi = 0; mi < 2; mi++) {
                        mma_tf32(acc[mi][ni], al[mi], bh[0], bh[1]);
                        mma_tf32(acc[mi][ni], ah[mi], bl[0], bl[1]);
                    }
                }
            }
        }
    };

    // Pipelined mainloop: one sync per K-tile; global load issued 2 tiles ahead.
    int nk = kchunk >> 4;
    load_tile(kbeg);
    store_frag(0);
    __syncthreads();
    if (nk > 1) load_tile(kbeg + 16);
    for (int kt = 0; kt < nk; kt++) {
        do_mma(kt & 1);
        if (kt + 1 < nk) {
            store_frag((kt + 1) & 1);
            if (kt + 2 < nk) load_tile(kbeg + ((kt + 2) << 4));
            __syncthreads();
        }
    }

    int g = lane >> 2, th = lane & 3;
    int mbase = wy * 32, nbase = wx * (NFRAG * 8);
#pragma unroll
    for (int mi = 0; mi < 2; mi++) {
        int gm0 = m0 + mbase + mi * 16 + g;
        float bv0 = 0.f, bv1 = 0.f;
        if (ACT) {
            if (gm0 < Mreal)     bv0 = bias[gm0];
            if (gm0 + 8 < Mreal) bv1 = bias[gm0 + 8];
        }
#pragma unroll
        for (int ni = 0; ni < NFRAG; ni++) {
            int gn = n0 + nbase + ni * 8 + 2 * th;
            float2 v0 = {acc[mi][ni][0], acc[mi][ni][1]};
            float2 v1 = {acc[mi][ni][2], acc[mi][ni][3]};
            if (MODE == 2) {
                v0.x = fmaxf(v0.x + bv0, 0.f); v0.y = fmaxf(v0.y + bv0, 0.f);
                v1.x = fmaxf(v1.x + bv1, 0.f); v1.y = fmaxf(v1.y + bv1, 0.f);
                int l = gn - n0;
                float ma = mask[s_m[l]], mb = mask[s_m[l + 1]];
                *(float2*)&Cz[(size_t)gm0 * N + gn] = v0;
                *(float2*)&Cz[(size_t)(gm0 + 8) * N + gn] = v1;
                float2 f0 = {v0.x * ma, v0.y * mb};
                float2 f1 = {v1.x * ma, v1.y * mb};
                *(float2*)&out2[(size_t)gm0 * N + gn] = f0;
                *(float2*)&out2[(size_t)(gm0 + 8) * N + gn] = f1;
            } else if (ACT) {
                v0.x += bv0; v0.y += bv0;
                v1.x += bv1; v1.y += bv1;
                if (ACT == 1) {
                    v0.x = v0.x > 0.f ? v0.x : expm1f(v0.x);
                    v0.y = v0.y > 0.f ? v0.y : expm1f(v0.y);
                    v1.x = v1.x > 0.f ? v1.x : expm1f(v1.x);
                    v1.y = v1.y > 0.f ? v1.y : expm1f(v1.y);
                } else {
                    v0.x = fmaxf(v0.x, 0.f); v0.y = fmaxf(v0.y, 0.f);
                    v1.x = fmaxf(v1.x, 0.f); v1.y = fmaxf(v1.y, 0.f);
                }
                if (gm0 < Mreal)     *(float2*)&Cz[(size_t)gm0 * N + gn] = v0;
                if (gm0 + 8 < Mreal) *(float2*)&Cz[(size_t)(gm0 + 8) * N + gn] = v1;
            } else {
                *(float2*)&Cz[(size_t)gm0 * N + gn] = v0;
                *(float2*)&Cz[(size_t)(gm0 + 8) * N + gn] = v1;
            }
        }
    }
}

// ---------------------------------------------------------------------------
// Attention helpers (shift-algebra form)
// ---------------------------------------------------------------------------
template <int SUMSQ>
__global__ void diag9_kernel(const float* __restrict__ In, float* __restrict__ Out) {
    unsigned stride = gridDim.x * blockDim.x;
    float ssq = 0.f;
    for (unsigned ii = blockIdx.x * blockDim.x + threadIdx.x; ii < 84934656u; ii += stride) {
        unsigned a = ii / 9216u, b = ii - a * 9216u;
        int ay = a / 96, ax = (int)a - ay * 96;
        int by = b / 96, bx = (int)b - by * 96;
        float s = 0.f;
#pragma unroll
        for (int dy = -1; dy <= 1; dy++) {
            if ((unsigned)(ay + dy) >= 96u || (unsigned)(by + dy) >= 96u) continue;
#pragma unroll
            for (int dx = -1; dx <= 1; dx++) {
                if ((unsigned)(ax + dx) >= 96u || (unsigned)(bx + dx) >= 96u) continue;
                s += In[(int)ii + (dy * 96 + dx) * 9217];
            }
        }
        Out[ii] = s;
        if (SUMSQ) ssq += s * s;
    }
    if (SUMSQ) {
        for (int o = 16; o; o >>= 1) ssq += __shfl_down_sync(0xffffffffu, ssq, o);
        __shared__ float red[8];
        int lane = threadIdx.x & 31, w = threadIdx.x >> 5;
        if (lane == 0) red[w] = ssq;
        __syncthreads();
        if (threadIdx.x < 32) {
            float v = (threadIdx.x < 8) ? red[threadIdx.x] : 0.f;
            for (int o = 4; o; o >>= 1) v += __shfl_down_sync(0xffffffffu, v, o);
            if (threadIdx.x == 0) atomicAdd(&g_sumsq, (double)v);
        }
    }
}

__global__ void zero_sum_kernel() {
    if (threadIdx.x == 0 && blockIdx.x == 0) g_sumsq = 0.0;
}

// One block per row p: A[p,:] = softmax(scale * S[p,:]), scale = 10/nrm. In-place.
__global__ void softmax_kernel(float* __restrict__ S) {
    extern __shared__ float row[];
    __shared__ float red[8];
    __shared__ float bval;
    int p = blockIdx.x;
    float* Sr = S + (size_t)p * 9216;
    float nrm = fmaxf(sqrtf((float)g_sumsq), 1e-12f);
    float scale = 10.f / nrm;
    int t = threadIdx.x;
    int lane = t & 31, w = t >> 5;

    float lm = -INFINITY;
    for (int i = t; i < 9216; i += 256) {
        float v = Sr[i] * scale;
        row[i] = v;
        lm = fmaxf(lm, v);
    }
    for (int o = 16; o; o >>= 1) lm = fmaxf(lm, __shfl_xor_sync(0xffffffffu, lm, o));
    if (lane == 0) red[w] = lm;
    __syncthreads();
    if (t < 32) {
        float v = (t < 8) ? red[t] : -INFINITY;
        for (int o = 4; o; o >>= 1) v = fmaxf(v, __shfl_xor_sync(0xffffffffu, v, o));
        if (t == 0) bval = v;
    }
    __syncthreads();
    float mx = bval;

    float ls = 0.f;
    for (int i = t; i < 9216; i += 256) {
        float e = __expf(row[i] - mx);
        row[i] = e;
        ls += e;
    }
    for (int o = 16; o; o >>= 1) ls += __shfl_xor_sync(0xffffffffu, ls, o);
    __syncthreads();
    if (lane == 0) red[w] = ls;
    __syncthreads();
    if (t < 32) {
        float v = (t < 8) ? red[t] : 0.f;
        for (int o = 4; o; o >>= 1) v += __shfl_xor_sync(0xffffffffu, v, o);
        if (t == 0) bval = v;
    }
    __syncthreads();
    float inv = 1.f / bval;
    for (int i = t; i < 9216; i += 256) Sr[i] = row[i] * inv;
}

// attn[c, 2x] = (sum of 4 split-K partials of Rt)[x, c] * m[x], 2x upsample.
__global__ void maskup_kernel(const float* __restrict__ Rt, const float* __restrict__ mask,
                              float* __restrict__ attn) {
    int idx = blockIdx.x * blockDim.x + threadIdx.x;
    if (idx >= 128 * 9216) return;
    int c = idx / 9216, x = idx % 9216;
    int yy = x / 96, xx = x % 96;
    float s = 0.f;
#pragma unroll
    for (int p = 0; p < 4; p++)
        s += Rt[(size_t)p * 1179648 + (size_t)x * 128 + c];
    s *= mask[(2 * yy) * 192 + 2 * xx];
    size_t base = (size_t)c * 36864 + (size_t)(2 * yy) * 192 + 2 * xx;
    attn[base]       = s;
    attn[base + 1]   = s;
    attn[base + 192] = s;
    attn[base + 193] = s;
}

// ---------------------------------------------------------------------------
// Host orchestration
// ---------------------------------------------------------------------------
// Dynamic smem bytes: 2 stages x (A + B) x planes x 4B
#define SMEM_MT128_SPLIT 65536   // (2*4096 + 2*4096)*4
#define SMEM_MT64_SPLIT  49152   // (2*2048 + 2*4096)*4
#define SMEM_MT32_SPLIT  40960   // (2*1024 + 2*4096)*4
#define SMEM_MT128_PLAIN 32768   // (2*2048 + 2*2048)*4

extern "C" void kernel_launch(void* const* d_in, const int* in_sizes, int n_in,
                              void* d_out, int out_size) {
    const float* x    = (const float*)d_in[0];
    const float* mask = (const float*)d_in[1];
    const float* w[8];
    const float* b[8];
    for (int i = 0; i < 8; i++) {
        w[i] = (const float*)d_in[2 + 2 * i];
        b[i] = (const float*)d_in[3 + 2 * i];
    }

    float *b1, *b2, *b3, *b4, *b5, *fg, *ds, *S, *CM, *Rt, *attn, *b7, *wt;
    cudaGetSymbolAddress((void**)&b1,   g_b1);
    cudaGetSymbolAddress((void**)&b2,   g_b2);
    cudaGetSymbolAddress((void**)&b3,   g_b3);
    cudaGetSymbolAddress((void**)&b4,   g_b4);
    cudaGetSymbolAddress((void**)&b5,   g_b5);
    cudaGetSymbolAddress((void**)&fg,   g_fg);
    cudaGetSymbolAddress((void**)&ds,   g_ds);
    cudaGetSymbolAddress((void**)&S,    g_S);
    cudaGetSymbolAddress((void**)&CM,   g_CM);
    cudaGetSymbolAddress((void**)&Rt,   g_Rt);
    cudaGetSymbolAddress((void**)&attn, g_attn);
    cudaGetSymbolAddress((void**)&b7,   g_b7);
    cudaGetSymbolAddress((void**)&wt,   g_wt);

    cudaFuncSetAttribute(mma_gemm_kernel<32, 0, 1, 1, 1, 32, 768, 768, 2>,
                         cudaFuncAttributeMaxDynamicSharedMemorySize, SMEM_MT32_SPLIT);
    cudaFuncSetAttribute(mma_gemm_kernel<64, 0, 1, 1, 1, 32, 384, 384, 1>,
                         cudaFuncAttributeMaxDynamicSharedMemorySize, SMEM_MT64_SPLIT);
    cudaFuncSetAttribute(mma_gemm_kernel<128, 0, 1, 1, 1, 64, 384, 384, 2>,
                         cudaFuncAttributeMaxDynamicSharedMemorySize, SMEM_MT128_SPLIT);
    cudaFuncSetAttribute(mma_gemm_kernel<128, 0, 1, 1, 1, 128, 192, 192, 1>,
                         cudaFuncAttributeMaxDynamicSharedMemorySize, SMEM_MT128_SPLIT);
    cudaFuncSetAttribute(mma_gemm_kernel<128, 0, 1, 2, 2, 128, 192, 192, 2>,
                         cudaFuncAttributeMaxDynamicSharedMemorySize, SMEM_MT128_SPLIT);
    cudaFuncSetAttribute(mma_gemm_kernel<128, 1, 1, 0, 0, 1, 1, 1, 1>,
                         cudaFuncAttributeMaxDynamicSharedMemorySize, SMEM_MT128_SPLIT);

    // conv1: K=75, FFMA with implicit gather (C=3, 768x768, 5x5, pad2, str1)
    conv_ffma_kernel<1, 32, 256, 3, 768, 768, 5, 2, 1>
        <<<dim3(589824 / 256, 1), 256>>>(w[0], x, b[0], b1, 32, 589824, 75);

    // All weight transposes in one launch (padded to each conv's MT).
    transpose_all_kernel<<<(691200 + 255) / 256, 256>>>(
        w[1], w[2], w[3], w[4], w[5], w[6], w[7], wt);

    // conv2: C=32, 768x768, str2 -> 384x384, K=288, OC=32, MT=32
    mma_gemm_kernel<32, 0, 1, 1, 1, 32, 768, 768, 2>
        <<<dim3(1152, 1, 1), 256, SMEM_MT32_SPLIT>>>(
        wt + 0, b1, b[1], b2, 32, 147456, 288, 32, nullptr, nullptr);

    // conv3: C=32, 384x384, str1, K=288, OC=64, MT=64
    mma_gemm_kernel<64, 0, 1, 1, 1, 32, 384, 384, 1>
        <<<dim3(1152, 1, 1), 256, SMEM_MT64_SPLIT>>>(
        wt + 9216, b2, b[2], b3, 64, 147456, 288, 64, nullptr, nullptr);

    // conv4: C=64, 384x384, str2 -> 192x192, K=576, OC=128
    mma_gemm_kernel<128, 0, 1, 1, 1, 64, 384, 384, 2>
        <<<dim3(288, 1, 1), 256, SMEM_MT128_SPLIT>>>(
        wt + 27648, b3, b[3], b4, 128, 36864, 576, 128, nullptr, nullptr);

    // conv5: C=128, 192x192, str1, K=1152
    mma_gemm_kernel<128, 0, 1, 1, 1, 128, 192, 192, 1>
        <<<dim3(288, 1, 1), 256, SMEM_MT128_SPLIT>>>(
        wt + 101376, b4, b[4], b5, 128, 36864, 1152, 128, nullptr, nullptr);

    // conv6: strided conv (192x192, str2 -> 96x96), relu epilogue -> ds, fg.
    mma_gemm_kernel<128, 0, 1, 2, 2, 128, 192, 192, 2>
        <<<dim3(72, 1, 1), 256, SMEM_MT128_SPLIT>>>(
        wt + 248832, b5, b[5], ds, 128, 9216, 1152, 128, mask, fg);

    // Contextual attention (shift algebra)
    // C = fg^T * ds : M=N=9216, K=128, TN layout, plain tf32.
    mma_gemm_kernel<128, 0, 0, 0, 0, 1, 1, 1, 1>
        <<<dim3(72, 72, 1), 256, SMEM_MT128_PLAIN>>>(
        fg, ds, nullptr, CM, 9216, 9216, 128, 9216, nullptr, nullptr);
    zero_sum_kernel<<<1, 32>>>();
    diag9_kernel<1><<<2048, 256>>>(CM, S);   // S = diag9(C), fused ||S||^2
    softmax_kernel<<<9216, 256, 9216 * sizeof(float)>>>(S);
    diag9_kernel<0><<<2048, 256>>>(S, CM);   // M = diag9(A)
    // out[x,c] = sum_u M[x,u] * ds[c,u] : NT, split tf32, split-K x4.
    mma_gemm_kernel<128, 1, 1, 0, 0, 1, 1, 1, 1>
        <<<dim3(1, 72, 4), 256, SMEM_MT128_SPLIT>>>(
        CM, ds, nullptr, Rt, 9216, 128, 9216, 9216, nullptr, nullptr);
    maskup_kernel<<<(128 * 9216 + 255) / 256, 256>>>(Rt, mask, attn);

    // conv7: C=128, 192x192, str1, K=1152
    mma_gemm_kernel<128, 0, 1, 1, 1, 128, 192, 192, 1>
        <<<dim3(288, 1, 1), 256, SMEM_MT128_SPLIT>>>(
        wt + 396288, attn, b[6], b7, 128, 36864, 1152, 128, nullptr, nullptr);

    // conv8
    mma_gemm_kernel<128, 0, 1, 1, 1, 128, 192, 192, 1>
        <<<dim3(288, 1, 1), 256, SMEM_MT128_SPLIT>>>(
        wt + 543744, b7, b[7], (float*)d_out, 128, 36864, 1152, 128, nullptr, nullptr);
}

// round 14
// speedup vs baseline: 5.1063x; 1.0504x over previous
#include <cuda_runtime.h>
#include <stdint.h>
#include <cstdint>
#include <math.h>

// ---------------------------------------------------------------------------
// Scratch (device globals -- allocation-free per harness rules)
// ---------------------------------------------------------------------------
__device__ float  g_b1[18874368];   // conv1 out 32*768*768
__device__ float  g_b2[4718592];    // conv2 out 32*384*384
__device__ float  g_b3[9437184];    // conv3 out 64*384*384
__device__ float  g_b4[4718592];    // conv4 out 128*192*192
__device__ float  g_b5[4718592];    // conv5 out
__device__ float  g_fg[1179648];    // fg = ds*mask, 128 x 9216
__device__ float  g_ds[1179648];    // ds downsampled bg, 128 x 9216
__device__ float  g_S[84934656];    // 9216 x 9216 (S, then softmaxed A in-place)
__device__ float  g_CM[84934656];   // C = fg^T ds, later M = diag9(A)
__device__ float  g_Rt[4718592];    // 4 split-K partials of 9216 x 128
__device__ float  g_attn[4718592];  // attention out 128*192*192
__device__ float  g_b7[4718592];    // conv7 out
__device__ __align__(16) float g_wt[1387520];  // frag-ordered hi/lo weight planes
__device__ double g_sumsq;          // Frobenius norm accumulator

// ---------------------------------------------------------------------------
// Helpers
// ---------------------------------------------------------------------------
__device__ __forceinline__ int refl(int i, int n) {
    if (i < 0) i = -i;
    if (i >= n) i = 2 * n - 2 - i;
    return i;
}

__device__ __forceinline__ unsigned f2tf32(float x) {
    unsigned r;
    asm("cvt.rna.tf32.f32 %0, %1;" : "=r"(r) : "f"(x));
    return r;
}

__device__ __forceinline__ void mma_tf32(float* c, const unsigned* a, unsigned b0, unsigned b1) {
    asm volatile(
        "mma.sync.aligned.m16n8k8.row.col.f32.tf32.tf32.f32 "
        "{%0,%1,%2,%3},{%4,%5,%6,%7},{%8,%9},{%0,%1,%2,%3};\n"
        : "+f"(c[0]), "+f"(c[1]), "+f"(c[2]), "+f"(c[3])
        : "r"(a[0]), "r"(a[1]), "r"(a[2]), "r"(a[3]), "r"(b0), "r"(b1));
}

__device__ __forceinline__ int rot(int r) { return r + (r >> 3); }

// A fragment-order index (smem, rot-swizzled) within a 16k x MT tile.
template <int AROWS>
__device__ __forceinline__ int a_widx(int kk, int mm) {
    int ks = kk >> 3, k = kk & 7;
    int th = k & 3, rh = (k >> 2) & 1;
    int mb = mm >> 4, rr = mm & 15, g = rr & 7, mh = (rr >> 3) & 1;
    int r = ks * AROWS + mb;
    int grp = (g * 4 + th + rot(r)) & 31;
    return r * 128 + grp * 4 + rh * 2 + mh;
}
// B fragment-order index (smem, rot-swizzled).
__device__ __forceinline__ int b_widx(int kk, int nn) {
    int ks = kk >> 3, k = kk & 7;
    int th = k & 3, rh = (k >> 2) & 1;
    int nb = nn >> 3, g = nn & 7;
    int R = ks * 16 + nb;
    int grp = (g * 4 + th + rot(R)) & 31;
    return R * 64 + grp * 2 + rh;
}

// One launch: all 8 conv weights -> fragment-ordered hi/lo tf32 planes in g_wt.
// Per conv segment: hi plane (Kp*MT words), then lo plane. No rot (global).
__global__ void transpose_all_kernel(
    const float* __restrict__ w1, const float* __restrict__ w2,
    const float* __restrict__ w3, const float* __restrict__ w4,
    const float* __restrict__ w5, const float* __restrict__ w6,
    const float* __restrict__ w7, const float* __restrict__ w8,
    float* __restrict__ wt) {
    int idx = blockIdx.x * blockDim.x + threadIdx.x;
    if (idx >= 693760) return;
    const float* w; int Kp, Kr, M, MT, l, base;
    if (idx < 2560)        { w = w1; Kp = 80;   Kr = 75;   M = 32;  MT = 32;  l = idx;          base = 0; }
    else if (idx < 11776)  { w = w2; Kp = 288;  Kr = 288;  M = 32;  MT = 32;  l = idx - 2560;   base = 5120; }
    else if (idx < 30208)  { w = w3; Kp = 288;  Kr = 288;  M = 64;  MT = 64;  l = idx - 11776;  base = 23552; }
    else if (idx < 103936) { w = w4; Kp = 576;  Kr = 576;  M = 128; MT = 128; l = idx - 30208;  base = 60416; }
    else if (idx < 251392) { w = w5; Kp = 1152; Kr = 1152; M = 128; MT = 128; l = idx - 103936; base = 207872; }
    else if (idx < 398848) { w = w6; Kp = 1152; Kr = 1152; M = 128; MT = 128; l = idx - 251392; base = 502784; }
    else if (idx < 546304) { w = w7; Kp = 1152; Kr = 1152; M = 128; MT = 128; l = idx - 398848; base = 797696; }
    else                   { w = w8; Kp = 1152; Kr = 1152; M = 128; MT = 128; l = idx - 546304; base = 1092608; }
    int k = l / MT, m = l - (l / MT) * MT;
    float a = (k < Kr && m < M) ? w[m * Kr + k] : 0.f;
    unsigned hi = f2tf32(a);
    unsigned lo = f2tf32(a - __uint_as_float(hi));
    int AROWS = MT >> 4;
    int kk = k & 15, kt = k >> 4;
    int ks = kk >> 3, kb = kk & 7, th = kb & 3, rh = (kb >> 2) & 1;
    int mb = m >> 4, rr = m & 15, g = rr & 7, mh = (rr >> 3) & 1;
    int r = ks * AROWS + mb;
    int word = r * 128 + (g * 4 + th) * 4 + rh * 2 + mh;
    int dst = base + kt * (16 * MT) + word;
    wt[dst] = __uint_as_float(hi);
    wt[dst + Kp * MT] = __uint_as_float(lo);
}

// ---------------------------------------------------------------------------
// TF32 tensor-core GEMM, double-buffered B in smem.
//   MT: M tile (32/64/128) matching OC.
//   LAYOUT 0 (TN): A: K x M, B: K x N.  LAYOUT 1 (NT): A: M x K, B: N x K.
//   SPLIT: hi/lo tf32 decomposition. ACT: 0 none, 1 elu, 2 relu (+bias).
//   MODE: 0 plain B; 1 implicit KSxKS reflect-pad conv gather; 2 strided conv
//         with dual ds/fg epilogue.
//   AGLOBAL 1: A is pre-converted fragment-ordered hi/lo planes in global
//              (weights) -- loaded directly via LDG.128, no smem round trip.
//   Split-K via gridDim.z (partials at C + z*M*N).
// ---------------------------------------------------------------------------
template <int MT, int LAYOUT, int SPLIT, int ACT, int MODE, int AGLOBAL,
          int KS, int PAD, int CC, int HH, int WW, int STR>
__global__ __launch_bounds__(256, AGLOBAL ? 2 : 1) void mma_gemm_kernel(
    const float* __restrict__ A, const float* __restrict__ B,
    const float* __restrict__ bias, float* __restrict__ C,
    int M, int N, int K, int Mreal, int Kreal,
    const float* __restrict__ mask, float* __restrict__ out2) {
    constexpr int KSQ = KS * KS;
    constexpr int OWc = MODE ? ((WW + 2 * PAD - KS) / STR + 1) : 1;
    constexpr int AROWS = MT / 16;
    constexpr int AW = 16 * MT;        // A words per 16-k tile
    constexpr int BW = 2 * 16 * 64;    // 2048
    constexpr int PL = SPLIT ? 2 : 1;
    constexpr int ASTG = AW * PL;
    constexpr int BSTG = BW * PL;
    constexpr int NW_Y = MT / 32;
    constexpr int NW_X = 8 / NW_Y;
    constexpr int NFRAG = 16 / NW_X;
    constexpr int AF4 = 4 * MT;
    extern __shared__ unsigned dyns[];
    unsigned* Abuf = dyns;                              // only if !AGLOBAL
    unsigned* Bbuf = AGLOBAL ? dyns : (dyns + 2 * ASTG);
    __shared__ int s_off[MODE ? 128 : 1][MODE ? KSQ : 1];
    __shared__ int s_m[MODE == 2 ? 128 : 1];
    int t = threadIdx.x;
    int m0 = blockIdx.y * MT, n0 = blockIdx.x * 128;
    int lane = t & 31, warp = t >> 5;
    int wy = warp / NW_X, wx = warp % NW_X;

    int kchunk = K / (int)gridDim.z;
    int kbeg = (int)blockIdx.z * kchunk;
    float* Cz = C + (size_t)blockIdx.z * ((size_t)M * N);
    const unsigned* Ag = (const unsigned*)A;
    int aplane = K * MT;

    if (MODE) {
        if (t < 128) {
            int n = n0 + t;
            int oy = n / OWc;
            int ox = n - oy * OWc;
            int by = oy * STR, bx = ox * STR;
            int iy[KS], ix[KS];
#pragma unroll
            for (int q = 0; q < KS; q++) {
                iy[q] = refl(by + q - PAD, HH) * WW;
                ix[q] = refl(bx + q - PAD, WW);
            }
#pragma unroll
            for (int ky = 0; ky < KS; ky++)
#pragma unroll
                for (int kx = 0; kx < KS; kx++)
                    s_off[t][ky * KS + kx] = iy[ky] + ix[kx];
            if (MODE == 2) s_m[t] = by * WW + bx;
        }
        __syncthreads();
    }

    // Hoisted (kt-invariant) smem store indices.
    int wbi[2][4], wai[2][4];
#pragma unroll
    for (int i = 0; i < 2; i++) {
        int id = t + i * 256;
#pragma unroll
        for (int j = 0; j < 4; j++) {
            int kk, ccb;
            if (LAYOUT == 0) {
                kk = id >> 5;
                ccb = MODE ? ((id & 31) + 32 * j) : ((id & 31) * 4 + j);
            } else {
                kk = (id & 3) * 4 + j;
                ccb = id >> 2;
            }
            wbi[i][j] = b_widx(kk, ccb);
            if (!AGLOBAL) {
                int kka, cca;
                if (LAYOUT == 0) { kka = id / (MT / 4); cca = (id % (MT / 4)) * 4 + j; }
                else             { kka = (id & 3) * 4 + j; cca = id >> 2; }
                wai[i][j] = a_widx<AROWS>(kka, cca);
            }
        }
    }

    float acc[2][NFRAG][4];
#pragma unroll
    for (int mi = 0; mi < 2; mi++)
#pragma unroll
        for (int ni = 0; ni < NFRAG; ni++)
#pragma unroll
            for (int r = 0; r < 4; r++) acc[mi][ni][r] = 0.f;

    float4 pa[2], pb[2];

    auto load_tile = [&](int k0) {
#pragma unroll
        for (int i = 0; i < 2; i++) {
            int id = t + i * 256;
            if (LAYOUT == 0) {
                if (!AGLOBAL && id < AF4) {
                    int kk = id / (MT / 4), cg = id % (MT / 4);
                    pa[i] = *(const float4*)&A[(size_t)(k0 + kk) * M + m0 + cg * 4];
                }
                int kk = id >> 5, cg = id & 31;
                if (MODE) {
                    int k = k0 + kk;
                    float v[4] = {0.f, 0.f, 0.f, 0.f};
                    if (k < Kreal) {
                        int c = k / KSQ;
                        int r9 = k - c * KSQ;
                        const float* Bp = B + (size_t)c * (HH * WW);
#pragma unroll
                        for (int j = 0; j < 4; j++) {
                            int nn = cg + 32 * j;  // lane-coalesced gather mapping
                            v[j] = Bp[s_off[nn][r9]];
                        }
                    }
                    pb[i] = {v[0], v[1], v[2], v[3]};
                } else {
                    pb[i] = *(const float4*)&B[(size_t)(k0 + kk) * N + n0 + cg * 4];
                }
            } else {
                int mm = id >> 2, kg = id & 3;
                pa[i] = *(const float4*)&A[(size_t)(m0 + mm) * K + k0 + kg * 4];
                pb[i] = *(const float4*)&B[(size_t)(n0 + mm) * K + k0 + kg * 4];
            }
        }
    };

    auto store_frag = [&](int stg) {
        unsigned* Bs = Bbuf + stg * BSTG;
#pragma unroll
        for (int i = 0; i < 2; i++) {
            int id = t + i * 256;
            const float* vb = (const float*)&pb[i];
            if (!AGLOBAL) {
                unsigned* As = Abuf + stg * ASTG;
                const float* va = (const float*)&pa[i];
                if (LAYOUT == 1 || id < AF4) {
#pragma unroll
                    for (int j = 0; j < 4; j++) {
                        unsigned ha = f2tf32(va[j]);
                        As[wai[i][j]] = ha;
                        if (SPLIT) As[AW + wai[i][j]] = f2tf32(va[j] - __uint_as_float(ha));
                    }
                }
            }
#pragma unroll
            for (int j = 0; j < 4; j++) {
                unsigned hb = f2tf32(vb[j]);
                Bs[wbi[i][j]] = hb;
                if (SPLIT) Bs[BW + wbi[i][j]] = f2tf32(vb[j] - __uint_as_float(hb));
            }
        }
    };

    auto do_mma = [&](int stg, int ktile) {
        const unsigned* Bs = Bbuf + stg * BSTG;
#pragma unroll
        for (int ks = 0; ks < 2; ks++) {
            unsigned ah[2][4], al[2][4];
#pragma unroll
            for (int mi = 0; mi < 2; mi++) {
                int r = ks * AROWS + wy * 2 + mi;
                if (AGLOBAL) {
                    int off = ktile * AW + r * 128 + lane * 4;
                    *(uint4*)ah[mi] = *(const uint4*)&Ag[off];
                    if (SPLIT) *(uint4*)al[mi] = *(const uint4*)&Ag[aplane + off];
                } else {
                    const unsigned* As = Abuf + stg * ASTG;
                    int off = r * 128 + ((lane + rot(r)) & 31) * 4;
                    *(uint4*)ah[mi] = *(const uint4*)&As[off];
                    if (SPLIT) *(uint4*)al[mi] = *(const uint4*)&As[AW + off];
                }
            }
#pragma unroll
            for (int ni = 0; ni < NFRAG; ni++) {
                int R = ks * 16 + wx * NFRAG + ni;
                int off = R * 64 + ((lane + rot(R)) & 31) * 2;
                unsigned bh[2];
                *(uint2*)bh = *(const uint2*)&Bs[off];
#pragma unroll
                for (int mi = 0; mi < 2; mi++) mma_tf32(acc[mi][ni], ah[mi], bh[0], bh[1]);
                if (SPLIT) {
                    unsigned bl[2];
                    *(uint2*)bl = *(const uint2*)&Bs[BW + off];
#pragma unroll
                    for (int mi = 0; mi < 2; mi++) {
                        mma_tf32(acc[mi][ni], al[mi], bh[0], bh[1]);
                        mma_tf32(acc[mi][ni], ah[mi], bl[0], bl[1]);
                    }
                }
            }
        }
    };

    // Pipelined mainloop: one sync per K-tile; global B load issued 2 tiles ahead.
    int nk = kchunk >> 4;
    int kt0 = kbeg >> 4;
    load_tile(kbeg);
    store_frag(0);
    __syncthreads();
    if (nk > 1) load_tile(kbeg + 16);
    for (int kt = 0; kt < nk; kt++) {
        do_mma(kt & 1, kt0 + kt);
        if (kt + 1 < nk) {
            store_frag((kt + 1) & 1);
            if (kt + 2 < nk) load_tile(kbeg + ((kt + 2) << 4));
            __syncthreads();
        }
    }

    int g = lane >> 2, th = lane & 3;
    int mbase = wy * 32, nbase = wx * (NFRAG * 8);
#pragma unroll
    for (int mi = 0; mi < 2; mi++) {
        int gm0 = m0 + mbase + mi * 16 + g;
        float bv0 = 0.f, bv1 = 0.f;
        if (ACT) {
            if (gm0 < Mreal)     bv0 = bias[gm0];
            if (gm0 + 8 < Mreal) bv1 = bias[gm0 + 8];
        }
#pragma unroll
        for (int ni = 0; ni < NFRAG; ni++) {
            int gn = n0 + nbase + ni * 8 + 2 * th;
            float2 v0 = {acc[mi][ni][0], acc[mi][ni][1]};
            float2 v1 = {acc[mi][ni][2], acc[mi][ni][3]};
            if (MODE == 2) {
                v0.x = fmaxf(v0.x + bv0, 0.f); v0.y = fmaxf(v0.y + bv0, 0.f);
                v1.x = fmaxf(v1.x + bv1, 0.f); v1.y = fmaxf(v1.y + bv1, 0.f);
                int l = gn - n0;
                float ma = mask[s_m[l]], mb = mask[s_m[l + 1]];
                *(float2*)&Cz[(size_t)gm0 * N + gn] = v0;
                *(float2*)&Cz[(size_t)(gm0 + 8) * N + gn] = v1;
                float2 f0 = {v0.x * ma, v0.y * mb};
                float2 f1 = {v1.x * ma, v1.y * mb};
                *(float2*)&out2[(size_t)gm0 * N + gn] = f0;
                *(float2*)&out2[(size_t)(gm0 + 8) * N + gn] = f1;
            } else if (ACT) {
                v0.x += bv0; v0.y += bv0;
                v1.x += bv1; v1.y += bv1;
                if (ACT == 1) {
                    v0.x = v0.x > 0.f ? v0.x : expm1f(v0.x);
                    v0.y = v0.y > 0.f ? v0.y : expm1f(v0.y);
                    v1.x = v1.x > 0.f ? v1.x : expm1f(v1.x);
                    v1.y = v1.y > 0.f ? v1.y : expm1f(v1.y);
                } else {
                    v0.x = fmaxf(v0.x, 0.f); v0.y = fmaxf(v0.y, 0.f);
                    v1.x = fmaxf(v1.x, 0.f); v1.y = fmaxf(v1.y, 0.f);
                }
                if (gm0 < Mreal)     *(float2*)&Cz[(size_t)gm0 * N + gn] = v0;
                if (gm0 + 8 < Mreal) *(float2*)&Cz[(size_t)(gm0 + 8) * N + gn] = v1;
            } else {
                *(float2*)&Cz[(size_t)gm0 * N + gn] = v0;
                *(float2*)&Cz[(size_t)(gm0 + 8) * N + gn] = v1;
            }
        }
    }
}

// ---------------------------------------------------------------------------
// Attention helpers (shift-algebra form)
// ---------------------------------------------------------------------------
template <int SUMSQ>
__global__ void diag9_kernel(const float* __restrict__ In, float* __restrict__ Out) {
    unsigned stride = gridDim.x * blockDim.x;
    float ssq = 0.f;
    for (unsigned ii = blockIdx.x * blockDim.x + threadIdx.x; ii < 84934656u; ii += stride) {
        unsigned a = ii / 9216u, b = ii - a * 9216u;
        int ay = a / 96, ax = (int)a - ay * 96;
        int by = b / 96, bx = (int)b - by * 96;
        float s = 0.f;
#pragma unroll
        for (int dy = -1; dy <= 1; dy++) {
            if ((unsigned)(ay + dy) >= 96u || (unsigned)(by + dy) >= 96u) continue;
#pragma unroll
            for (int dx = -1; dx <= 1; dx++) {
                if ((unsigned)(ax + dx) >= 96u || (unsigned)(bx + dx) >= 96u) continue;
                s += In[(int)ii + (dy * 96 + dx) * 9217];
            }
        }
        Out[ii] = s;
        if (SUMSQ) ssq += s * s;
    }
    if (SUMSQ) {
        for (int o = 16; o; o >>= 1) ssq += __shfl_down_sync(0xffffffffu, ssq, o);
        __shared__ float red[8];
        int lane = threadIdx.x & 31, w = threadIdx.x >> 5;
        if (lane == 0) red[w] = ssq;
        __syncthreads();
        if (threadIdx.x < 32) {
            float v = (threadIdx.x < 8) ? red[threadIdx.x] : 0.f;
            for (int o = 4; o; o >>= 1) v += __shfl_down_sync(0xffffffffu, v, o);
            if (threadIdx.x == 0) atomicAdd(&g_sumsq, (double)v);
        }
    }
}

__global__ void zero_sum_kernel() {
    if (threadIdx.x == 0 && blockIdx.x == 0) g_sumsq = 0.0;
}

// One block per row p: A[p,:] = softmax(scale * S[p,:]), scale = 10/nrm. In-place.
__global__ void softmax_kernel(float* __restrict__ S) {
    extern __shared__ float row[];
    __shared__ float red[8];
    __shared__ float bval;
    int p = blockIdx.x;
    float* Sr = S + (size_t)p * 9216;
    float nrm = fmaxf(sqrtf((float)g_sumsq), 1e-12f);
    float scale = 10.f / nrm;
    int t = threadIdx.x;
    int lane = t & 31, w = t >> 5;

    float lm = -INFINITY;
    for (int i = t; i < 9216; i += 256) {
        float v = Sr[i] * scale;
        row[i] = v;
        lm = fmaxf(lm, v);
    }
    for (int o = 16; o; o >>= 1) lm = fmaxf(lm, __shfl_xor_sync(0xffffffffu, lm, o));
    if (lane == 0) red[w] = lm;
    __syncthreads();
    if (t < 32) {
        float v = (t < 8) ? red[t] : -INFINITY;
        for (int o = 4; o; o >>= 1) v = fmaxf(v, __shfl_xor_sync(0xffffffffu, v, o));
        if (t == 0) bval = v;
    }
    __syncthreads();
    float mx = bval;

    float ls = 0.f;
    for (int i = t; i < 9216; i += 256) {
        float e = __expf(row[i] - mx);
        row[i] = e;
        ls += e;
    }
    for (int o = 16; o; o >>= 1) ls += __shfl_xor_sync(0xffffffffu, ls, o);
    __syncthreads();
    if (lane == 0) red[w] = ls;
    __syncthreads();
    if (t < 32) {
        float v = (t < 8) ? red[t] : 0.f;
        for (int o = 4; o; o >>= 1) v += __shfl_down_sync(0xffffffffu, v, o);
        if (t == 0) bval = v;
    }
    __syncthreads();
    float inv = 1.f / bval;
    for (int i = t; i < 9216; i += 256) Sr[i] = row[i] * inv;
}

// attn[c, 2x] = (sum of 4 split-K partials of Rt)[x, c] * m[x], 2x upsample.
__global__ void maskup_kernel(const float* __restrict__ Rt, const float* __restrict__ mask,
                              float* __restrict__ attn) {
    int idx = blockIdx.x * blockDim.x + threadIdx.x;
    if (idx >= 128 * 9216) return;
    int c = idx / 9216, x = idx % 9216;
    int yy = x / 96, xx = x % 96;
    float s = 0.f;
#pragma unroll
    for (int p = 0; p < 4; p++)
        s += Rt[(size_t)p * 1179648 + (size_t)x * 128 + c];
    s *= mask[(2 * yy) * 192 + 2 * xx];
    size_t base = (size_t)c * 36864 + (size_t)(2 * yy) * 192 + 2 * xx;
    attn[base]       = s;
    attn[base + 1]   = s;
    attn[base + 192] = s;
    attn[base + 193] = s;
}

// ---------------------------------------------------------------------------
// Host orchestration
// ---------------------------------------------------------------------------
#define SMEM_B_SPLIT     32768   // 2 stages x 4096 words x 4B (B only, AGLOBAL)
#define SMEM_MT128_PLAIN 32768   // A+B, plain (C GEMM)
#define SMEM_MT128_SPLIT 65536   // A+B, split (R GEMM)

extern "C" void kernel_launch(void* const* d_in, const int* in_sizes, int n_in,
                              void* d_out, int out_size) {
    const float* x    = (const float*)d_in[0];
    const float* mask = (const float*)d_in[1];
    const float* w[8];
    const float* b[8];
    for (int i = 0; i < 8; i++) {
        w[i] = (const float*)d_in[2 + 2 * i];
        b[i] = (const float*)d_in[3 + 2 * i];
    }

    float *b1, *b2, *b3, *b4, *b5, *fg, *ds, *S, *CM, *Rt, *attn, *b7, *wt;
    cudaGetSymbolAddress((void**)&b1,   g_b1);
    cudaGetSymbolAddress((void**)&b2,   g_b2);
    cudaGetSymbolAddress((void**)&b3,   g_b3);
    cudaGetSymbolAddress((void**)&b4,   g_b4);
    cudaGetSymbolAddress((void**)&b5,   g_b5);
    cudaGetSymbolAddress((void**)&fg,   g_fg);
    cudaGetSymbolAddress((void**)&ds,   g_ds);
    cudaGetSymbolAddress((void**)&S,    g_S);
    cudaGetSymbolAddress((void**)&CM,   g_CM);
    cudaGetSymbolAddress((void**)&Rt,   g_Rt);
    cudaGetSymbolAddress((void**)&attn, g_attn);
    cudaGetSymbolAddress((void**)&b7,   g_b7);
    cudaGetSymbolAddress((void**)&wt,   g_wt);

    cudaFuncSetAttribute(mma_gemm_kernel<128, 1, 1, 0, 0, 0, 3, 1, 1, 1, 1, 1>,
                         cudaFuncAttributeMaxDynamicSharedMemorySize, SMEM_MT128_SPLIT);

    // All weights -> fragment-ordered hi/lo planes, one launch.
    transpose_all_kernel<<<(693760 + 255) / 256, 256>>>(
        w[0], w[1], w[2], w[3], w[4], w[5], w[6], w[7], wt);

    // conv1: C=3, 768x768, 5x5, pad2, str1, K=80 (75 real), OC=32, MT=32
    mma_gemm_kernel<32, 0, 1, 1, 1, 1, 5, 2, 3, 768, 768, 1>
        <<<dim3(4608, 1, 1), 256, SMEM_B_SPLIT>>>(
        wt + 0, x, b[0], b1, 32, 589824, 80, 32, 75, nullptr, nullptr);

    // conv2: C=32, 768x768, str2 -> 384x384, K=288, OC=32, MT=32
    mma_gemm_kernel<32, 0, 1, 1, 1, 1, 3, 1, 32, 768, 768, 2>
        <<<dim3(1152, 1, 1), 256, SMEM_B_SPLIT>>>(
        wt + 5120, b1, b[1], b2, 32, 147456, 288, 32, 288, nullptr, nullptr);

    // conv3: C=32, 384x384, str1, K=288, OC=64, MT=64
    mma_gemm_kernel<64, 0, 1, 1, 1, 1, 3, 1, 32, 384, 384, 1>
        <<<dim3(1152, 1, 1), 256, SMEM_B_SPLIT>>>(
        wt + 23552, b2, b[2], b3, 64, 147456, 288, 64, 288, nullptr, nullptr);

    // conv4: C=64, 384x384, str2 -> 192x192, K=576, OC=128
    mma_gemm_kernel<128, 0, 1, 1, 1, 1, 3, 1, 64, 384, 384, 2>
        <<<dim3(288, 1, 1), 256, SMEM_B_SPLIT>>>(
        wt + 60416, b3, b[3], b4, 128, 36864, 576, 128, 576, nullptr, nullptr);

    // conv5: C=128, 192x192, str1, K=1152
    mma_gemm_kernel<128, 0, 1, 1, 1, 1, 3, 1, 128, 192, 192, 1>
        <<<dim3(288, 1, 1), 256, SMEM_B_SPLIT>>>(
        wt + 207872, b4, b[4], b5, 128, 36864, 1152, 128, 1152, nullptr, nullptr);

    // conv6: strided conv (192x192, str2 -> 96x96), relu epilogue -> ds, fg.
    mma_gemm_kernel<128, 0, 1, 2, 2, 1, 3, 1, 128, 192, 192, 2>
        <<<dim3(72, 1, 1), 256, SMEM_B_SPLIT>>>(
        wt + 502784, b5, b[5], ds, 128, 9216, 1152, 128, 1152, mask, fg);

    // Contextual attention (shift algebra)
    // C = fg^T * ds : M=N=9216, K=128, TN layout, plain tf32 (A via smem).
    mma_gemm_kernel<128, 0, 0, 0, 0, 0, 3, 1, 1, 1, 1, 1>
        <<<dim3(72, 72, 1), 256, SMEM_MT128_PLAIN>>>(
        fg, ds, nullptr, CM, 9216, 9216, 128, 9216, 128, nullptr, nullptr);
    zero_sum_kernel<<<1, 32>>>();
    diag9_kernel<1><<<2048, 256>>>(CM, S);   // S = diag9(C), fused ||S||^2
    softmax_kernel<<<9216, 256, 9216 * sizeof(float)>>>(S);
    diag9_kernel<0><<<2048, 256>>>(S, CM);   // M = diag9(A)
    // out[x,c] = sum_u M[x,u] * ds[c,u] : NT, split tf32, split-K x4.
    mma_gemm_kernel<128, 1, 1, 0, 0, 0, 3, 1, 1, 1, 1, 1>
        <<<dim3(1, 72, 4), 256, SMEM_MT128_SPLIT>>>(
        CM, ds, nullptr, Rt, 9216, 128, 9216, 9216, 9216, nullptr, nullptr);
    maskup_kernel<<<(128 * 9216 + 255) / 256, 256>>>(Rt, mask, attn);

    // conv7: C=128, 192x192, str1, K=1152
    mma_gemm_kernel<128, 0, 1, 1, 1, 1, 3, 1, 128, 192, 192, 1>
        <<<dim3(288, 1, 1), 256, SMEM_B_SPLIT>>>(
        wt + 797696, attn, b[6], b7, 128, 36864, 1152, 128, 1152, nullptr, nullptr);

    // conv8
    mma_gemm_kernel<128, 0, 1, 1, 1, 1, 3, 1, 128, 192, 192, 1>
        <<<dim3(288, 1, 1), 256, SMEM_B_SPLIT>>>(
        wt + 1092608, b7, b[7], (float*)d_out, 128, 36864, 1152, 128, 1152, nullptr, nullptr);
}

// round 15
// speedup vs baseline: 5.1081x; 1.0004x over previous
#include <cuda_runtime.h>
#include <stdint.h>
#include <cstdint>
#include <math.h>

// ---------------------------------------------------------------------------
// Scratch (device globals -- allocation-free per harness rules)
// ---------------------------------------------------------------------------
__device__ float  g_b1[18874368];   // conv1 out 32*768*768
__device__ float  g_b2[4718592];    // conv2 out 32*384*384
__device__ float  g_b3[9437184];    // conv3 out 64*384*384
__device__ float  g_b4[4718592];    // conv4 out 128*192*192
__device__ float  g_b5[4718592];    // conv5 out
__device__ float  g_fg[1179648];    // fg = ds*mask, 128 x 9216
__device__ float  g_ds[1179648];    // ds downsampled bg, 128 x 9216
__device__ float  g_S[84934656];    // 9216 x 9216 (S, then softmaxed A in-place)
__device__ float  g_CM[84934656];   // C = fg^T ds, later M = diag9(A)
__device__ float  g_Rt[4718592];    // 4 split-K partials of 9216 x 128
__device__ float  g_attn[4718592];  // attention out 128*192*192
__device__ float  g_b7[4718592];    // conv7 out
__device__ __align__(16) float g_wt[1387520];  // frag-ordered hi/lo weight planes
__device__ double g_sumsq;          // Frobenius norm accumulator

// ---------------------------------------------------------------------------
// Helpers
// ---------------------------------------------------------------------------
__device__ __forceinline__ int refl(int i, int n) {
    if (i < 0) i = -i;
    if (i >= n) i = 2 * n - 2 - i;
    return i;
}

__device__ __forceinline__ unsigned f2tf32(float x) {
    unsigned r;
    asm("cvt.rna.tf32.f32 %0, %1;" : "=r"(r) : "f"(x));
    return r;
}

__device__ __forceinline__ void mma_tf32(float* c, const unsigned* a, unsigned b0, unsigned b1) {
    asm volatile(
        "mma.sync.aligned.m16n8k8.row.col.f32.tf32.tf32.f32 "
        "{%0,%1,%2,%3},{%4,%5,%6,%7},{%8,%9},{%0,%1,%2,%3};\n"
        : "+f"(c[0]), "+f"(c[1]), "+f"(c[2]), "+f"(c[3])
        : "r"(a[0]), "r"(a[1]), "r"(a[2]), "r"(a[3]), "r"(b0), "r"(b1));
}

__device__ __forceinline__ unsigned smem_u32(const void* p) {
    unsigned r;
    asm("{ .reg .u64 t; cvta.to.shared.u64 t, %1; cvt.u32.u64 %0, t; }"
        : "=r"(r) : "l"(p));
    return r;
}
__device__ __forceinline__ void cp_async16(unsigned sa, const void* g) {
    asm volatile("cp.async.ca.shared.global [%0], [%1], 16;\n" :: "r"(sa), "l"(g));
}
__device__ __forceinline__ void cp_async8(unsigned sa, const void* g) {
    asm volatile("cp.async.ca.shared.global [%0], [%1], 8;\n" :: "r"(sa), "l"(g));
}
#define CP_COMMIT() asm volatile("cp.async.commit_group;\n" ::: "memory")
#define CP_WAIT1()  asm volatile("cp.async.wait_group 1;\n" ::: "memory")

__device__ __forceinline__ int rot(int r) { return r + (r >> 3); }

// A fragment-order index (smem path, rot-swizzled) within a 16k x MT tile.
template <int AROWS>
__device__ __forceinline__ int a_widx(int kk, int mm) {
    int ks = kk >> 3, k = kk & 7;
    int th = k & 3, rh = (k >> 2) & 1;
    int mb = mm >> 4, rr = mm & 15, g = rr & 7, mh = (rr >> 3) & 1;
    int r = ks * AROWS + mb;
    int grp = (g * 4 + th + rot(r)) & 31;
    return r * 128 + grp * 4 + rh * 2 + mh;
}
// B fragment-order index (smem, rot-swizzled).
__device__ __forceinline__ int b_widx(int kk, int nn) {
    int ks = kk >> 3, k = kk & 7;
    int th = k & 3, rh = (k >> 2) & 1;
    int nb = nn >> 3, g = nn & 7;
    int R = ks * 16 + nb;
    int grp = (g * 4 + th + rot(R)) & 31;
    return R * 64 + grp * 2 + rh;
}

// One launch: all 8 conv weights -> fragment-ordered hi/lo tf32 planes in g_wt.
// Per conv segment: hi plane (Kp*MT words), then lo plane. No rot (linear order).
__global__ void transpose_all_kernel(
    const float* __restrict__ w1, const float* __restrict__ w2,
    const float* __restrict__ w3, const float* __restrict__ w4,
    const float* __restrict__ w5, const float* __restrict__ w6,
    const float* __restrict__ w7, const float* __restrict__ w8,
    float* __restrict__ wt) {
    int idx = blockIdx.x * blockDim.x + threadIdx.x;
    if (idx >= 693760) return;
    const float* w; int Kp, Kr, M, MT, l, base;
    if (idx < 2560)        { w = w1; Kp = 80;   Kr = 75;   M = 32;  MT = 32;  l = idx;          base = 0; }
    else if (idx < 11776)  { w = w2; Kp = 288;  Kr = 288;  M = 32;  MT = 32;  l = idx - 2560;   base = 5120; }
    else if (idx < 30208)  { w = w3; Kp = 288;  Kr = 288;  M = 64;  MT = 64;  l = idx - 11776;  base = 23552; }
    else if (idx < 103936) { w = w4; Kp = 576;  Kr = 576;  M = 128; MT = 128; l = idx - 30208;  base = 60416; }
    else if (idx < 251392) { w = w5; Kp = 1152; Kr = 1152; M = 128; MT = 128; l = idx - 103936; base = 207872; }
    else if (idx < 398848) { w = w6; Kp = 1152; Kr = 1152; M = 128; MT = 128; l = idx - 251392; base = 502784; }
    else if (idx < 546304) { w = w7; Kp = 1152; Kr = 1152; M = 128; MT = 128; l = idx - 398848; base = 797696; }
    else                   { w = w8; Kp = 1152; Kr = 1152; M = 128; MT = 128; l = idx - 546304; base = 1092608; }
    int k = l / MT, m = l - (l / MT) * MT;
    float a = (k < Kr && m < M) ? w[m * Kr + k] : 0.f;
    unsigned hi = f2tf32(a);
    unsigned lo = f2tf32(a - __uint_as_float(hi));
    int AROWS = MT >> 4;
    int kk = k & 15, kt = k >> 4;
    int ks = kk >> 3, kb = kk & 7, th = kb & 3, rh = (kb >> 2) & 1;
    int mb = m >> 4, rr = m & 15, g = rr & 7, mh = (rr >> 3) & 1;
    int r = ks * AROWS + mb;
    int word = r * 128 + (g * 4 + th) * 4 + rh * 2 + mh;
    int dst = base + kt * (16 * MT) + word;
    wt[dst] = __uint_as_float(hi);
    wt[dst + Kp * MT] = __uint_as_float(lo);
}

// ---------------------------------------------------------------------------
// TF32 tensor-core GEMM.
//   MT: M tile (32/64/128) matching OC. BLK: min blocks/SM hint.
//   LAYOUT 0 (TN): A: K x M, B: K x N.  LAYOUT 1 (NT): A: M x K, B: N x K.
//   SPLIT: hi/lo tf32 decomposition. ACT: 0 none, 1 elu, 2 relu (+bias).
//   MODE: 0 plain B; 1 implicit KSxKS reflect-pad conv gather; 2 strided conv
//         with dual ds/fg epilogue.
//   AGLOBAL 1: A is pre-converted fragment-ordered hi/lo planes in global;
//              staged to smem via cp.async (3-stage ring, 2 tiles ahead).
//   B double-buffered in smem (register->cvt->STS path).
//   Split-K via gridDim.z (partials at C + z*M*N).
// ---------------------------------------------------------------------------
template <int MT, int LAYOUT, int SPLIT, int ACT, int MODE, int AGLOBAL,
          int KS, int PAD, int CC, int HH, int WW, int STR, int BLK>
__global__ __launch_bounds__(256, BLK) void mma_gemm_kernel(
    const float* __restrict__ A, const float* __restrict__ B,
    const float* __restrict__ bias, float* __restrict__ C,
    int M, int N, int K, int Mreal, int Kreal,
    const float* __restrict__ mask, float* __restrict__ out2) {
    constexpr int KSQ = KS * KS;
    constexpr int OWc = MODE ? ((WW + 2 * PAD - KS) / STR + 1) : 1;
    constexpr int AROWS = MT / 16;
    constexpr int AW = 16 * MT;        // A words per 16-k tile per plane
    constexpr int BW = 2 * 16 * 64;    // 2048
    constexpr int PL = SPLIT ? 2 : 1;
    constexpr int ASTG = AW * PL;
    constexpr int BSTG = BW * PL;
    constexpr int NASTG = AGLOBAL ? 3 : 2;
    constexpr int NW_Y = MT / 32;
    constexpr int NW_X = 8 / NW_Y;
    constexpr int NFRAG = 16 / NW_X;
    constexpr int AF4 = 4 * MT;
    constexpr int CPW = MT / 16;       // A words per thread per plane (cp.async)
    extern __shared__ unsigned dyns[];
    unsigned* Abuf = dyns;
    unsigned* Bbuf = dyns + NASTG * ASTG;
    __shared__ int s_off[MODE ? 128 : 1][MODE ? KSQ : 1];
    __shared__ int s_m[MODE == 2 ? 128 : 1];
    int t = threadIdx.x;
    int m0 = blockIdx.y * MT, n0 = blockIdx.x * 128;
    int lane = t & 31, warp = t >> 5;
    int wy = warp / NW_X, wx = warp % NW_X;

    int kchunk = K / (int)gridDim.z;
    int kbeg = (int)blockIdx.z * kchunk;
    float* Cz = C + (size_t)blockIdx.z * ((size_t)M * N);
    const unsigned* Ag = (const unsigned*)A;
    int aplane = K * MT;

    if (MODE) {
        if (t < 128) {
            int n = n0 + t;
            int oy = n / OWc;
            int ox = n - oy * OWc;
            int by = oy * STR, bx = ox * STR;
            int iy[KS], ix[KS];
#pragma unroll
            for (int q = 0; q < KS; q++) {
                iy[q] = refl(by + q - PAD, HH) * WW;
                ix[q] = refl(bx + q - PAD, WW);
            }
#pragma unroll
            for (int ky = 0; ky < KS; ky++)
#pragma unroll
                for (int kx = 0; kx < KS; kx++)
                    s_off[t][ky * KS + kx] = iy[ky] + ix[kx];
            if (MODE == 2) s_m[t] = by * WW + bx;
        }
        __syncthreads();
    }

    // Hoisted (kt-invariant) smem store indices.
    int wbi[2][4], wai[2][4];
#pragma unroll
    for (int i = 0; i < 2; i++) {
        int id = t + i * 256;
#pragma unroll
        for (int j = 0; j < 4; j++) {
            int kk, ccb;
            if (LAYOUT == 0) {
                kk = id >> 5;
                ccb = MODE ? ((id & 31) + 32 * j) : ((id & 31) * 4 + j);
            } else {
                kk = (id & 3) * 4 + j;
                ccb = id >> 2;
            }
            wbi[i][j] = b_widx(kk, ccb);
            if (!AGLOBAL) {
                int kka, cca;
                if (LAYOUT == 0) { kka = id / (MT / 4); cca = (id % (MT / 4)) * 4 + j; }
                else             { kka = (id & 3) * 4 + j; cca = id >> 2; }
                wai[i][j] = a_widx<AROWS>(kka, cca);
            }
        }
    }

    float acc[2][NFRAG][4];
#pragma unroll
    for (int mi = 0; mi < 2; mi++)
#pragma unroll
        for (int ni = 0; ni < NFRAG; ni++)
#pragma unroll
            for (int r = 0; r < 4; r++) acc[mi][ni][r] = 0.f;

    float4 pa[2], pb[2];
    int kt0g = kbeg >> 4;

    // cp.async staging of a pre-converted A tile into ring stage stg.
    auto stage_A = [&](int ktile, int stg) {
        unsigned* As = Abuf + stg * ASTG;
        unsigned sa = smem_u32(As);
#pragma unroll
        for (int pl = 0; pl < PL; pl++) {
            const unsigned* src = Ag + (pl ? aplane : 0)
                                + (size_t)(kt0g + ktile) * AW + t * CPW;
            unsigned dst = sa + (unsigned)(pl * AW + t * CPW) * 4u;
            if (CPW == 8) { cp_async16(dst, src); cp_async16(dst + 16, src + 4); }
            else if (CPW == 4) { cp_async16(dst, src); }
            else { cp_async8(dst, src); }
        }
    };

    auto load_tile = [&](int k0) {
#pragma unroll
        for (int i = 0; i < 2; i++) {
            int id = t + i * 256;
            if (LAYOUT == 0) {
                if (!AGLOBAL && id < AF4) {
                    int kk = id / (MT / 4), cg = id % (MT / 4);
                    pa[i] = *(const float4*)&A[(size_t)(k0 + kk) * M + m0 + cg * 4];
                }
                int kk = id >> 5, cg = id & 31;
                if (MODE) {
                    int k = k0 + kk;
                    float v[4] = {0.f, 0.f, 0.f, 0.f};
                    if (k < Kreal) {
                        int c = k / KSQ;
                        int r9 = k - c * KSQ;
                        const float* Bp = B + (size_t)c * (HH * WW);
#pragma unroll
                        for (int j = 0; j < 4; j++) {
                            int nn = cg + 32 * j;  // lane-coalesced gather mapping
                            v[j] = Bp[s_off[nn][r9]];
                        }
                    }
                    pb[i] = {v[0], v[1], v[2], v[3]};
                } else {
                    pb[i] = *(const float4*)&B[(size_t)(k0 + kk) * N + n0 + cg * 4];
                }
            } else {
                int mm = id >> 2, kg = id & 3;
                pa[i] = *(const float4*)&A[(size_t)(m0 + mm) * K + k0 + kg * 4];
                pb[i] = *(const float4*)&B[(size_t)(n0 + mm) * K + k0 + kg * 4];
            }
        }
    };

    auto store_frag = [&](int stg) {
        unsigned* Bs = Bbuf + stg * BSTG;
#pragma unroll
        for (int i = 0; i < 2; i++) {
            int id = t + i * 256;
            const float* vb = (const float*)&pb[i];
            if (!AGLOBAL) {
                unsigned* As = Abuf + stg * ASTG;
                const float* va = (const float*)&pa[i];
                if (LAYOUT == 1 || id < AF4) {
#pragma unroll
                    for (int j = 0; j < 4; j++) {
                        unsigned ha = f2tf32(va[j]);
                        As[wai[i][j]] = ha;
                        if (SPLIT) As[AW + wai[i][j]] = f2tf32(va[j] - __uint_as_float(ha));
                    }
                }
            }
#pragma unroll
            for (int j = 0; j < 4; j++) {
                unsigned hb = f2tf32(vb[j]);
                Bs[wbi[i][j]] = hb;
                if (SPLIT) Bs[BW + wbi[i][j]] = f2tf32(vb[j] - __uint_as_float(hb));
            }
        }
    };

    auto do_mma = [&](int sA, int sB) {
        const unsigned* As = Abuf + sA * ASTG;
        const unsigned* Bs = Bbuf + sB * BSTG;
#pragma unroll
        for (int ks = 0; ks < 2; ks++) {
            unsigned ah[2][4], al[2][4];
#pragma unroll
            for (int mi = 0; mi < 2; mi++) {
                int r = ks * AROWS + wy * 2 + mi;
                int off;
                if (AGLOBAL) off = r * 128 + lane * 4;            // linear order
                else         off = r * 128 + ((lane + rot(r)) & 31) * 4;
                *(uint4*)ah[mi] = *(const uint4*)&As[off];
                if (SPLIT) *(uint4*)al[mi] = *(const uint4*)&As[AW + off];
            }
#pragma unroll
            for (int ni = 0; ni < NFRAG; ni++) {
                int R = ks * 16 + wx * NFRAG + ni;
                int off = R * 64 + ((lane + rot(R)) & 31) * 2;
                unsigned bh[2];
                *(uint2*)bh = *(const uint2*)&Bs[off];
#pragma unroll
                for (int mi = 0; mi < 2; mi++) mma_tf32(acc[mi][ni], ah[mi], bh[0], bh[1]);
                if (SPLIT) {
                    unsigned bl[2];
                    *(uint2*)bl = *(const uint2*)&Bs[BW + off];
#pragma unroll
                    for (int mi = 0; mi < 2; mi++) {
                        mma_tf32(acc[mi][ni], al[mi], bh[0], bh[1]);
                        mma_tf32(acc[mi][ni], ah[mi], bl[0], bl[1]);
                    }
                }
            }
        }
    };

    int nk = kchunk >> 4;
    if (AGLOBAL) {
        // 3-stage cp.async A ring, 2-stage B. One sync per K-tile.
        stage_A(0, 0); CP_COMMIT();
        if (nk > 1) stage_A(1, 1);
        CP_COMMIT();
        load_tile(kbeg);
        store_frag(0);
        if (nk > 1) load_tile(kbeg + 16);
        CP_WAIT1();
        __syncthreads();
        int sA = 0;
        for (int kt = 0; kt < nk; kt++) {
            if (kt + 2 < nk) { int st = sA + 2; if (st >= 3) st -= 3; stage_A(kt + 2, st); }
            CP_COMMIT();
            do_mma(sA, kt & 1);
            if (kt + 1 < nk) {
                store_frag((kt + 1) & 1);
                if (kt + 2 < nk) load_tile(kbeg + ((kt + 2) << 4));
                CP_WAIT1();
                __syncthreads();
            }
            if (++sA >= 3) sA = 0;
        }
    } else {
        load_tile(kbeg);
        store_frag(0);
        __syncthreads();
        if (nk > 1) load_tile(kbeg + 16);
        for (int kt = 0; kt < nk; kt++) {
            do_mma(kt & 1, kt & 1);
            if (kt + 1 < nk) {
                store_frag((kt + 1) & 1);
                if (kt + 2 < nk) load_tile(kbeg + ((kt + 2) << 4));
                __syncthreads();
            }
        }
    }

    int g = lane >> 2, th = lane & 3;
    int mbase = wy * 32, nbase = wx * (NFRAG * 8);
#pragma unroll
    for (int mi = 0; mi < 2; mi++) {
        int gm0 = m0 + mbase + mi * 16 + g;
        float bv0 = 0.f, bv1 = 0.f;
        if (ACT) {
            if (gm0 < Mreal)     bv0 = bias[gm0];
            if (gm0 + 8 < Mreal) bv1 = bias[gm0 + 8];
        }
#pragma unroll
        for (int ni = 0; ni < NFRAG; ni++) {
            int gn = n0 + nbase + ni * 8 + 2 * th;
            float2 v0 = {acc[mi][ni][0], acc[mi][ni][1]};
            float2 v1 = {acc[mi][ni][2], acc[mi][ni][3]};
            if (MODE == 2) {
                v0.x = fmaxf(v0.x + bv0, 0.f); v0.y = fmaxf(v0.y + bv0, 0.f);
                v1.x = fmaxf(v1.x + bv1, 0.f); v1.y = fmaxf(v1.y + bv1, 0.f);
                int l = gn - n0;
                float ma = mask[s_m[l]], mb = mask[s_m[l + 1]];
                *(float2*)&Cz[(size_t)gm0 * N + gn] = v0;
                *(float2*)&Cz[(size_t)(gm0 + 8) * N + gn] = v1;
                float2 f0 = {v0.x * ma, v0.y * mb};
                float2 f1 = {v1.x * ma, v1.y * mb};
                *(float2*)&out2[(size_t)gm0 * N + gn] = f0;
                *(float2*)&out2[(size_t)(gm0 + 8) * N + gn] = f1;
            } else if (ACT) {
                v0.x += bv0; v0.y += bv0;
                v1.x += bv1; v1.y += bv1;
                if (ACT == 1) {
                    v0.x = v0.x > 0.f ? v0.x : expm1f(v0.x);
                    v0.y = v0.y > 0.f ? v0.y : expm1f(v0.y);
                    v1.x = v1.x > 0.f ? v1.x : expm1f(v1.x);
                    v1.y = v1.y > 0.f ? v1.y : expm1f(v1.y);
                } else {
                    v0.x = fmaxf(v0.x, 0.f); v0.y = fmaxf(v0.y, 0.f);
                    v1.x = fmaxf(v1.x, 0.f); v1.y = fmaxf(v1.y, 0.f);
                }
                if (gm0 < Mreal)     *(float2*)&Cz[(size_t)gm0 * N + gn] = v0;
                if (gm0 + 8 < Mreal) *(float2*)&Cz[(size_t)(gm0 + 8) * N + gn] = v1;
            } else {
                *(float2*)&Cz[(size_t)gm0 * N + gn] = v0;
                *(float2*)&Cz[(size_t)(gm0 + 8) * N + gn] = v1;
            }
        }
    }
}

// ---------------------------------------------------------------------------
// Attention helpers (shift-algebra form)
// ---------------------------------------------------------------------------
template <int SUMSQ>
__global__ void diag9_kernel(const float* __restrict__ In, float* __restrict__ Out) {
    unsigned stride = gridDim.x * blockDim.x;
    float ssq = 0.f;
    for (unsigned ii = blockIdx.x * blockDim.x + threadIdx.x; ii < 84934656u; ii += stride) {
        unsigned a = ii / 9216u, b = ii - a * 9216u;
        int ay = a / 96, ax = (int)a - ay * 96;
        int by = b / 96, bx = (int)b - by * 96;
        float s = 0.f;
#pragma unroll
        for (int dy = -1; dy <= 1; dy++) {
            if ((unsigned)(ay + dy) >= 96u || (unsigned)(by + dy) >= 96u) continue;
#pragma unroll
            for (int dx = -1; dx <= 1; dx++) {
                if ((unsigned)(ax + dx) >= 96u || (unsigned)(bx + dx) >= 96u) continue;
                s += In[(int)ii + (dy * 96 + dx) * 9217];
            }
        }
        Out[ii] = s;
        if (SUMSQ) ssq += s * s;
    }
    if (SUMSQ) {
        for (int o = 16; o; o >>= 1) ssq += __shfl_down_sync(0xffffffffu, ssq, o);
        __shared__ float red[8];
        int lane = threadIdx.x & 31, w = threadIdx.x >> 5;
        if (lane == 0) red[w] = ssq;
        __syncthreads();
        if (threadIdx.x < 32) {
            float v = (threadIdx.x < 8) ? red[threadIdx.x] : 0.f;
            for (int o = 4; o; o >>= 1) v += __shfl_down_sync(0xffffffffu, v, o);
            if (threadIdx.x == 0) atomicAdd(&g_sumsq, (double)v);
        }
    }
}

__global__ void zero_sum_kernel() {
    if (threadIdx.x == 0 && blockIdx.x == 0) g_sumsq = 0.0;
}

// One block per row p: A[p,:] = softmax(scale * S[p,:]), scale = 10/nrm. In-place.
__global__ void softmax_kernel(float* __restrict__ S) {
    extern __shared__ float row[];
    __shared__ float red[8];
    __shared__ float bval;
    int p = blockIdx.x;
    float* Sr = S + (size_t)p * 9216;
    float nrm = fmaxf(sqrtf((float)g_sumsq), 1e-12f);
    float scale = 10.f / nrm;
    int t = threadIdx.x;
    int lane = t & 31, w = t >> 5;

    float lm = -INFINITY;
    for (int i = t; i < 9216; i += 256) {
        float v = Sr[i] * scale;
        row[i] = v;
        lm = fmaxf(lm, v);
    }
    for (int o = 16; o; o >>= 1) lm = fmaxf(lm, __shfl_xor_sync(0xffffffffu, lm, o));
    if (lane == 0) red[w] = lm;
    __syncthreads();
    if (t < 32) {
        float v = (t < 8) ? red[t] : -INFINITY;
        for (int o = 4; o; o >>= 1) v = fmaxf(v, __shfl_xor_sync(0xffffffffu, v, o));
        if (t == 0) bval = v;
    }
    __syncthreads();
    float mx = bval;

    float ls = 0.f;
    for (int i = t; i < 9216; i += 256) {
        float e = __expf(row[i] - mx);
        row[i] = e;
        ls += e;
    }
    for (int o = 16; o; o >>= 1) ls += __shfl_xor_sync(0xffffffffu, ls, o);
    __syncthreads();
    if (lane == 0) red[w] = ls;
    __syncthreads();
    if (t < 32) {
        float v = (t < 8) ? red[t] : 0.f;
        for (int o = 4; o; o >>= 1) v += __shfl_down_sync(0xffffffffu, v, o);
        if (t == 0) bval = v;
    }
    __syncthreads();
    float inv = 1.f / bval;
    for (int i = t; i < 9216; i += 256) Sr[i] = row[i] * inv;
}

// attn[c, 2x] = (sum of 4 split-K partials of Rt)[x, c] * m[x], 2x upsample.
__global__ void maskup_kernel(const float* __restrict__ Rt, const float* __restrict__ mask,
                              float* __restrict__ attn) {
    int idx = blockIdx.x * blockDim.x + threadIdx.x;
    if (idx >= 128 * 9216) return;
    int c = idx / 9216, x = idx % 9216;
    int yy = x / 96, xx = x % 96;
    float s = 0.f;
#pragma unroll
    for (int p = 0; p < 4; p++)
        s += Rt[(size_t)p * 1179648 + (size_t)x * 128 + c];
    s *= mask[(2 * yy) * 192 + 2 * xx];
    size_t base = (size_t)c * 36864 + (size_t)(2 * yy) * 192 + 2 * xx;
    attn[base]       = s;
    attn[base + 1]   = s;
    attn[base + 192] = s;
    attn[base + 193] = s;
}

// ---------------------------------------------------------------------------
// Host orchestration
// ---------------------------------------------------------------------------
// Dynamic smem bytes: A ring (3 stages AGLOBAL / 2 else) + 2-stage B.
#define SMEM_CONV_MT128 81920   // 3*4096*4 + 2*4096*4
#define SMEM_CONV_MT64  57344   // 3*2048*4 + 2*4096*4
#define SMEM_CONV_MT32  45056   // 3*1024*4 + 2*4096*4
#define SMEM_C_PLAIN    32768   // 2*2048*4 + 2*2048*4
#define SMEM_R_SPLIT    65536   // 2*4096*4 + 2*4096*4

extern "C" void kernel_launch(void* const* d_in, const int* in_sizes, int n_in,
                              void* d_out, int out_size) {
    const float* x    = (const float*)d_in[0];
    const float* mask = (const float*)d_in[1];
    const float* w[8];
    const float* b[8];
    for (int i = 0; i < 8; i++) {
        w[i] = (const float*)d_in[2 + 2 * i];
        b[i] = (const float*)d_in[3 + 2 * i];
    }

    float *b1, *b2, *b3, *b4, *b5, *fg, *ds, *S, *CM, *Rt, *attn, *b7, *wt;
    cudaGetSymbolAddress((void**)&b1,   g_b1);
    cudaGetSymbolAddress((void**)&b2,   g_b2);
    cudaGetSymbolAddress((void**)&b3,   g_b3);
    cudaGetSymbolAddress((void**)&b4,   g_b4);
    cudaGetSymbolAddress((void**)&b5,   g_b5);
    cudaGetSymbolAddress((void**)&fg,   g_fg);
    cudaGetSymbolAddress((void**)&ds,   g_ds);
    cudaGetSymbolAddress((void**)&S,    g_S);
    cudaGetSymbolAddress((void**)&CM,   g_CM);
    cudaGetSymbolAddress((void**)&Rt,   g_Rt);
    cudaGetSymbolAddress((void**)&attn, g_attn);
    cudaGetSymbolAddress((void**)&b7,   g_b7);
    cudaGetSymbolAddress((void**)&wt,   g_wt);

    cudaFuncSetAttribute(mma_gemm_kernel<32, 0, 1, 1, 1, 1, 5, 2, 3, 768, 768, 1, 2>,
                         cudaFuncAttributeMaxDynamicSharedMemorySize, SMEM_CONV_MT32);
    cudaFuncSetAttribute(mma_gemm_kernel<32, 0, 1, 1, 1, 1, 3, 1, 32, 768, 768, 2, 2>,
                         cudaFuncAttributeMaxDynamicSharedMemorySize, SMEM_CONV_MT32);
    cudaFuncSetAttribute(mma_gemm_kernel<64, 0, 1, 1, 1, 1, 3, 1, 32, 384, 384, 1, 2>,
                         cudaFuncAttributeMaxDynamicSharedMemorySize, SMEM_CONV_MT64);
    cudaFuncSetAttribute(mma_gemm_kernel<128, 0, 1, 1, 1, 1, 3, 1, 64, 384, 384, 2, 2>,
                         cudaFuncAttributeMaxDynamicSharedMemorySize, SMEM_CONV_MT128);
    cudaFuncSetAttribute(mma_gemm_kernel<128, 0, 1, 1, 1, 1, 3, 1, 128, 192, 192, 1, 2>,
                         cudaFuncAttributeMaxDynamicSharedMemorySize, SMEM_CONV_MT128);
    cudaFuncSetAttribute(mma_gemm_kernel<128, 0, 1, 2, 2, 1, 3, 1, 128, 192, 192, 2, 2>,
                         cudaFuncAttributeMaxDynamicSharedMemorySize, SMEM_CONV_MT128);
    cudaFuncSetAttribute(mma_gemm_kernel<128, 1, 1, 0, 0, 0, 3, 1, 1, 1, 1, 1, 1>,
                         cudaFuncAttributeMaxDynamicSharedMemorySize, SMEM_R_SPLIT);

    // All weights -> fragment-ordered hi/lo planes, one launch.
    transpose_all_kernel<<<(693760 + 255) / 256, 256>>>(
        w[0], w[1], w[2], w[3], w[4], w[5], w[6], w[7], wt);

    // conv1: C=3, 768x768, 5x5, pad2, str1, K=80 (75 real), OC=32, MT=32
    mma_gemm_kernel<32, 0, 1, 1, 1, 1, 5, 2, 3, 768, 768, 1, 2>
        <<<dim3(4608, 1, 1), 256, SMEM_CONV_MT32>>>(
        wt + 0, x, b[0], b1, 32, 589824, 80, 32, 75, nullptr, nullptr);

    // conv2: C=32, 768x768, str2 -> 384x384, K=288, OC=32, MT=32
    mma_gemm_kernel<32, 0, 1, 1, 1, 1, 3, 1, 32, 768, 768, 2, 2>
        <<<dim3(1152, 1, 1), 256, SMEM_CONV_MT32>>>(
        wt + 5120, b1, b[1], b2, 32, 147456, 288, 32, 288, nullptr, nullptr);

    // conv3: C=32, 384x384, str1, K=288, OC=64, MT=64
    mma_gemm_kernel<64, 0, 1, 1, 1, 1, 3, 1, 32, 384, 384, 1, 2>
        <<<dim3(1152, 1, 1), 256, SMEM_CONV_MT64>>>(
        wt + 23552, b2, b[2], b3, 64, 147456, 288, 64, 288, nullptr, nullptr);

    // conv4: C=64, 384x384, str2 -> 192x192, K=576, OC=128
    mma_gemm_kernel<128, 0, 1, 1, 1, 1, 3, 1, 64, 384, 384, 2, 2>
        <<<dim3(288, 1, 1), 256, SMEM_CONV_MT128>>>(
        wt + 60416, b3, b[3], b4, 128, 36864, 576, 128, 576, nullptr, nullptr);

    // conv5: C=128, 192x192, str1, K=1152
    mma_gemm_kernel<128, 0, 1, 1, 1, 1, 3, 1, 128, 192, 192, 1, 2>
        <<<dim3(288, 1, 1), 256, SMEM_CONV_MT128>>>(
        wt + 207872, b4, b[4], b5, 128, 36864, 1152, 128, 1152, nullptr, nullptr);

    // conv6: strided conv (192x192, str2 -> 96x96), relu epilogue -> ds, fg.
    mma_gemm_kernel<128, 0, 1, 2, 2, 1, 3, 1, 128, 192, 192, 2, 2>
        <<<dim3(72, 1, 1), 256, SMEM_CONV_MT128>>>(
        wt + 502784, b5, b[5], ds, 128, 9216, 1152, 128, 1152, mask, fg);

    // Contextual attention (shift algebra)
    // C = fg^T * ds : M=N=9216, K=128, TN layout, plain tf32 (A via smem), 2 blk/SM.
    mma_gemm_kernel<128, 0, 0, 0, 0, 0, 3, 1, 1, 1, 1, 1, 2>
        <<<dim3(72, 72, 1), 256, SMEM_C_PLAIN>>>(
        fg, ds, nullptr, CM, 9216, 9216, 128, 9216, 128, nullptr, nullptr);
    zero_sum_kernel<<<1, 32>>>();
    diag9_kernel<1><<<2048, 256>>>(CM, S);   // S = diag9(C), fused ||S||^2
    softmax_kernel<<<9216, 256, 9216 * sizeof(float)>>>(S);
    diag9_kernel<0><<<2048, 256>>>(S, CM);   // M = diag9(A)
    // out[x,c] = sum_u M[x,u] * ds[c,u] : NT, split tf32, split-K x4.
    mma_gemm_kernel<128, 1, 1, 0, 0, 0, 3, 1, 1, 1, 1, 1, 1>
        <<<dim3(1, 72, 4), 256, SMEM_R_SPLIT>>>(
        CM, ds, nullptr, Rt, 9216, 128, 9216, 9216, 9216, nullptr, nullptr);
    maskup_kernel<<<(128 * 9216 + 255) / 256, 256>>>(Rt, mask, attn);

    // conv7: C=128, 192x192, str1, K=1152
    mma_gemm_kernel<128, 0, 1, 1, 1, 1, 3, 1, 128, 192, 192, 1, 2>
        <<<dim3(288, 1, 1), 256, SMEM_CONV_MT128>>>(
        wt + 797696, attn, b[6], b7, 128, 36864, 1152, 128, 1152, nullptr, nullptr);

    // conv8
    mma_gemm_kernel<128, 0, 1, 1, 1, 1, 3, 1, 128, 192, 192, 1, 2>
        <<<dim3(288, 1, 1), 256, SMEM_CONV_MT128>>>(
        wt + 1092608, b7, b[7], (float*)d_out, 128, 36864, 1152, 128, 1152, nullptr, nullptr);
}

// round 16
// speedup vs baseline: 5.8354x; 1.1424x over previous
#include <cuda_runtime.h>
#include <cuda_fp16.h>
#include <stdint.h>
#include <cstdint>
#include <math.h>

// ---------------------------------------------------------------------------
// Scratch (device globals -- allocation-free per harness rules)
// ---------------------------------------------------------------------------
__device__ float  g_b1[18874368];   // conv1 out 32*768*768
__device__ float  g_b2[4718592];    // conv2 out 32*384*384
__device__ float  g_b3[9437184];    // conv3 out 64*384*384
__device__ float  g_b4[4718592];    // conv4 out 128*192*192
__device__ float  g_b5[4718592];    // conv5 out
__device__ float  g_fg[1179648];    // fg = ds*mask, 128 x 9216
__device__ float  g_ds[1179648];    // ds downsampled bg, 128 x 9216
__device__ float  g_S[84934656];    // 9216 x 9216 (S, then softmaxed A in-place)
__device__ float  g_CM[84934656];   // C = fg^T ds, later M = diag9(A)
__device__ float  g_Rt[4718592];    // 4 split-K partials of 9216 x 128
__device__ float  g_attn[4718592];  // attention out 128*192*192
__device__ float  g_b7[4718592];    // conv7 out
__device__ __align__(16) float g_wt[693760];   // fp16 hi/lo weight frag planes
__device__ double g_sumsq;          // Frobenius norm accumulator

// ---------------------------------------------------------------------------
// Helpers
// ---------------------------------------------------------------------------
__device__ __forceinline__ int refl(int i, int n) {
    if (i < 0) i = -i;
    if (i >= n) i = 2 * n - 2 - i;
    return i;
}

__device__ __forceinline__ unsigned f2tf32(float x) {
    unsigned r;
    asm("cvt.rna.tf32.f32 %0, %1;" : "=r"(r) : "f"(x));
    return r;
}

__device__ __forceinline__ void mma_tf32(float* c, const unsigned* a, unsigned b0, unsigned b1) {
    asm volatile(
        "mma.sync.aligned.m16n8k8.row.col.f32.tf32.tf32.f32 "
        "{%0,%1,%2,%3},{%4,%5,%6,%7},{%8,%9},{%0,%1,%2,%3};\n"
        : "+f"(c[0]), "+f"(c[1]), "+f"(c[2]), "+f"(c[3])
        : "r"(a[0]), "r"(a[1]), "r"(a[2]), "r"(a[3]), "r"(b0), "r"(b1));
}

__device__ __forceinline__ void mma_fp16(float* c, const unsigned* a, unsigned b0, unsigned b1) {
    asm volatile(
        "mma.sync.aligned.m16n8k16.row.col.f32.f16.f16.f32 "
        "{%0,%1,%2,%3},{%4,%5,%6,%7},{%8,%9},{%0,%1,%2,%3};\n"
        : "+f"(c[0]), "+f"(c[1]), "+f"(c[2]), "+f"(c[3])
        : "r"(a[0]), "r"(a[1]), "r"(a[2]), "r"(a[3]), "r"(b0), "r"(b1));
}

__device__ __forceinline__ unsigned packh2(float x, float y) {
    __half2 h = __floats2half2_rn(x, y);
    return *(unsigned*)&h;
}
__device__ __forceinline__ unsigned packh2_lo(float x, float y, unsigned hi) {
    __half2 h = *(__half2*)&hi;
    return packh2(x - __low2float(h), y - __high2float(h));
}

__device__ __forceinline__ unsigned smem_u32(const void* p) {
    unsigned r;
    asm("{ .reg .u64 t; cvta.to.shared.u64 t, %1; cvt.u32.u64 %0, t; }"
        : "=r"(r) : "l"(p));
    return r;
}
__device__ __forceinline__ void cp_async16(unsigned sa, const void* g) {
    asm volatile("cp.async.ca.shared.global [%0], [%1], 16;\n" :: "r"(sa), "l"(g));
}
__device__ __forceinline__ void cp_async8(unsigned sa, const void* g) {
    asm volatile("cp.async.ca.shared.global [%0], [%1], 8;\n" :: "r"(sa), "l"(g));
}
__device__ __forceinline__ void cp_async4(unsigned sa, const void* g) {
    asm volatile("cp.async.ca.shared.global [%0], [%1], 4;\n" :: "r"(sa), "l"(g));
}
#define CP_COMMIT() asm volatile("cp.async.commit_group;\n" ::: "memory")
#define CP_WAIT1()  asm volatile("cp.async.wait_group 1;\n" ::: "memory")

__device__ __forceinline__ int rot(int r) { return r + (r >> 3); }

// tf32 fragment-order indices (for the legacy LAYOUT-1 R GEMM only).
template <int AROWS>
__device__ __forceinline__ int a_widx(int kk, int mm) {
    int ks = kk >> 3, k = kk & 7;
    int th = k & 3, rh = (k >> 2) & 1;
    int mb = mm >> 4, rr = mm & 15, g = rr & 7, mh = (rr >> 3) & 1;
    int r = ks * AROWS + mb;
    int grp = (g * 4 + th + rot(r)) & 31;
    return r * 128 + grp * 4 + rh * 2 + mh;
}
__device__ __forceinline__ int b_widx(int kk, int nn) {
    int ks = kk >> 3, k = kk & 7;
    int th = k & 3, rh = (k >> 2) & 1;
    int nb = nn >> 3, g = nn & 7;
    int R = ks * 16 + nb;
    int grp = (g * 4 + th + rot(R)) & 31;
    return R * 64 + grp * 2 + rh;
}

// ---------------------------------------------------------------------------
// Weights -> fp16 hi/lo m16n8k16-A-fragment planes (one thread per hi word).
// Segment layout (word offsets in g_wt): hi plane [base, base+Kp*MT/2),
// lo plane follows. Tile = 16k x MT: word = mb*128 + lane*4 + reg,
// reg = mh + 2*k8; halves = (k, k+1), k = kt*16 + k8*8 + th*2.
// ---------------------------------------------------------------------------
__global__ void transpose_all_kernel(
    const float* __restrict__ w1, const float* __restrict__ w2,
    const float* __restrict__ w3, const float* __restrict__ w4,
    const float* __restrict__ w5, const float* __restrict__ w6,
    const float* __restrict__ w7, const float* __restrict__ w8,
    float* __restrict__ wt) {
    int idx = blockIdx.x * blockDim.x + threadIdx.x;
    if (idx >= 346880) return;
    const float* w; int Kp, Kr, M, MT, l, baseW;
    if (idx < 1280)        { w = w1; Kp = 80;   Kr = 75;   M = 32;  MT = 32;  l = idx;          baseW = 0; }
    else if (idx < 5888)   { w = w2; Kp = 288;  Kr = 288;  M = 32;  MT = 32;  l = idx - 1280;   baseW = 2560; }
    else if (idx < 15104)  { w = w3; Kp = 288;  Kr = 288;  M = 64;  MT = 64;  l = idx - 5888;   baseW = 11776; }
    else if (idx < 51968)  { w = w4; Kp = 576;  Kr = 576;  M = 128; MT = 128; l = idx - 15104;  baseW = 30208; }
    else if (idx < 125696) { w = w5; Kp = 1152; Kr = 1152; M = 128; MT = 128; l = idx - 51968;  baseW = 103936; }
    else if (idx < 199424) { w = w6; Kp = 1152; Kr = 1152; M = 128; MT = 128; l = idx - 125696; baseW = 251392; }
    else if (idx < 273152) { w = w7; Kp = 1152; Kr = 1152; M = 128; MT = 128; l = idx - 199424; baseW = 398848; }
    else                   { w = w8; Kp = 1152; Kr = 1152; M = 128; MT = 128; l = idx - 273152; baseW = 546304; }
    int AWH = 8 * MT;
    int kt = l / AWH, word = l - kt * AWH;
    int mb = word >> 7, rem = word & 127;
    int lanei = rem >> 2, reg = rem & 3;
    int g = lanei >> 2, th = lanei & 3;
    int mh = reg & 1, k8 = reg >> 1;
    int m = mb * 16 + mh * 8 + g;
    int ke = kt * 16 + k8 * 8 + th * 2;
    float v0 = (ke < Kr && m < M) ? w[m * Kr + ke] : 0.f;
    float v1 = (ke + 1 < Kr && m < M) ? w[m * Kr + ke + 1] : 0.f;
    unsigned hi = packh2(v0, v1);
    unsigned lo = packh2_lo(v0, v1, hi);
    unsigned* uw = (unsigned*)wt;
    uw[baseW + l] = hi;
    uw[baseW + Kp * MT / 2 + l] = lo;
}

// ---------------------------------------------------------------------------
// FP16 hi/lo tensor-core GEMM (m16n8k16), LAYOUT TN only.
//   MT: M tile matching OC. SPLIT: hi/lo (22-bit) vs plain (11-bit).
//   ACT/MODE as before. AGLOBAL 1: A = pre-converted fp16 frag planes in
//   global, cp.async 3-stage ring; 0: A float in global, cvt+STS 2-stage.
//   B double-buffered: k-paired half2 words (kk=2q/2q+1 thread pairing).
// ---------------------------------------------------------------------------
template <int MT, int SPLIT, int ACT, int MODE, int AGLOBAL,
          int KS, int PAD, int CC, int HH, int WW, int STR, int BLK>
__global__ __launch_bounds__(256, BLK) void mma_fp16_kernel(
    const float* __restrict__ A, const float* __restrict__ B,
    const float* __restrict__ bias, float* __restrict__ C,
    int M, int N, int K, int Mreal, int Kreal,
    const float* __restrict__ mask, float* __restrict__ out2) {
    constexpr int KSQ = KS * KS;
    constexpr int OWc = MODE ? ((WW + 2 * PAD - KS) / STR + 1) : 1;
    constexpr int AWH = 8 * MT;       // half2 words per 16-k tile per plane
    constexpr int BWH = 1024;         // 16 n-atoms * 64
    constexpr int PL = SPLIT ? 2 : 1;
    constexpr int ASTGH = AWH * PL;
    constexpr int BSTGH = BWH * PL;
    constexpr int NASTG = AGLOBAL ? 3 : 2;
    constexpr int NW_Y = MT / 32;
    constexpr int NW_X = 8 / NW_Y;
    constexpr int NFRAG = 16 / NW_X;
    constexpr int CPWH = MT / 32;     // cp.async words per thread per plane
    extern __shared__ unsigned dyns[];
    unsigned* Abuf = dyns;
    unsigned* Bbuf = dyns + NASTG * ASTGH;
    __shared__ int s_off[MODE ? 128 : 1][MODE ? KSQ : 1];
    __shared__ int s_m[MODE == 2 ? 128 : 1];
    int t = threadIdx.x;
    int m0 = blockIdx.y * MT, n0 = blockIdx.x * 128;
    int lane = t & 31, warp = t >> 5;
    int wy = warp / NW_X, wx = warp % NW_X;
    int q = t >> 5, cg = t & 31;
    int thq = q & 3, k8q = q >> 2;

    float* Cz = C;
    const unsigned* Ag = (const unsigned*)A;
    int aplaneH = K * MT / 2;

    if (MODE) {
        if (t < 128) {
            int n = n0 + t;
            int oy = n / OWc;
            int ox = n - oy * OWc;
            int by = oy * STR, bx = ox * STR;
            int iy[KS], ix[KS];
#pragma unroll
            for (int p = 0; p < KS; p++) {
                iy[p] = refl(by + p - PAD, HH) * WW;
                ix[p] = refl(bx + p - PAD, WW);
            }
#pragma unroll
            for (int ky = 0; ky < KS; ky++)
#pragma unroll
                for (int kx = 0; kx < KS; kx++)
                    s_off[t][ky * KS + kx] = iy[ky] + ix[kx];
            if (MODE == 2) s_m[t] = by * WW + bx;
        }
        __syncthreads();
    }

    // Hoisted kt-invariant smem word indices (4 per thread each side).
    int wb[4], wa[4];
#pragma unroll
    for (int j = 0; j < 4; j++) {
        int n = MODE ? (cg + 32 * j) : (cg * 4 + j);
        int nb = n >> 3, gb = n & 7;
        wb[j] = nb * 64 + ((gb * 4 + thq + rot(nb)) & 31) * 2 + k8q;
        if (!AGLOBAL) {
            int m = cg * 4 + j;
            int mb = m >> 4, sub = m & 15, ga = sub & 7, mha = sub >> 3;
            wa[j] = mb * 128 + ((ga * 4 + thq + rot(mb)) & 31) * 4 + (mha + 2 * k8q);
        }
    }

    float acc[2][NFRAG][4];
#pragma unroll
    for (int mi = 0; mi < 2; mi++)
#pragma unroll
        for (int ni = 0; ni < NFRAG; ni++)
#pragma unroll
            for (int r = 0; r < 4; r++) acc[mi][ni][r] = 0.f;

    float4 pa[2], pb[2];

    auto stage_A = [&](int ktile, int stg) {
        unsigned sa = smem_u32(Abuf + stg * ASTGH);
#pragma unroll
        for (int pl = 0; pl < PL; pl++) {
            const unsigned* src = Ag + pl * aplaneH + (size_t)ktile * AWH + t * CPWH;
            unsigned dst = sa + (unsigned)(pl * AWH + t * CPWH) * 4u;
            if (CPWH == 4) cp_async16(dst, src);
            else if (CPWH == 2) cp_async8(dst, src);
            else cp_async4(dst, src);
        }
    };

    auto load_tile = [&](int k0) {
#pragma unroll
        for (int i = 0; i < 2; i++) {
            int kk = 2 * q + i;
            if (!AGLOBAL)
                pa[i] = *(const float4*)&A[(size_t)(k0 + kk) * M + m0 + cg * 4];
            if (MODE) {
                int k = k0 + kk;
                float v[4] = {0.f, 0.f, 0.f, 0.f};
                if (k < Kreal) {
                    int c = k / KSQ;
                    int r9 = k - c * KSQ;
                    const float* Bp = B + (size_t)c * (HH * WW);
#pragma unroll
                    for (int j = 0; j < 4; j++)
                        v[j] = Bp[s_off[cg + 32 * j][r9]];
                }
                pb[i] = {v[0], v[1], v[2], v[3]};
            } else {
                pb[i] = *(const float4*)&B[(size_t)(k0 + kk) * N + n0 + cg * 4];
            }
        }
    };

    auto store_frag = [&](int stg) {
        unsigned* Bs = Bbuf + stg * BSTGH;
        const float* v0 = (const float*)&pb[0];
        const float* v1 = (const float*)&pb[1];
#pragma unroll
        for (int j = 0; j < 4; j++) {
            unsigned hi = packh2(v0[j], v1[j]);
            Bs[wb[j]] = hi;
            if (SPLIT) Bs[BWH + wb[j]] = packh2_lo(v0[j], v1[j], hi);
        }
        if (!AGLOBAL) {
            unsigned* As = Abuf + stg * ASTGH;
            const float* a0 = (const float*)&pa[0];
            const float* a1 = (const float*)&pa[1];
#pragma unroll
            for (int j = 0; j < 4; j++) {
                unsigned hi = packh2(a0[j], a1[j]);
                As[wa[j]] = hi;
                if (SPLIT) As[AWH + wa[j]] = packh2_lo(a0[j], a1[j], hi);
            }
        }
    };

    auto do_mma = [&](int sA, int sB) {
        const unsigned* As = Abuf + sA * ASTGH;
        const unsigned* Bs = Bbuf + sB * BSTGH;
        unsigned ah[2][4], al[2][4];
#pragma unroll
        for (int mi = 0; mi < 2; mi++) {
            int atom = wy * 2 + mi;
            int off = AGLOBAL ? (atom * 128 + lane * 4)
                              : (atom * 128 + ((lane + rot(atom)) & 31) * 4);
            *(uint4*)ah[mi] = *(const uint4*)&As[off];
            if (SPLIT) *(uint4*)al[mi] = *(const uint4*)&As[AWH + off];
        }
#pragma unroll
        for (int ni = 0; ni < NFRAG; ni++) {
            int nb = wx * NFRAG + ni;
            int off = nb * 64 + ((lane + rot(nb)) & 31) * 2;
            uint2 bh = *(const uint2*)&Bs[off];
#pragma unroll
            for (int mi = 0; mi < 2; mi++) mma_fp16(acc[mi][ni], ah[mi], bh.x, bh.y);
            if (SPLIT) {
                uint2 bl = *(const uint2*)&Bs[BWH + off];
#pragma unroll
                for (int mi = 0; mi < 2; mi++) {
                    mma_fp16(acc[mi][ni], al[mi], bh.x, bh.y);
                    mma_fp16(acc[mi][ni], ah[mi], bl.x, bl.y);
                }
            }
        }
    };

    int nk = K >> 4;
    if (AGLOBAL) {
        stage_A(0, 0); CP_COMMIT();
        if (nk > 1) stage_A(1, 1);
        CP_COMMIT();
        load_tile(0);
        store_frag(0);
        if (nk > 1) load_tile(16);
        CP_WAIT1();
        __syncthreads();
        int sA = 0;
        for (int kt = 0; kt < nk; kt++) {
            if (kt + 2 < nk) { int st = sA + 2; if (st >= 3) st -= 3; stage_A(kt + 2, st); }
            CP_COMMIT();
            do_mma(sA, kt & 1);
            if (kt + 1 < nk) {
                store_frag((kt + 1) & 1);
                if (kt + 2 < nk) load_tile((kt + 2) << 4);
                CP_WAIT1();
                __syncthreads();
            }
            if (++sA >= 3) sA = 0;
        }
    } else {
        load_tile(0);
        store_frag(0);
        __syncthreads();
        if (nk > 1) load_tile(16);
        for (int kt = 0; kt < nk; kt++) {
            do_mma(kt & 1, kt & 1);
            if (kt + 1 < nk) {
                store_frag((kt + 1) & 1);
                if (kt + 2 < nk) load_tile((kt + 2) << 4);
                __syncthreads();
            }
        }
    }

    int g = lane >> 2, th = lane & 3;
    int mbase = wy * 32, nbase = wx * (NFRAG * 8);
#pragma unroll
    for (int mi = 0; mi < 2; mi++) {
        int gm0 = m0 + mbase + mi * 16 + g;
        float bv0 = 0.f, bv1 = 0.f;
        if (ACT) {
            if (gm0 < Mreal)     bv0 = bias[gm0];
            if (gm0 + 8 < Mreal) bv1 = bias[gm0 + 8];
        }
#pragma unroll
        for (int ni = 0; ni < NFRAG; ni++) {
            int gn = n0 + nbase + ni * 8 + 2 * th;
            float2 v0 = {acc[mi][ni][0], acc[mi][ni][1]};
            float2 v1 = {acc[mi][ni][2], acc[mi][ni][3]};
            if (MODE == 2) {
                v0.x = fmaxf(v0.x + bv0, 0.f); v0.y = fmaxf(v0.y + bv0, 0.f);
                v1.x = fmaxf(v1.x + bv1, 0.f); v1.y = fmaxf(v1.y + bv1, 0.f);
                int l = gn - n0;
                float ma = mask[s_m[l]], mb = mask[s_m[l + 1]];
                *(float2*)&Cz[(size_t)gm0 * N + gn] = v0;
                *(float2*)&Cz[(size_t)(gm0 + 8) * N + gn] = v1;
                float2 f0 = {v0.x * ma, v0.y * mb};
                float2 f1 = {v1.x * ma, v1.y * mb};
                *(float2*)&out2[(size_t)gm0 * N + gn] = f0;
                *(float2*)&out2[(size_t)(gm0 + 8) * N + gn] = f1;
            } else if (ACT) {
                v0.x += bv0; v0.y += bv0;
                v1.x += bv1; v1.y += bv1;
                if (ACT == 1) {
                    v0.x = v0.x > 0.f ? v0.x : expm1f(v0.x);
                    v0.y = v0.y > 0.f ? v0.y : expm1f(v0.y);
                    v1.x = v1.x > 0.f ? v1.x : expm1f(v1.x);
                    v1.y = v1.y > 0.f ? v1.y : expm1f(v1.y);
                } else {
                    v0.x = fmaxf(v0.x, 0.f); v0.y = fmaxf(v0.y, 0.f);
                    v1.x = fmaxf(v1.x, 0.f); v1.y = fmaxf(v1.y, 0.f);
                }
                if (gm0 < Mreal)     *(float2*)&Cz[(size_t)gm0 * N + gn] = v0;
                if (gm0 + 8 < Mreal) *(float2*)&Cz[(size_t)(gm0 + 8) * N + gn] = v1;
            } else {
                *(float2*)&Cz[(size_t)gm0 * N + gn] = v0;
                *(float2*)&Cz[(size_t)(gm0 + 8) * N + gn] = v1;
            }
        }
    }
}

// ---------------------------------------------------------------------------
// Legacy tf32 GEMM (LAYOUT 1 / NT only -- the attention R GEMM, split tf32).
// ---------------------------------------------------------------------------
template <int MT, int LAYOUT, int SPLIT, int BLK>
__global__ __launch_bounds__(256, BLK) void mma_tf32_nt_kernel(
    const float* __restrict__ A, const float* __restrict__ B,
    float* __restrict__ C, int M, int N, int K) {
    constexpr int AROWS = MT / 16;
    constexpr int AW = 16 * MT;
    constexpr int BW = 2 * 16 * 64;
    constexpr int PL = SPLIT ? 2 : 1;
    constexpr int ASTG = AW * PL;
    constexpr int BSTG = BW * PL;
    constexpr int NW_X = 2;
    constexpr int NFRAG = 8;
    extern __shared__ unsigned dyns[];
    unsigned* Abuf = dyns;
    unsigned* Bbuf = dyns + 2 * ASTG;
    int t = threadIdx.x;
    int m0 = blockIdx.y * MT, n0 = blockIdx.x * 128;
    int lane = t & 31, warp = t >> 5;
    int wy = warp / NW_X, wx = warp % NW_X;

    int kchunk = K / (int)gridDim.z;
    int kbeg = (int)blockIdx.z * kchunk;
    float* Cz = C + (size_t)blockIdx.z * ((size_t)M * N);

    int wbi[2][4], wai[2][4];
#pragma unroll
    for (int i = 0; i < 2; i++) {
        int id = t + i * 256;
#pragma unroll
        for (int j = 0; j < 4; j++) {
            int kk = (id & 3) * 4 + j;
            wbi[i][j] = b_widx(kk, id >> 2);
            wai[i][j] = a_widx<AROWS>(kk, id >> 2);
        }
    }

    float acc[2][NFRAG][4];
#pragma unroll
    for (int mi = 0; mi < 2; mi++)
#pragma unroll
        for (int ni = 0; ni < NFRAG; ni++)
#pragma unroll
            for (int r = 0; r < 4; r++) acc[mi][ni][r] = 0.f;

    float4 pa[2], pb[2];

    auto load_tile = [&](int k0) {
#pragma unroll
        for (int i = 0; i < 2; i++) {
            int id = t + i * 256;
            int mm = id >> 2, kg = id & 3;
            pa[i] = *(const float4*)&A[(size_t)(m0 + mm) * K + k0 + kg * 4];
            pb[i] = *(const float4*)&B[(size_t)(n0 + mm) * K + k0 + kg * 4];
        }
    };
    auto store_frag = [&](int stg) {
        unsigned* As = Abuf + stg * ASTG;
        unsigned* Bs = Bbuf + stg * BSTG;
#pragma unroll
        for (int i = 0; i < 2; i++) {
            const float* va = (const float*)&pa[i];
            const float* vb = (const float*)&pb[i];
#pragma unroll
            for (int j = 0; j < 4; j++) {
                unsigned ha = f2tf32(va[j]);
                As[wai[i][j]] = ha;
                if (SPLIT) As[AW + wai[i][j]] = f2tf32(va[j] - __uint_as_float(ha));
                unsigned hb = f2tf32(vb[j]);
                Bs[wbi[i][j]] = hb;
                if (SPLIT) Bs[BW + wbi[i][j]] = f2tf32(vb[j] - __uint_as_float(hb));
            }
        }
    };
    auto do_mma = [&](int stg) {
        const unsigned* As = Abuf + stg * ASTG;
        const unsigned* Bs = Bbuf + stg * BSTG;
#pragma unroll
        for (int ks = 0; ks < 2; ks++) {
            unsigned ah[2][4], al[2][4];
#pragma unroll
            for (int mi = 0; mi < 2; mi++) {
                int r = ks * AROWS + wy * 2 + mi;
                int off = r * 128 + ((lane + rot(r)) & 31) * 4;
                *(uint4*)ah[mi] = *(const uint4*)&As[off];
                if (SPLIT) *(uint4*)al[mi] = *(const uint4*)&As[AW + off];
            }
#pragma unroll
            for (int ni = 0; ni < NFRAG; ni++) {
                int R = ks * 16 + wx * NFRAG + ni;
                int off = R * 64 + ((lane + rot(R)) & 31) * 2;
                unsigned bh[2];
                *(uint2*)bh = *(const uint2*)&Bs[off];
#pragma unroll
                for (int mi = 0; mi < 2; mi++) mma_tf32(acc[mi][ni], ah[mi], bh[0], bh[1]);
                if (SPLIT) {
                    unsigned bl[2];
                    *(uint2*)bl = *(const uint2*)&Bs[BW + off];
#pragma unroll
                    for (int mi = 0; mi < 2; mi++) {
                        mma_tf32(acc[mi][ni], al[mi], bh[0], bh[1]);
                        mma_tf32(acc[mi][ni], ah[mi], bl[0], bl[1]);
                    }
                }
            }
        }
    };

    int nk = kchunk >> 4;
    load_tile(kbeg);
    store_frag(0);
    __syncthreads();
    if (nk > 1) load_tile(kbeg + 16);
    for (int kt = 0; kt < nk; kt++) {
        do_mma(kt & 1);
        if (kt + 1 < nk) {
            store_frag((kt + 1) & 1);
            if (kt + 2 < nk) load_tile(kbeg + ((kt + 2) << 4));
            __syncthreads();
        }
    }

    int g = lane >> 2, th = lane & 3;
    int mbase = wy * 32, nbase = wx * (NFRAG * 8);
#pragma unroll
    for (int mi = 0; mi < 2; mi++) {
        int gm0 = m0 + mbase + mi * 16 + g;
#pragma unroll
        for (int ni = 0; ni < NFRAG; ni++) {
            int gn = n0 + nbase + ni * 8 + 2 * th;
            float2 v0 = {acc[mi][ni][0], acc[mi][ni][1]};
            float2 v1 = {acc[mi][ni][2], acc[mi][ni][3]};
            *(float2*)&Cz[(size_t)gm0 * N + gn] = v0;
            *(float2*)&Cz[(size_t)(gm0 + 8) * N + gn] = v1;
        }
    }
}

// ---------------------------------------------------------------------------
// Attention helpers (shift-algebra form)
// ---------------------------------------------------------------------------
template <int SUMSQ>
__global__ void diag9_kernel(const float* __restrict__ In, float* __restrict__ Out) {
    unsigned stride = gridDim.x * blockDim.x;
    float ssq = 0.f;
    for (unsigned ii = blockIdx.x * blockDim.x + threadIdx.x; ii < 84934656u; ii += stride) {
        unsigned a = ii / 9216u, b = ii - a * 9216u;
        int ay = a / 96, ax = (int)a - ay * 96;
        int by = b / 96, bx = (int)b - by * 96;
        float s = 0.f;
#pragma unroll
        for (int dy = -1; dy <= 1; dy++) {
            if ((unsigned)(ay + dy) >= 96u || (unsigned)(by + dy) >= 96u) continue;
#pragma unroll
            for (int dx = -1; dx <= 1; dx++) {
                if ((unsigned)(ax + dx) >= 96u || (unsigned)(bx + dx) >= 96u) continue;
                s += In[(int)ii + (dy * 96 + dx) * 9217];
            }
        }
        Out[ii] = s;
        if (SUMSQ) ssq += s * s;
    }
    if (SUMSQ) {
        for (int o = 16; o; o >>= 1) ssq += __shfl_down_sync(0xffffffffu, ssq, o);
        __shared__ float red[8];
        int lane = threadIdx.x & 31, w = threadIdx.x >> 5;
        if (lane == 0) red[w] = ssq;
        __syncthreads();
        if (threadIdx.x < 32) {
            float v = (threadIdx.x < 8) ? red[threadIdx.x] : 0.f;
            for (int o = 4; o; o >>= 1) v += __shfl_down_sync(0xffffffffu, v, o);
            if (threadIdx.x == 0) atomicAdd(&g_sumsq, (double)v);
        }
    }
}

__global__ void zero_sum_kernel() {
    if (threadIdx.x == 0 && blockIdx.x == 0) g_sumsq = 0.0;
}

// One block per row p: A[p,:] = softmax(scale * S[p,:]), scale = 10/nrm. In-place.
__global__ void softmax_kernel(float* __restrict__ S) {
    extern __shared__ float row[];
    __shared__ float red[8];
    __shared__ float bval;
    int p = blockIdx.x;
    float* Sr = S + (size_t)p * 9216;
    float nrm = fmaxf(sqrtf((float)g_sumsq), 1e-12f);
    float scale = 10.f / nrm;
    int t = threadIdx.x;
    int lane = t & 31, w = t >> 5;

    float lm = -INFINITY;
    for (int i = t; i < 9216; i += 256) {
        float v = Sr[i] * scale;
        row[i] = v;
        lm = fmaxf(lm, v);
    }
    for (int o = 16; o; o >>= 1) lm = fmaxf(lm, __shfl_xor_sync(0xffffffffu, lm, o));
    if (lane == 0) red[w] = lm;
    __syncthreads();
    if (t < 32) {
        float v = (t < 8) ? red[t] : -INFINITY;
        for (int o = 4; o; o >>= 1) v = fmaxf(v, __shfl_xor_sync(0xffffffffu, v, o));
        if (t == 0) bval = v;
    }
    __syncthreads();
    float mx = bval;

    float ls = 0.f;
    for (int i = t; i < 9216; i += 256) {
        float e = __expf(row[i] - mx);
        row[i] = e;
        ls += e;
    }
    for (int o = 16; o; o >>= 1) ls += __shfl_xor_sync(0xffffffffu, ls, o);
    __syncthreads();
    if (lane == 0) red[w] = ls;
    __syncthreads();
    if (t < 32) {
        float v = (t < 8) ? red[t] : 0.f;
        for (int o = 4; o; o >>= 1) v += __shfl_down_sync(0xffffffffu, v, o);
        if (t == 0) bval = v;
    }
    __syncthreads();
    float inv = 1.f / bval;
    for (int i = t; i < 9216; i += 256) Sr[i] = row[i] * inv;
}

// attn[c, 2x] = (sum of 4 split-K partials of Rt)[x, c] * m[x], 2x upsample.
__global__ void maskup_kernel(const float* __restrict__ Rt, const float* __restrict__ mask,
                              float* __restrict__ attn) {
    int idx = blockIdx.x * blockDim.x + threadIdx.x;
    if (idx >= 128 * 9216) return;
    int c = idx / 9216, x = idx % 9216;
    int yy = x / 96, xx = x % 96;
    float s = 0.f;
#pragma unroll
    for (int p = 0; p < 4; p++)
        s += Rt[(size_t)p * 1179648 + (size_t)x * 128 + c];
    s *= mask[(2 * yy) * 192 + 2 * xx];
    size_t base = (size_t)c * 36864 + (size_t)(2 * yy) * 192 + 2 * xx;
    attn[base]       = s;
    attn[base + 1]   = s;
    attn[base + 192] = s;
    attn[base + 193] = s;
}

// ---------------------------------------------------------------------------
// Host orchestration
// ---------------------------------------------------------------------------
#define SMEM_F16_MT128 40960   // (3*2048 + 2*2048)*4
#define SMEM_F16_MT64  28672   // (3*1024 + 2*2048)*4
#define SMEM_F16_MT32  22528   // (3*512  + 2*2048)*4
#define SMEM_F16_C     16384   // (2*1024 + 2*1024)*4
#define SMEM_R_SPLIT   65536

extern "C" void kernel_launch(void* const* d_in, const int* in_sizes, int n_in,
                              void* d_out, int out_size) {
    const float* x    = (const float*)d_in[0];
    const float* mask = (const float*)d_in[1];
    const float* w[8];
    const float* b[8];
    for (int i = 0; i < 8; i++) {
        w[i] = (const float*)d_in[2 + 2 * i];
        b[i] = (const float*)d_in[3 + 2 * i];
    }

    float *b1, *b2, *b3, *b4, *b5, *fg, *ds, *S, *CM, *Rt, *attn, *b7, *wt;
    cudaGetSymbolAddress((void**)&b1,   g_b1);
    cudaGetSymbolAddress((void**)&b2,   g_b2);
    cudaGetSymbolAddress((void**)&b3,   g_b3);
    cudaGetSymbolAddress((void**)&b4,   g_b4);
    cudaGetSymbolAddress((void**)&b5,   g_b5);
    cudaGetSymbolAddress((void**)&fg,   g_fg);
    cudaGetSymbolAddress((void**)&ds,   g_ds);
    cudaGetSymbolAddress((void**)&S,    g_S);
    cudaGetSymbolAddress((void**)&CM,   g_CM);
    cudaGetSymbolAddress((void**)&Rt,   g_Rt);
    cudaGetSymbolAddress((void**)&attn, g_attn);
    cudaGetSymbolAddress((void**)&b7,   g_b7);
    cudaGetSymbolAddress((void**)&wt,   g_wt);

    cudaFuncSetAttribute(mma_tf32_nt_kernel<128, 1, 1, 1>,
                         cudaFuncAttributeMaxDynamicSharedMemorySize, SMEM_R_SPLIT);

    // All weights -> fp16 hi/lo fragment planes, one launch.
    transpose_all_kernel<<<(346880 + 255) / 256, 256>>>(
        w[0], w[1], w[2], w[3], w[4], w[5], w[6], w[7], wt);

    // conv1: C=3, 768x768, 5x5, pad2, str1, K=80 (75 real), OC=32
    mma_fp16_kernel<32, 1, 1, 1, 1, 5, 2, 3, 768, 768, 1, 3>
        <<<dim3(4608, 1, 1), 256, SMEM_F16_MT32>>>(
        wt + 0, x, b[0], b1, 32, 589824, 80, 32, 75, nullptr, nullptr);

    // conv2: C=32, 768x768, str2 -> 384x384, K=288, OC=32
    mma_fp16_kernel<32, 1, 1, 1, 1, 3, 1, 32, 768, 768, 2, 3>
        <<<dim3(1152, 1, 1), 256, SMEM_F16_MT32>>>(
        wt + 2560, b1, b[1], b2, 32, 147456, 288, 32, 288, nullptr, nullptr);

    // conv3: C=32, 384x384, str1, K=288, OC=64
    mma_fp16_kernel<64, 1, 1, 1, 1, 3, 1, 32, 384, 384, 1, 3>
        <<<dim3(1152, 1, 1), 256, SMEM_F16_MT64>>>(
        wt + 11776, b2, b[2], b3, 64, 147456, 288, 64, 288, nullptr, nullptr);

    // conv4: C=64, 384x384, str2 -> 192x192, K=576, OC=128
    mma_fp16_kernel<128, 1, 1, 1, 1, 3, 1, 64, 384, 384, 2, 2>
        <<<dim3(288, 1, 1), 256, SMEM_F16_MT128>>>(
        wt + 30208, b3, b[3], b4, 128, 36864, 576, 128, 576, nullptr, nullptr);

    // conv5: C=128, 192x192, str1, K=1152
    mma_fp16_kernel<128, 1, 1, 1, 1, 3, 1, 128, 192, 192, 1, 2>
        <<<dim3(288, 1, 1), 256, SMEM_F16_MT128>>>(
        wt + 103936, b4, b[4], b5, 128, 36864, 1152, 128, 1152, nullptr, nullptr);

    // conv6: strided conv (192x192, str2 -> 96x96), relu epilogue -> ds, fg.
    mma_fp16_kernel<128, 1, 2, 2, 1, 3, 1, 128, 192, 192, 2, 2>
        <<<dim3(72, 1, 1), 256, SMEM_F16_MT128>>>(
        wt + 251392, b5, b[5], ds, 128, 9216, 1152, 128, 1152, mask, fg);

    // Contextual attention (shift algebra)
    // C = fg^T * ds : M=N=9216, K=128, fp16 plain (11-bit ~ tf32; softmax-suppressed).
    mma_fp16_kernel<128, 0, 0, 0, 0, 3, 1, 1, 1, 1, 1, 3>
        <<<dim3(72, 72, 1), 256, SMEM_F16_C>>>(
        fg, ds, nullptr, CM, 9216, 9216, 128, 9216, 128, nullptr, nullptr);
    zero_sum_kernel<<<1, 32>>>();
    diag9_kernel<1><<<2048, 256>>>(CM, S);   // S = diag9(C), fused ||S||^2
    softmax_kernel<<<9216, 256, 9216 * sizeof(float)>>>(S);
    diag9_kernel<0><<<2048, 256>>>(S, CM);   // M = diag9(A)
    // out[x,c] = sum_u M[x,u] * ds[c,u] : NT, split tf32, split-K x4 (legacy path).
    mma_tf32_nt_kernel<128, 1, 1, 1>
        <<<dim3(1, 72, 4), 256, SMEM_R_SPLIT>>>(
        CM, ds, Rt, 9216, 128, 9216);
    maskup_kernel<<<(128 * 9216 + 255) / 256, 256>>>(Rt, mask, attn);

    // conv7: C=128, 192x192, str1, K=1152
    mma_fp16_kernel<128, 1, 1, 1, 1, 3, 1, 128, 192, 192, 1, 2>
        <<<dim3(288, 1, 1), 256, SMEM_F16_MT128>>>(
        wt + 398848, attn, b[6], b7, 128, 36864, 1152, 128, 1152, nullptr, nullptr);

    // conv8
    mma_fp16_kernel<128, 1, 1, 1, 1, 3, 1, 128, 192, 192, 1, 2>
        <<<dim3(288, 1, 1), 256, SMEM_F16_MT128>>>(
        wt + 546304, b7, b[7], (float*)d_out, 128, 36864, 1152, 128, 1152, nullptr, nullptr);
}

// round 17
// speedup vs baseline: 6.3518x; 1.0885x over previous
#include <cuda_runtime.h>
#include <cuda_fp16.h>
#include <stdint.h>
#include <cstdint>
#include <math.h>

// ---------------------------------------------------------------------------
// Scratch (device globals -- allocation-free per harness rules)
// ---------------------------------------------------------------------------
__device__ float  g_b1[18874368];   // conv1 out 32*768*768
__device__ float  g_b2[4718592];    // conv2 out 32*384*384
__device__ float  g_b3[9437184];    // conv3 out 64*384*384
__device__ float  g_b4[4718592];    // conv4 out 128*192*192
__device__ float  g_b5[4718592];    // conv5 out
__device__ float  g_fg[1179648];    // fg = ds*mask, 128 x 9216
__device__ float  g_ds[1179648];    // ds downsampled bg, 128 x 9216
__device__ float  g_S[84934656];    // ping-pong buffer (x-pass temps)
__device__ float  g_CM[84934656];   // C, then S_final/A (softmaxed), then M
__device__ float  g_Rt[4718592];    // 4 split-K partials of 9216 x 128
__device__ float  g_attn[4718592];  // attention out 128*192*192
__device__ float  g_b7[4718592];    // conv7 out
__device__ __align__(16) float g_wt[693760];   // fp16 hi/lo weight frag planes
__device__ double g_sumsq;          // Frobenius norm accumulator

// ---------------------------------------------------------------------------
// Helpers
// ---------------------------------------------------------------------------
__device__ __forceinline__ int refl(int i, int n) {
    if (i < 0) i = -i;
    if (i >= n) i = 2 * n - 2 - i;
    return i;
}

__device__ __forceinline__ void mma_fp16(float* c, const unsigned* a, unsigned b0, unsigned b1) {
    asm volatile(
        "mma.sync.aligned.m16n8k16.row.col.f32.f16.f16.f32 "
        "{%0,%1,%2,%3},{%4,%5,%6,%7},{%8,%9},{%0,%1,%2,%3};\n"
        : "+f"(c[0]), "+f"(c[1]), "+f"(c[2]), "+f"(c[3])
        : "r"(a[0]), "r"(a[1]), "r"(a[2]), "r"(a[3]), "r"(b0), "r"(b1));
}

__device__ __forceinline__ unsigned packh2(float x, float y) {
    __half2 h = __floats2half2_rn(x, y);
    return *(unsigned*)&h;
}
__device__ __forceinline__ unsigned packh2_lo(float x, float y, unsigned hi) {
    __half2 h = *(__half2*)&hi;
    return packh2(x - __low2float(h), y - __high2float(h));
}

__device__ __forceinline__ unsigned smem_u32(const void* p) {
    unsigned r;
    asm("{ .reg .u64 t; cvta.to.shared.u64 t, %1; cvt.u32.u64 %0, t; }"
        : "=r"(r) : "l"(p));
    return r;
}
__device__ __forceinline__ void cp_async16(unsigned sa, const void* g) {
    asm volatile("cp.async.ca.shared.global [%0], [%1], 16;\n" :: "r"(sa), "l"(g));
}
__device__ __forceinline__ void cp_async8(unsigned sa, const void* g) {
    asm volatile("cp.async.ca.shared.global [%0], [%1], 8;\n" :: "r"(sa), "l"(g));
}
__device__ __forceinline__ void cp_async4(unsigned sa, const void* g) {
    asm volatile("cp.async.ca.shared.global [%0], [%1], 4;\n" :: "r"(sa), "l"(g));
}
#define CP_COMMIT() asm volatile("cp.async.commit_group;\n" ::: "memory")
#define CP_WAIT1()  asm volatile("cp.async.wait_group 1;\n" ::: "memory")

__device__ __forceinline__ int rot(int r) { return r + (r >> 3); }

// ---------------------------------------------------------------------------
// Weights -> fp16 hi/lo m16n8k16-A-fragment planes (one thread per hi word).
// ---------------------------------------------------------------------------
__global__ void transpose_all_kernel(
    const float* __restrict__ w1, const float* __restrict__ w2,
    const float* __restrict__ w3, const float* __restrict__ w4,
    const float* __restrict__ w5, const float* __restrict__ w6,
    const float* __restrict__ w7, const float* __restrict__ w8,
    float* __restrict__ wt) {
    int idx = blockIdx.x * blockDim.x + threadIdx.x;
    if (idx >= 346880) return;
    const float* w; int Kp, Kr, M, MT, l, baseW;
    if (idx < 1280)        { w = w1; Kp = 80;   Kr = 75;   M = 32;  MT = 32;  l = idx;          baseW = 0; }
    else if (idx < 5888)   { w = w2; Kp = 288;  Kr = 288;  M = 32;  MT = 32;  l = idx - 1280;   baseW = 2560; }
    else if (idx < 15104)  { w = w3; Kp = 288;  Kr = 288;  M = 64;  MT = 64;  l = idx - 5888;   baseW = 11776; }
    else if (idx < 51968)  { w = w4; Kp = 576;  Kr = 576;  M = 128; MT = 128; l = idx - 15104;  baseW = 30208; }
    else if (idx < 125696) { w = w5; Kp = 1152; Kr = 1152; M = 128; MT = 128; l = idx - 51968;  baseW = 103936; }
    else if (idx < 199424) { w = w6; Kp = 1152; Kr = 1152; M = 128; MT = 128; l = idx - 125696; baseW = 251392; }
    else if (idx < 273152) { w = w7; Kp = 1152; Kr = 1152; M = 128; MT = 128; l = idx - 199424; baseW = 398848; }
    else                   { w = w8; Kp = 1152; Kr = 1152; M = 128; MT = 128; l = idx - 273152; baseW = 546304; }
    int AWH = 8 * MT;
    int kt = l / AWH, word = l - kt * AWH;
    int mb = word >> 7, rem = word & 127;
    int lanei = rem >> 2, reg = rem & 3;
    int g = lanei >> 2, th = lanei & 3;
    int mh = reg & 1, k8 = reg >> 1;
    int m = mb * 16 + mh * 8 + g;
    int ke = kt * 16 + k8 * 8 + th * 2;
    float v0 = (ke < Kr && m < M) ? w[m * Kr + ke] : 0.f;
    float v1 = (ke + 1 < Kr && m < M) ? w[m * Kr + ke + 1] : 0.f;
    unsigned hi = packh2(v0, v1);
    unsigned lo = packh2_lo(v0, v1, hi);
    unsigned* uw = (unsigned*)wt;
    uw[baseW + l] = hi;
    uw[baseW + Kp * MT / 2 + l] = lo;
}

// ---------------------------------------------------------------------------
// FP16 hi/lo tensor-core GEMM (m16n8k16), LAYOUT TN (convs + C GEMM).
// ---------------------------------------------------------------------------
template <int MT, int SPLIT, int ACT, int MODE, int AGLOBAL,
          int KS, int PAD, int CC, int HH, int WW, int STR, int BLK>
__global__ __launch_bounds__(256, BLK) void mma_fp16_kernel(
    const float* __restrict__ A, const float* __restrict__ B,
    const float* __restrict__ bias, float* __restrict__ C,
    int M, int N, int K, int Mreal, int Kreal,
    const float* __restrict__ mask, float* __restrict__ out2) {
    constexpr int KSQ = KS * KS;
    constexpr int OWc = MODE ? ((WW + 2 * PAD - KS) / STR + 1) : 1;
    constexpr int AWH = 8 * MT;
    constexpr int BWH = 1024;
    constexpr int PL = SPLIT ? 2 : 1;
    constexpr int ASTGH = AWH * PL;
    constexpr int BSTGH = BWH * PL;
    constexpr int NASTG = AGLOBAL ? 3 : 2;
    constexpr int NW_Y = MT / 32;
    constexpr int NW_X = 8 / NW_Y;
    constexpr int NFRAG = 16 / NW_X;
    constexpr int CPWH = MT / 32;
    extern __shared__ unsigned dyns[];
    unsigned* Abuf = dyns;
    unsigned* Bbuf = dyns + NASTG * ASTGH;
    __shared__ int s_off[MODE ? 128 : 1][MODE ? KSQ : 1];
    __shared__ int s_m[MODE == 2 ? 128 : 1];
    int t = threadIdx.x;
    int m0 = blockIdx.y * MT, n0 = blockIdx.x * 128;
    int lane = t & 31, warp = t >> 5;
    int wy = warp / NW_X, wx = warp % NW_X;
    int q = t >> 5, cg = t & 31;
    int thq = q & 3, k8q = q >> 2;

    float* Cz = C;
    const unsigned* Ag = (const unsigned*)A;
    int aplaneH = K * MT / 2;

    if (MODE) {
        if (t < 128) {
            int n = n0 + t;
            int oy = n / OWc;
            int ox = n - oy * OWc;
            int by = oy * STR, bx = ox * STR;
            int iy[KS], ix[KS];
#pragma unroll
            for (int p = 0; p < KS; p++) {
                iy[p] = refl(by + p - PAD, HH) * WW;
                ix[p] = refl(bx + p - PAD, WW);
            }
#pragma unroll
            for (int ky = 0; ky < KS; ky++)
#pragma unroll
                for (int kx = 0; kx < KS; kx++)
                    s_off[t][ky * KS + kx] = iy[ky] + ix[kx];
            if (MODE == 2) s_m[t] = by * WW + bx;
        }
        __syncthreads();
    }

    int wb[4], wa[4];
#pragma unroll
    for (int j = 0; j < 4; j++) {
        int n = MODE ? (cg + 32 * j) : (cg * 4 + j);
        int nb = n >> 3, gb = n & 7;
        wb[j] = nb * 64 + ((gb * 4 + thq + rot(nb)) & 31) * 2 + k8q;
        if (!AGLOBAL) {
            int m = cg * 4 + j;
            int mb = m >> 4, sub = m & 15, ga = sub & 7, mha = sub >> 3;
            wa[j] = mb * 128 + ((ga * 4 + thq + rot(mb)) & 31) * 4 + (mha + 2 * k8q);
        }
    }

    float acc[2][NFRAG][4];
#pragma unroll
    for (int mi = 0; mi < 2; mi++)
#pragma unroll
        for (int ni = 0; ni < NFRAG; ni++)
#pragma unroll
            for (int r = 0; r < 4; r++) acc[mi][ni][r] = 0.f;

    float4 pa[2], pb[2];

    auto stage_A = [&](int ktile, int stg) {
        unsigned sa = smem_u32(Abuf + stg * ASTGH);
#pragma unroll
        for (int pl = 0; pl < PL; pl++) {
            const unsigned* src = Ag + pl * aplaneH + (size_t)ktile * AWH + t * CPWH;
            unsigned dst = sa + (unsigned)(pl * AWH + t * CPWH) * 4u;
            if (CPWH == 4) cp_async16(dst, src);
            else if (CPWH == 2) cp_async8(dst, src);
            else cp_async4(dst, src);
        }
    };

    auto load_tile = [&](int k0) {
#pragma unroll
        for (int i = 0; i < 2; i++) {
            int kk = 2 * q + i;
            if (!AGLOBAL)
                pa[i] = *(const float4*)&A[(size_t)(k0 + kk) * M + m0 + cg * 4];
            if (MODE) {
                int k = k0 + kk;
                float v[4] = {0.f, 0.f, 0.f, 0.f};
                if (k < Kreal) {
                    int c = k / KSQ;
                    int r9 = k - c * KSQ;
                    const float* Bp = B + (size_t)c * (HH * WW);
#pragma unroll
                    for (int j = 0; j < 4; j++)
                        v[j] = Bp[s_off[cg + 32 * j][r9]];
                }
                pb[i] = {v[0], v[1], v[2], v[3]};
            } else {
                pb[i] = *(const float4*)&B[(size_t)(k0 + kk) * N + n0 + cg * 4];
            }
        }
    };

    auto store_frag = [&](int stg) {
        unsigned* Bs = Bbuf + stg * BSTGH;
        const float* v0 = (const float*)&pb[0];
        const float* v1 = (const float*)&pb[1];
#pragma unroll
        for (int j = 0; j < 4; j++) {
            unsigned hi = packh2(v0[j], v1[j]);
            Bs[wb[j]] = hi;
            if (SPLIT) Bs[BWH + wb[j]] = packh2_lo(v0[j], v1[j], hi);
        }
        if (!AGLOBAL) {
            unsigned* As = Abuf + stg * ASTGH;
            const float* a0 = (const float*)&pa[0];
            const float* a1 = (const float*)&pa[1];
#pragma unroll
            for (int j = 0; j < 4; j++) {
                unsigned hi = packh2(a0[j], a1[j]);
                As[wa[j]] = hi;
                if (SPLIT) As[AWH + wa[j]] = packh2_lo(a0[j], a1[j], hi);
            }
        }
    };

    auto do_mma = [&](int sA, int sB) {
        const unsigned* As = Abuf + sA * ASTGH;
        const unsigned* Bs = Bbuf + sB * BSTGH;
        unsigned ah[2][4], al[2][4];
#pragma unroll
        for (int mi = 0; mi < 2; mi++) {
            int atom = wy * 2 + mi;
            int off = AGLOBAL ? (atom * 128 + lane * 4)
                              : (atom * 128 + ((lane + rot(atom)) & 31) * 4);
            *(uint4*)ah[mi] = *(const uint4*)&As[off];
            if (SPLIT) *(uint4*)al[mi] = *(const uint4*)&As[AWH + off];
        }
#pragma unroll
        for (int ni = 0; ni < NFRAG; ni++) {
            int nb = wx * NFRAG + ni;
            int off = nb * 64 + ((lane + rot(nb)) & 31) * 2;
            uint2 bh = *(const uint2*)&Bs[off];
#pragma unroll
            for (int mi = 0; mi < 2; mi++) mma_fp16(acc[mi][ni], ah[mi], bh.x, bh.y);
            if (SPLIT) {
                uint2 bl = *(const uint2*)&Bs[BWH + off];
#pragma unroll
                for (int mi = 0; mi < 2; mi++) {
                    mma_fp16(acc[mi][ni], al[mi], bh.x, bh.y);
                    mma_fp16(acc[mi][ni], ah[mi], bl.x, bl.y);
                }
            }
        }
    };

    int nk = K >> 4;
    if (AGLOBAL) {
        stage_A(0, 0); CP_COMMIT();
        if (nk > 1) stage_A(1, 1);
        CP_COMMIT();
        load_tile(0);
        store_frag(0);
        if (nk > 1) load_tile(16);
        CP_WAIT1();
        __syncthreads();
        int sA = 0;
        for (int kt = 0; kt < nk; kt++) {
            if (kt + 2 < nk) { int st = sA + 2; if (st >= 3) st -= 3; stage_A(kt + 2, st); }
            CP_COMMIT();
            do_mma(sA, kt & 1);
            if (kt + 1 < nk) {
                store_frag((kt + 1) & 1);
                if (kt + 2 < nk) load_tile((kt + 2) << 4);
                CP_WAIT1();
                __syncthreads();
            }
            if (++sA >= 3) sA = 0;
        }
    } else {
        load_tile(0);
        store_frag(0);
        __syncthreads();
        if (nk > 1) load_tile(16);
        for (int kt = 0; kt < nk; kt++) {
            do_mma(kt & 1, kt & 1);
            if (kt + 1 < nk) {
                store_frag((kt + 1) & 1);
                if (kt + 2 < nk) load_tile((kt + 2) << 4);
                __syncthreads();
            }
        }
    }

    int g = lane >> 2, th = lane & 3;
    int mbase = wy * 32, nbase = wx * (NFRAG * 8);
#pragma unroll
    for (int mi = 0; mi < 2; mi++) {
        int gm0 = m0 + mbase + mi * 16 + g;
        float bv0 = 0.f, bv1 = 0.f;
        if (ACT) {
            if (gm0 < Mreal)     bv0 = bias[gm0];
            if (gm0 + 8 < Mreal) bv1 = bias[gm0 + 8];
        }
#pragma unroll
        for (int ni = 0; ni < NFRAG; ni++) {
            int gn = n0 + nbase + ni * 8 + 2 * th;
            float2 v0 = {acc[mi][ni][0], acc[mi][ni][1]};
            float2 v1 = {acc[mi][ni][2], acc[mi][ni][3]};
            if (MODE == 2) {
                v0.x = fmaxf(v0.x + bv0, 0.f); v0.y = fmaxf(v0.y + bv0, 0.f);
                v1.x = fmaxf(v1.x + bv1, 0.f); v1.y = fmaxf(v1.y + bv1, 0.f);
                int l = gn - n0;
                float ma = mask[s_m[l]], mb = mask[s_m[l + 1]];
                *(float2*)&Cz[(size_t)gm0 * N + gn] = v0;
                *(float2*)&Cz[(size_t)(gm0 + 8) * N + gn] = v1;
                float2 f0 = {v0.x * ma, v0.y * mb};
                float2 f1 = {v1.x * ma, v1.y * mb};
                *(float2*)&out2[(size_t)gm0 * N + gn] = f0;
                *(float2*)&out2[(size_t)(gm0 + 8) * N + gn] = f1;
            } else if (ACT) {
                v0.x += bv0; v0.y += bv0;
                v1.x += bv1; v1.y += bv1;
                if (ACT == 1) {
                    v0.x = v0.x > 0.f ? v0.x : expm1f(v0.x);
                    v0.y = v0.y > 0.f ? v0.y : expm1f(v0.y);
                    v1.x = v1.x > 0.f ? v1.x : expm1f(v1.x);
                    v1.y = v1.y > 0.f ? v1.y : expm1f(v1.y);
                } else {
                    v0.x = fmaxf(v0.x, 0.f); v0.y = fmaxf(v0.y, 0.f);
                    v1.x = fmaxf(v1.x, 0.f); v1.y = fmaxf(v1.y, 0.f);
                }
                if (gm0 < Mreal)     *(float2*)&Cz[(size_t)gm0 * N + gn] = v0;
                if (gm0 + 8 < Mreal) *(float2*)&Cz[(size_t)(gm0 + 8) * N + gn] = v1;
            } else {
                *(float2*)&Cz[(size_t)gm0 * N + gn] = v0;
                *(float2*)&Cz[(size_t)(gm0 + 8) * N + gn] = v1;
            }
        }
    }
}

// ---------------------------------------------------------------------------
// FP16 hi/lo NT GEMM (the R GEMM): A: M x K, B: N x K, K contiguous both.
// MT = 128 fixed, 128-n tile, split-K via gridDim.z.
// ---------------------------------------------------------------------------
template <int BLK>
__global__ __launch_bounds__(256, BLK) void mma_fp16_nt_kernel(
    const float* __restrict__ A, const float* __restrict__ B,
    float* __restrict__ C, int M, int N, int K) {
    constexpr int AWH = 1024, BWH = 1024;
    constexpr int ASTGH = 2048, BSTGH = 2048;  // 2 planes each
    extern __shared__ unsigned dyns[];
    unsigned* Abuf = dyns;
    unsigned* Bbuf = dyns + 2 * ASTGH;
    int t = threadIdx.x;
    int m0 = blockIdx.y * 128, n0 = blockIdx.x * 128;
    int lane = t & 31, warp = t >> 5;
    int wy = warp >> 1, wx = warp & 1;

    int kchunk = K / (int)gridDim.z;
    int kbeg = (int)blockIdx.z * kchunk;
    float* Cz = C + (size_t)blockIdx.z * ((size_t)M * N);

    // Hoisted store indices: 2 loads x 2 k-pairs each, A and B sides.
    int wai[2][2], wbi[2][2];
#pragma unroll
    for (int i = 0; i < 2; i++) {
        int id = t + i * 256;
        int mm = id >> 2, kg = id & 3;
        int mb = mm >> 4, sub = mm & 15, ga = sub & 7, mha = sub >> 3;
        int nb = mm >> 3, gb = mm & 7;
#pragma unroll
        for (int p = 0; p < 2; p++) {
            int th = (2 * kg + p) & 3;
            int k8 = (4 * kg + 2 * p) >> 3;
            wai[i][p] = mb * 128 + ((ga * 4 + th + rot(mb)) & 31) * 4 + (mha + 2 * k8);
            wbi[i][p] = nb * 64 + ((gb * 4 + th + rot(nb)) & 31) * 2 + k8;
        }
    }

    float acc[2][8][4];
#pragma unroll
    for (int mi = 0; mi < 2; mi++)
#pragma unroll
        for (int ni = 0; ni < 8; ni++)
#pragma unroll
            for (int r = 0; r < 4; r++) acc[mi][ni][r] = 0.f;

    float4 pa[2], pb[2];

    auto load_tile = [&](int k0) {
#pragma unroll
        for (int i = 0; i < 2; i++) {
            int id = t + i * 256;
            int mm = id >> 2, kg = id & 3;
            pa[i] = *(const float4*)&A[(size_t)(m0 + mm) * K + k0 + kg * 4];
            pb[i] = *(const float4*)&B[(size_t)(n0 + mm) * K + k0 + kg * 4];
        }
    };
    auto store_frag = [&](int stg) {
        unsigned* As = Abuf + stg * ASTGH;
        unsigned* Bs = Bbuf + stg * BSTGH;
#pragma unroll
        for (int i = 0; i < 2; i++) {
            const float* va = (const float*)&pa[i];
            const float* vb = (const float*)&pb[i];
#pragma unroll
            for (int p = 0; p < 2; p++) {
                unsigned hia = packh2(va[2 * p], va[2 * p + 1]);
                As[wai[i][p]] = hia;
                As[AWH + wai[i][p]] = packh2_lo(va[2 * p], va[2 * p + 1], hia);
                unsigned hib = packh2(vb[2 * p], vb[2 * p + 1]);
                Bs[wbi[i][p]] = hib;
                Bs[BWH + wbi[i][p]] = packh2_lo(vb[2 * p], vb[2 * p + 1], hib);
            }
        }
    };
    auto do_mma = [&](int stg) {
        const unsigned* As = Abuf + stg * ASTGH;
        const unsigned* Bs = Bbuf + stg * BSTGH;
        unsigned ah[2][4], al[2][4];
#pragma unroll
        for (int mi = 0; mi < 2; mi++) {
            int atom = wy * 2 + mi;
            int off = atom * 128 + ((lane + rot(atom)) & 31) * 4;
            *(uint4*)ah[mi] = *(const uint4*)&As[off];
            *(uint4*)al[mi] = *(const uint4*)&As[AWH + off];
        }
#pragma unroll
        for (int ni = 0; ni < 8; ni++) {
            int nb = wx * 8 + ni;
            int off = nb * 64 + ((lane + rot(nb)) & 31) * 2;
            uint2 bh = *(const uint2*)&Bs[off];
            uint2 bl = *(const uint2*)&Bs[BWH + off];
#pragma unroll
            for (int mi = 0; mi < 2; mi++) {
                mma_fp16(acc[mi][ni], ah[mi], bh.x, bh.y);
                mma_fp16(acc[mi][ni], al[mi], bh.x, bh.y);
                mma_fp16(acc[mi][ni], ah[mi], bl.x, bl.y);
            }
        }
    };

    int nk = kchunk >> 4;
    load_tile(kbeg);
    store_frag(0);
    __syncthreads();
    if (nk > 1) load_tile(kbeg + 16);
    for (int kt = 0; kt < nk; kt++) {
        do_mma(kt & 1);
        if (kt + 1 < nk) {
            store_frag((kt + 1) & 1);
            if (kt + 2 < nk) load_tile(kbeg + ((kt + 2) << 4));
            __syncthreads();
        }
    }

    int g = lane >> 2, th = lane & 3;
#pragma unroll
    for (int mi = 0; mi < 2; mi++) {
        int gm0 = m0 + wy * 32 + mi * 16 + g;
#pragma unroll
        for (int ni = 0; ni < 8; ni++) {
            int gn = n0 + wx * 64 + ni * 8 + 2 * th;
            float2 v0 = {acc[mi][ni][0], acc[mi][ni][1]};
            float2 v1 = {acc[mi][ni][2], acc[mi][ni][3]};
            *(float2*)&Cz[(size_t)gm0 * N + gn] = v0;
            *(float2*)&Cz[(size_t)(gm0 + 8) * N + gn] = v1;
        }
    }
}

// ---------------------------------------------------------------------------
// Separable diag9: x-pass (taps +-9217) then y-pass (taps +-96*9217).
// Validity factorizes per axis. SUMSQ on the y-pass accumulates ||Out||^2.
// ---------------------------------------------------------------------------
__global__ void diagx_kernel(const float* __restrict__ In, float* __restrict__ Out) {
    unsigned stride = gridDim.x * blockDim.x;
    for (unsigned ii = blockIdx.x * blockDim.x + threadIdx.x; ii < 84934656u; ii += stride) {
        unsigned a = ii / 9216u, b = ii - a * 9216u;
        int ax = (int)(a % 96u), bx = (int)(b % 96u);
        float s = In[ii];
        if (ax > 0 && bx > 0)   s += In[(int)ii - 9217];
        if (ax < 95 && bx < 95) s += In[(int)ii + 9217];
        Out[ii] = s;
    }
}

template <int SUMSQ>
__global__ void diagy_kernel(const float* __restrict__ In, float* __restrict__ Out) {
    unsigned stride = gridDim.x * blockDim.x;
    float ssq = 0.f;
    for (unsigned ii = blockIdx.x * blockDim.x + threadIdx.x; ii < 84934656u; ii += stride) {
        unsigned a = ii / 9216u, b = ii - a * 9216u;
        int ay = (int)(a / 96u), by = (int)(b / 96u);
        float s = In[ii];
        if (ay > 0 && by > 0)   s += In[(int)ii - 884832];
        if (ay < 95 && by < 95) s += In[(int)ii + 884832];
        Out[ii] = s;
        if (SUMSQ) ssq += s * s;
    }
    if (SUMSQ) {
        for (int o = 16; o; o >>= 1) ssq += __shfl_down_sync(0xffffffffu, ssq, o);
        __shared__ float red[8];
        int lane = threadIdx.x & 31, w = threadIdx.x >> 5;
        if (lane == 0) red[w] = ssq;
        __syncthreads();
        if (threadIdx.x < 32) {
            float v = (threadIdx.x < 8) ? red[threadIdx.x] : 0.f;
            for (int o = 4; o; o >>= 1) v += __shfl_down_sync(0xffffffffu, v, o);
            if (threadIdx.x == 0) atomicAdd(&g_sumsq, (double)v);
        }
    }
}

__global__ void zero_sum_kernel() {
    if (threadIdx.x == 0 && blockIdx.x == 0) g_sumsq = 0.0;
}

// One block per row p: A[p,:] = softmax(scale * S[p,:]), scale = 10/nrm. In-place.
__global__ void softmax_kernel(float* __restrict__ S) {
    extern __shared__ float row[];
    __shared__ float red[8];
    __shared__ float bval;
    int p = blockIdx.x;
    float* Sr = S + (size_t)p * 9216;
    float nrm = fmaxf(sqrtf((float)g_sumsq), 1e-12f);
    float scale = 10.f / nrm;
    int t = threadIdx.x;
    int lane = t & 31, w = t >> 5;

    float lm = -INFINITY;
    for (int i = t; i < 9216; i += 256) {
        float v = Sr[i] * scale;
        row[i] = v;
        lm = fmaxf(lm, v);
    }
    for (int o = 16; o; o >>= 1) lm = fmaxf(lm, __shfl_xor_sync(0xffffffffu, lm, o));
    if (lane == 0) red[w] = lm;
    __syncthreads();
    if (t < 32) {
        float v = (t < 8) ? red[t] : -INFINITY;
        for (int o = 4; o; o >>= 1) v = fmaxf(v, __shfl_xor_sync(0xffffffffu, v, o));
        if (t == 0) bval = v;
    }
    __syncthreads();
    float mx = bval;

    float ls = 0.f;
    for (int i = t; i < 9216; i += 256) {
        float e = __expf(row[i] - mx);
        row[i] = e;
        ls += e;
    }
    for (int o = 16; o; o >>= 1) ls += __shfl_xor_sync(0xffffffffu, ls, o);
    __syncthreads();
    if (lane == 0) red[w] = ls;
    __syncthreads();
    if (t < 32) {
        float v = (t < 8) ? red[t] : 0.f;
        for (int o = 4; o; o >>= 1) v += __shfl_down_sync(0xffffffffu, v, o);
        if (t == 0) bval = v;
    }
    __syncthreads();
    float inv = 1.f / bval;
    for (int i = t; i < 9216; i += 256) Sr[i] = row[i] * inv;
}

// attn[c, 2x] = (sum of 4 split-K partials of Rt)[x, c] * m[x], 2x upsample.
__global__ void maskup_kernel(const float* __restrict__ Rt, const float* __restrict__ mask,
                              float* __restrict__ attn) {
    int idx = blockIdx.x * blockDim.x + threadIdx.x;
    if (idx >= 128 * 9216) return;
    int c = idx / 9216, x = idx % 9216;
    int yy = x / 96, xx = x % 96;
    float s = 0.f;
#pragma unroll
    for (int p = 0; p < 4; p++)
        s += Rt[(size_t)p * 1179648 + (size_t)x * 128 + c];
    s *= mask[(2 * yy) * 192 + 2 * xx];
    size_t base = (size_t)c * 36864 + (size_t)(2 * yy) * 192 + 2 * xx;
    attn[base]       = s;
    attn[base + 1]   = s;
    attn[base + 192] = s;
    attn[base + 193] = s;
}

// ---------------------------------------------------------------------------
// Host orchestration
// ---------------------------------------------------------------------------
#define SMEM_F16_MT128 40960   // (3*2048 + 2*2048)*4
#define SMEM_F16_MT64  28672   // (3*1024 + 2*2048)*4
#define SMEM_F16_MT32  22528   // (3*512  + 2*2048)*4
#define SMEM_F16_C     16384   // (2*1024 + 2*1024)*4
#define SMEM_F16_NT    32768   // (2*2048 + 2*2048)*4

extern "C" void kernel_launch(void* const* d_in, const int* in_sizes, int n_in,
                              void* d_out, int out_size) {
    const float* x    = (const float*)d_in[0];
    const float* mask = (const float*)d_in[1];
    const float* w[8];
    const float* b[8];
    for (int i = 0; i < 8; i++) {
        w[i] = (const float*)d_in[2 + 2 * i];
        b[i] = (const float*)d_in[3 + 2 * i];
    }

    float *b1, *b2, *b3, *b4, *b5, *fg, *ds, *S, *CM, *Rt, *attn, *b7, *wt;
    cudaGetSymbolAddress((void**)&b1,   g_b1);
    cudaGetSymbolAddress((void**)&b2,   g_b2);
    cudaGetSymbolAddress((void**)&b3,   g_b3);
    cudaGetSymbolAddress((void**)&b4,   g_b4);
    cudaGetSymbolAddress((void**)&b5,   g_b5);
    cudaGetSymbolAddress((void**)&fg,   g_fg);
    cudaGetSymbolAddress((void**)&ds,   g_ds);
    cudaGetSymbolAddress((void**)&S,    g_S);
    cudaGetSymbolAddress((void**)&CM,   g_CM);
    cudaGetSymbolAddress((void**)&Rt,   g_Rt);
    cudaGetSymbolAddress((void**)&attn, g_attn);
    cudaGetSymbolAddress((void**)&b7,   g_b7);
    cudaGetSymbolAddress((void**)&wt,   g_wt);

    // All weights -> fp16 hi/lo fragment planes, one launch.
    transpose_all_kernel<<<(346880 + 255) / 256, 256>>>(
        w[0], w[1], w[2], w[3], w[4], w[5], w[6], w[7], wt);

    // conv1: C=3, 768x768, 5x5, pad2, str1, K=80 (75 real), OC=32
    mma_fp16_kernel<32, 1, 1, 1, 1, 5, 2, 3, 768, 768, 1, 3>
        <<<dim3(4608, 1, 1), 256, SMEM_F16_MT32>>>(
        wt + 0, x, b[0], b1, 32, 589824, 80, 32, 75, nullptr, nullptr);

    // conv2: C=32, 768x768, str2 -> 384x384, K=288, OC=32
    mma_fp16_kernel<32, 1, 1, 1, 1, 3, 1, 32, 768, 768, 2, 3>
        <<<dim3(1152, 1, 1), 256, SMEM_F16_MT32>>>(
        wt + 2560, b1, b[1], b2, 32, 147456, 288, 32, 288, nullptr, nullptr);

    // conv3: C=32, 384x384, str1, K=288, OC=64
    mma_fp16_kernel<64, 1, 1, 1, 1, 3, 1, 32, 384, 384, 1, 3>
        <<<dim3(1152, 1, 1), 256, SMEM_F16_MT64>>>(
        wt + 11776, b2, b[2], b3, 64, 147456, 288, 64, 288, nullptr, nullptr);

    // conv4: C=64, 384x384, str2 -> 192x192, K=576, OC=128
    mma_fp16_kernel<128, 1, 1, 1, 1, 3, 1, 64, 384, 384, 2, 2>
        <<<dim3(288, 1, 1), 256, SMEM_F16_MT128>>>(
        wt + 30208, b3, b[3], b4, 128, 36864, 576, 128, 576, nullptr, nullptr);

    // conv5: C=128, 192x192, str1, K=1152
    mma_fp16_kernel<128, 1, 1, 1, 1, 3, 1, 128, 192, 192, 1, 2>
        <<<dim3(288, 1, 1), 256, SMEM_F16_MT128>>>(
        wt + 103936, b4, b[4], b5, 128, 36864, 1152, 128, 1152, nullptr, nullptr);

    // conv6: strided conv (192x192, str2 -> 96x96), relu epilogue -> ds, fg.
    mma_fp16_kernel<128, 1, 2, 2, 1, 3, 1, 128, 192, 192, 2, 2>
        <<<dim3(72, 1, 1), 256, SMEM_F16_MT128>>>(
        wt + 251392, b5, b[5], ds, 128, 9216, 1152, 128, 1152, mask, fg);

    // Contextual attention (shift algebra, separable diag)
    // C = fg^T * ds : M=N=9216, K=128, fp16 plain.
    mma_fp16_kernel<128, 0, 0, 0, 0, 3, 1, 1, 1, 1, 1, 3>
        <<<dim3(72, 72, 1), 256, SMEM_F16_C>>>(
        fg, ds, nullptr, CM, 9216, 9216, 128, 9216, 128, nullptr, nullptr);
    diagx_kernel<<<2048, 256>>>(CM, S);        // x-pass of S
    zero_sum_kernel<<<1, 32>>>();
    diagy_kernel<1><<<2048, 256>>>(S, CM);     // y-pass -> S final in CM, + ||S||^2
    softmax_kernel<<<9216, 256, 9216 * sizeof(float)>>>(CM);  // CM -> A in place
    diagx_kernel<<<2048, 256>>>(CM, S);        // x-pass of M
    diagy_kernel<0><<<2048, 256>>>(S, CM);     // y-pass -> M in CM
    // out[x,c] = sum_u M[x,u] * ds[c,u] : NT, fp16 hi/lo, split-K x4.
    mma_fp16_nt_kernel<1><<<dim3(1, 72, 4), 256, SMEM_F16_NT>>>(
        CM, ds, Rt, 9216, 128, 9216);
    maskup_kernel<<<(128 * 9216 + 255) / 256, 256>>>(Rt, mask, attn);

    // conv7: C=128, 192x192, str1, K=1152
    mma_fp16_kernel<128, 1, 1, 1, 1, 3, 1, 128, 192, 192, 1, 2>
        <<<dim3(288, 1, 1), 256, SMEM_F16_MT128>>>(
        wt + 398848, attn, b[6], b7, 128, 36864, 1152, 128, 1152, nullptr, nullptr);

    // conv8
    mma_fp16_kernel<128, 1, 1, 1, 1, 3, 1, 128, 192, 192, 1, 2>
        <<<dim3(288, 1, 1), 256, SMEM_F16_MT128>>>(
        wt + 546304, b7, b[7], (float*)d_out, 128, 36864, 1152, 128, 1152, nullptr, nullptr);
}